// round 1
// baseline (speedup 1.0000x reference)
#include <cuda_runtime.h>
#include <cuda_bf16.h>
#include <math.h>

#define HID   512
#define G4    2048
#define BATCH 64
#define VOCAB 32000
#define SRC   50
#define TGT   49   // decode steps

// ---------------- scratch (static device globals; no allocation) ----------------
__device__ float g_gx[(SRC + TGT) * BATCH * G4];   // precomputed x-projections (+biases)
__device__ float g_h[2][BATCH * HID];              // ping-pong hidden state
__device__ float g_c[BATCH * HID];                 // cell state (in-place)
__device__ float g_logits[BATCH * VOCAB];
__device__ float g_losses[TGT * BATCH];

__device__ __forceinline__ float sigmoidf_(float x) { return 1.0f / (1.0f + expf(-x)); }

// ---------------- init: zero h and c ----------------
__global__ void init_kernel() {
    int i = blockIdx.x * blockDim.x + threadIdx.x;
    if (i < BATCH * HID) {
        g_h[0][i] = 0.0f;
        g_h[1][i] = 0.0f;
        g_c[i]    = 0.0f;
    }
}

// ---------------- gx = emb[tok] @ W_ih^T + b_ih + b_hh ----------------
// Tiled 64x64 GEMM, K=512. grid = (G4/64, M/64). M rows are (t,b) pairs.
__global__ void gx_kernel(const int* __restrict__ toks,
                          const float* __restrict__ emb,
                          const float* __restrict__ Wih,
                          const float* __restrict__ bih,
                          const float* __restrict__ bhh,
                          int gx_row0) {
    __shared__ float As[32][65];
    __shared__ float Bs[32][65];
    __shared__ int   stoks[64];

    const int tid = threadIdx.x;
    const int n0 = blockIdx.x * 64;
    const int m0 = blockIdx.y * 64;

    if (tid < 64) stoks[tid] = toks[m0 + tid];
    __syncthreads();

    const int ty = tid >> 4;   // 0..15 -> 4 m-rows each
    const int tx = tid & 15;   // 0..15 -> 4 n-cols each

    float acc[4][4];
#pragma unroll
    for (int i = 0; i < 4; ++i)
#pragma unroll
        for (int j = 0; j < 4; ++j) acc[i][j] = 0.0f;

    for (int kt = 0; kt < HID; kt += 32) {
#pragma unroll
        for (int i = 0; i < 8; ++i) {
            int idx = tid + i * 256;        // 0..2047
            int m = idx >> 5;               // 0..63
            int k = idx & 31;
            As[k][m] = emb[(size_t)stoks[m] * HID + kt + k];
            Bs[k][m] = Wih[(size_t)(n0 + m) * HID + kt + k];
        }
        __syncthreads();
#pragma unroll
        for (int k = 0; k < 32; ++k) {
            float a[4], b[4];
#pragma unroll
            for (int i = 0; i < 4; ++i) a[i] = As[k][ty * 4 + i];
#pragma unroll
            for (int j = 0; j < 4; ++j) b[j] = Bs[k][tx * 4 + j];
#pragma unroll
            for (int i = 0; i < 4; ++i)
#pragma unroll
                for (int j = 0; j < 4; ++j) acc[i][j] += a[i] * b[j];
        }
        __syncthreads();
    }

#pragma unroll
    for (int i = 0; i < 4; ++i) {
        int m = m0 + ty * 4 + i;
#pragma unroll
        for (int j = 0; j < 4; ++j) {
            int n = n0 + tx * 4 + j;
            g_gx[(size_t)(gx_row0 + m) * G4 + n] = acc[i][j] + bih[n] + bhh[n];
        }
    }
}

// ---------------- one recurrent step: gates = gx[t] + h @ W_hh^T; cell update ----------------
// grid = 128 blocks (4 hidden units each), 256 threads (64 batch x 4 K-splits)
__global__ void lstm_step(const float* __restrict__ Whh,
                          int gxrow, int hin, int hout) {
    __shared__ float smem[16 * 512];   // W tile, then reduction scratch

    const int tid = threadIdx.x;
    const int j0 = blockIdx.x * 4;

    // load 16 rows of Whh (4 gates x 4 j), each 512 floats
    for (int idx = tid; idx < 16 * 512; idx += 256) {
        int r = idx >> 9;          // 0..15
        int k = idx & 511;
        int g = r >> 2, jj = r & 3;
        smem[idx] = Whh[(size_t)(g * HID + j0 + jj) * HID + k];
    }
    __syncthreads();

    const int b = tid >> 2;    // 0..63
    const int q = tid & 3;     // K-split
    const float4* Wsh4 = (const float4*)smem;
    const float4* h4 = (const float4*)(&g_h[hin][b * HID]) + q * 32;  // 128 floats per q

    float acc[16];
#pragma unroll
    for (int r = 0; r < 16; ++r) acc[r] = 0.0f;

#pragma unroll 4
    for (int kk = 0; kk < 32; ++kk) {
        float4 hv = h4[kk];
        int kidx = q * 32 + kk;
#pragma unroll
        for (int r = 0; r < 16; ++r) {
            float4 w = Wsh4[r * 128 + kidx];
            acc[r] += w.x * hv.x + w.y * hv.y + w.z * hv.z + w.w * hv.w;
        }
    }

    __syncthreads();   // done reading W tile
#pragma unroll
    for (int r = 0; r < 16; ++r) smem[tid * 16 + r] = acc[r];
    __syncthreads();

    if (tid < 64) {
        const int bb = tid;
        const float* gxp = g_gx + (size_t)(gxrow + bb) * G4;
        float s[16];
#pragma unroll
        for (int r = 0; r < 16; ++r) {
            s[r] = smem[(bb * 4 + 0) * 16 + r] + smem[(bb * 4 + 1) * 16 + r]
                 + smem[(bb * 4 + 2) * 16 + r] + smem[(bb * 4 + 3) * 16 + r];
        }
#pragma unroll
        for (int jj = 0; jj < 4; ++jj) {
            int j = j0 + jj;
            float ig = gxp[0 * HID + j] + s[0 + jj];
            float fg = gxp[1 * HID + j] + s[4 + jj];
            float gg = gxp[2 * HID + j] + s[8 + jj];
            float og = gxp[3 * HID + j] + s[12 + jj];
            float cc = g_c[bb * HID + j];
            float cn = sigmoidf_(fg) * cc + sigmoidf_(ig) * tanhf(gg);
            float hn = sigmoidf_(og) * tanhf(cn);
            g_c[bb * HID + j] = cn;
            g_h[hout][bb * HID + j] = hn;
        }
    }
}

// ---------------- logits = h @ W_out^T + b_out ----------------
// grid = VOCAB/64 = 500 blocks, tile 64(m) x 64(n), K=512
__global__ void logits_kernel(int hsel,
                              const float* __restrict__ Wout,
                              const float* __restrict__ bout) {
    __shared__ float As[32][65];
    __shared__ float Bs[32][65];

    const int tid = threadIdx.x;
    const int n0 = blockIdx.x * 64;
    const float* h = g_h[hsel];

    const int ty = tid >> 4;
    const int tx = tid & 15;

    float acc[4][4];
#pragma unroll
    for (int i = 0; i < 4; ++i)
#pragma unroll
        for (int j = 0; j < 4; ++j) acc[i][j] = 0.0f;

    for (int kt = 0; kt < HID; kt += 32) {
#pragma unroll
        for (int i = 0; i < 8; ++i) {
            int idx = tid + i * 256;
            int m = idx >> 5;
            int k = idx & 31;
            As[k][m] = h[(size_t)m * HID + kt + k];
            Bs[k][m] = Wout[(size_t)(n0 + m) * HID + kt + k];
        }
        __syncthreads();
#pragma unroll
        for (int k = 0; k < 32; ++k) {
            float a[4], b[4];
#pragma unroll
            for (int i = 0; i < 4; ++i) a[i] = As[k][ty * 4 + i];
#pragma unroll
            for (int j = 0; j < 4; ++j) b[j] = Bs[k][tx * 4 + j];
#pragma unroll
            for (int i = 0; i < 4; ++i)
#pragma unroll
                for (int j = 0; j < 4; ++j) acc[i][j] += a[i] * b[j];
        }
        __syncthreads();
    }

#pragma unroll
    for (int i = 0; i < 4; ++i) {
        int m = ty * 4 + i;
#pragma unroll
        for (int j = 0; j < 4; ++j) {
            int n = n0 + tx * 4 + j;
            g_logits[(size_t)m * VOCAB + n] = acc[i][j] + bout[n];
        }
    }
}

// ---------------- per-row logsumexp + NLL ----------------
__global__ void loss_kernel(const int* __restrict__ target_lines, int d) {
    __shared__ float sred[256];
    const int b = blockIdx.x;
    const int tid = threadIdx.x;
    const float* row = g_logits + (size_t)b * VOCAB;

    float mx = -INFINITY;
    for (int v = tid; v < VOCAB; v += 256) mx = fmaxf(mx, row[v]);
    sred[tid] = mx;
    __syncthreads();
    for (int s = 128; s > 0; s >>= 1) {
        if (tid < s) sred[tid] = fmaxf(sred[tid], sred[tid + s]);
        __syncthreads();
    }
    const float m = sred[0];
    __syncthreads();

    float sum = 0.0f;
    for (int v = tid; v < VOCAB; v += 256) sum += __expf(row[v] - m);
    sred[tid] = sum;
    __syncthreads();
    for (int s = 128; s > 0; s >>= 1) {
        if (tid < s) sred[tid] += sred[tid + s];
        __syncthreads();
    }

    if (tid == 0) {
        int nxt = target_lines[(d + 1) * BATCH + b];
        g_losses[d * BATCH + b] = -(row[nxt] - m - logf(sred[0]));
    }
}

// ---------------- deterministic final reduction ----------------
__global__ void final_kernel(float* __restrict__ out) {
    __shared__ float sred[256];
    const int tid = threadIdx.x;
    float s = 0.0f;
    for (int i = tid; i < TGT * BATCH; i += 256) s += g_losses[i];
    sred[tid] = s;
    __syncthreads();
    for (int st = 128; st > 0; st >>= 1) {
        if (tid < st) sred[tid] += sred[tid + st];
        __syncthreads();
    }
    if (tid == 0) out[0] = sred[0] * (1.0f / (float)BATCH);
}

// ---------------- host ----------------
extern "C" void kernel_launch(void* const* d_in, const int* in_sizes, int n_in,
                              void* d_out, int out_size) {
    (void)in_sizes; (void)n_in; (void)out_size;
    const int*   input_lines  = (const int*)  d_in[0];
    const int*   target_lines = (const int*)  d_in[1];
    const float* emb_in       = (const float*)d_in[2];
    const float* emb_tgt      = (const float*)d_in[3];
    const float* W_ih_enc     = (const float*)d_in[4];
    const float* W_hh_enc     = (const float*)d_in[5];
    const float* b_ih_enc     = (const float*)d_in[6];
    const float* b_hh_enc     = (const float*)d_in[7];
    const float* W_ih_dec     = (const float*)d_in[8];
    const float* W_hh_dec     = (const float*)d_in[9];
    const float* b_ih_dec     = (const float*)d_in[10];
    const float* b_hh_dec     = (const float*)d_in[11];
    const float* W_out        = (const float*)d_in[12];
    const float* b_out        = (const float*)d_in[13];
    float* out = (float*)d_out;

    init_kernel<<<(BATCH * HID + 255) / 256, 256>>>();

    // precompute all x-projections (off critical path, fully parallel)
    gx_kernel<<<dim3(G4 / 64, SRC), 256>>>(input_lines,  emb_in,  W_ih_enc, b_ih_enc, b_hh_enc, 0);
    gx_kernel<<<dim3(G4 / 64, TGT), 256>>>(target_lines, emb_tgt, W_ih_dec, b_ih_dec, b_hh_dec, SRC * BATCH);

    // encoder
    for (int t = 0; t < SRC; ++t)
        lstm_step<<<128, 256>>>(W_hh_enc, t * BATCH, t & 1, (t + 1) & 1);

    // decoder
    for (int d = 0; d < TGT; ++d) {
        int p = SRC + d;
        lstm_step<<<128, 256>>>(W_hh_dec, (SRC + d) * BATCH, p & 1, (p + 1) & 1);
        logits_kernel<<<VOCAB / 64, 256>>>((p + 1) & 1, W_out, b_out);
        loss_kernel<<<BATCH, 256>>>(target_lines, d);
    }

    final_kernel<<<1, 256>>>(out);
}

// round 2
// speedup vs baseline: 1.8759x; 1.8759x over previous
#include <cuda_runtime.h>
#include <cuda_bf16.h>
#include <math.h>

#define HID   512
#define G4    2048
#define BATCH 64
#define VOCAB 32000
#define SRC   50
#define TGT   49
#define NSTEP (SRC + TGT)

#define LOGN  128                 // logits N tile
#define LOGB  (VOCAB / LOGN)      // 250 blocks
#define KC    128                 // lstm split-K chunk

// ---------------- scratch ----------------
__device__ float g_gx[NSTEP * BATCH * G4];
__device__ float g_h[2][BATCH * HID];
__device__ float g_c[BATCH * HID];
__device__ float g_part[4][BATCH][G4];      // split-K partials
__device__ float g_pmax[BATCH * LOGB];      // per-block row max
__device__ float g_psum[BATCH * LOGB];      // per-block row sum-exp
__device__ float g_losses[TGT * BATCH];

__device__ __forceinline__ float sigmoidf_(float x) { return 1.0f / (1.0f + __expf(-x)); }

// ---------------- init ----------------
__global__ void init_kernel() {
    int i = blockIdx.x * blockDim.x + threadIdx.x;
    if (i < BATCH * HID) {
        g_h[0][i] = 0.0f;
        g_h[1][i] = 0.0f;
        g_c[i]    = 0.0f;
    }
}

// ---------------- gx = emb[tok] @ W_ih^T + b_ih + b_hh ----------------
__global__ void gx_kernel(const int* __restrict__ toks,
                          const float* __restrict__ emb,
                          const float* __restrict__ Wih,
                          const float* __restrict__ bih,
                          const float* __restrict__ bhh,
                          int gx_row0) {
    __shared__ float As[32][65];
    __shared__ float Bs[32][65];
    __shared__ int   stoks[64];

    const int tid = threadIdx.x;
    const int n0 = blockIdx.x * 64;
    const int m0 = blockIdx.y * 64;

    if (tid < 64) stoks[tid] = toks[m0 + tid];
    __syncthreads();

    const int ty = tid >> 4;
    const int tx = tid & 15;

    float acc[4][4];
#pragma unroll
    for (int i = 0; i < 4; ++i)
#pragma unroll
        for (int j = 0; j < 4; ++j) acc[i][j] = 0.0f;

    for (int kt = 0; kt < HID; kt += 32) {
#pragma unroll
        for (int i = 0; i < 8; ++i) {
            int idx = tid + i * 256;
            int m = idx >> 5;
            int k = idx & 31;
            As[k][m] = emb[(size_t)stoks[m] * HID + kt + k];
            Bs[k][m] = Wih[(size_t)(n0 + m) * HID + kt + k];
        }
        __syncthreads();
#pragma unroll
        for (int k = 0; k < 32; ++k) {
            float a[4], b[4];
#pragma unroll
            for (int i = 0; i < 4; ++i) a[i] = As[k][ty * 4 + i];
#pragma unroll
            for (int j = 0; j < 4; ++j) b[j] = Bs[k][tx * 4 + j];
#pragma unroll
            for (int i = 0; i < 4; ++i)
#pragma unroll
                for (int j = 0; j < 4; ++j) acc[i][j] += a[i] * b[j];
        }
        __syncthreads();
    }

#pragma unroll
    for (int i = 0; i < 4; ++i) {
        int m = m0 + ty * 4 + i;
#pragma unroll
        for (int j = 0; j < 4; ++j) {
            int n = n0 + tx * 4 + j;
            g_gx[(size_t)(gx_row0 + m) * G4 + n] = acc[i][j] + bih[n] + bhh[n];
        }
    }
}

// ---------------- lstm gemm: split-K partials of h @ W_hh^T ----------------
// grid = (32 n-tiles, 4 k-chunks), 256 threads, 64x64 tile, 4x4/thread
__global__ void lstm_gemm(const float* __restrict__ Whh, int hin) {
    __shared__ float As[32][65];
    __shared__ float Bs[32][65];

    const int tid = threadIdx.x;
    const int n0 = blockIdx.x * 64;
    const int kc = blockIdx.y;
    const int kbase = kc * KC;
    const int ty = tid >> 4;
    const int tx = tid & 15;
    const float* h = g_h[hin];

    float acc[4][4];
#pragma unroll
    for (int i = 0; i < 4; ++i)
#pragma unroll
        for (int j = 0; j < 4; ++j) acc[i][j] = 0.0f;

    for (int kt = 0; kt < KC; kt += 32) {
#pragma unroll
        for (int i = 0; i < 8; ++i) {
            int idx = tid + i * 256;
            int m = idx >> 5;
            int k = idx & 31;
            As[k][m] = h[(size_t)m * HID + kbase + kt + k];
            Bs[k][m] = Whh[(size_t)(n0 + m) * HID + kbase + kt + k];
        }
        __syncthreads();
#pragma unroll
        for (int k = 0; k < 32; ++k) {
            float a[4], b[4];
#pragma unroll
            for (int i = 0; i < 4; ++i) a[i] = As[k][ty * 4 + i];
#pragma unroll
            for (int j = 0; j < 4; ++j) b[j] = Bs[k][tx * 4 + j];
#pragma unroll
            for (int i = 0; i < 4; ++i)
#pragma unroll
                for (int j = 0; j < 4; ++j) acc[i][j] += a[i] * b[j];
        }
        __syncthreads();
    }

#pragma unroll
    for (int i = 0; i < 4; ++i) {
        int m = ty * 4 + i;
#pragma unroll
        for (int j = 0; j < 4; ++j)
            g_part[kc][m][n0 + tx * 4 + j] = acc[i][j];
    }
}

// ---------------- cell update: combine partials + gx, update c/h ----------------
__global__ void lstm_cell(int gxrow, int hout) {
    const int idx = blockIdx.x * 256 + threadIdx.x;   // 32768 = BATCH*HID
    const int b = idx >> 9;
    const int j = idx & 511;
    const float* gxp = g_gx + (size_t)(gxrow + b) * G4;

    float gate[4];
#pragma unroll
    for (int g = 0; g < 4; ++g) {
        int n = g * HID + j;
        float v = gxp[n];
#pragma unroll
        for (int kc = 0; kc < 4; ++kc) v += g_part[kc][b][n];
        gate[g] = v;
    }
    float cc = g_c[idx];
    float cn = sigmoidf_(gate[1]) * cc + sigmoidf_(gate[0]) * tanhf(gate[2]);
    float hn = sigmoidf_(gate[3]) * tanhf(cn);
    g_c[idx] = cn;
    g_h[hout][idx] = hn;
}

// ---------------- logits GEMM + fused log-sum-exp partials ----------------
// grid = 250 blocks (128 vocab cols each), 128 threads, 64x128 tile, 8x8/thread
__global__ void logits_lse_kernel(int hsel,
                                  const float* __restrict__ Wout,
                                  const float* __restrict__ bout) {
    __shared__ float As[32][68];
    __shared__ float Bs[32][132];
    __shared__ float red[64][17];
    __shared__ float rowmax[64];

    const int tid = threadIdx.x;    // 0..127
    const int tx = tid & 15;        // N: 8 cols each
    const int ty = tid >> 4;        // M: 8 rows each (0..7)
    const int n0 = blockIdx.x * LOGN;
    const float* h = g_h[hsel];

    float acc[8][8];
#pragma unroll
    for (int i = 0; i < 8; ++i)
#pragma unroll
        for (int j = 0; j < 8; ++j) acc[i][j] = 0.0f;

    for (int kt = 0; kt < HID; kt += 32) {
        // As: 64m x 32k = 512 float4, 4 per thread
#pragma unroll
        for (int i = 0; i < 4; ++i) {
            int f = tid + i * 128;
            int m = f >> 3;
            int kq = f & 7;
            float4 v = *(const float4*)&h[(size_t)m * HID + kt + kq * 4];
            As[kq * 4 + 0][m] = v.x;
            As[kq * 4 + 1][m] = v.y;
            As[kq * 4 + 2][m] = v.z;
            As[kq * 4 + 3][m] = v.w;
        }
        // Bs: 128n x 32k = 1024 float4, 8 per thread
#pragma unroll
        for (int i = 0; i < 8; ++i) {
            int f = tid + i * 128;
            int n = f >> 3;
            int kq = f & 7;
            float4 v = *(const float4*)&Wout[(size_t)(n0 + n) * HID + kt + kq * 4];
            Bs[kq * 4 + 0][n] = v.x;
            Bs[kq * 4 + 1][n] = v.y;
            Bs[kq * 4 + 2][n] = v.z;
            Bs[kq * 4 + 3][n] = v.w;
        }
        __syncthreads();
#pragma unroll
        for (int k = 0; k < 32; ++k) {
            float a[8], b[8];
            *(float4*)&a[0] = *(float4*)&As[k][ty * 8];
            *(float4*)&a[4] = *(float4*)&As[k][ty * 8 + 4];
            *(float4*)&b[0] = *(float4*)&Bs[k][tx * 8];
            *(float4*)&b[4] = *(float4*)&Bs[k][tx * 8 + 4];
#pragma unroll
            for (int i = 0; i < 8; ++i)
#pragma unroll
                for (int j = 0; j < 8; ++j) acc[i][j] += a[i] * b[j];
        }
        __syncthreads();
    }

    // add bias
    float bv[8];
    *(float4*)&bv[0] = *(const float4*)&bout[n0 + tx * 8];
    *(float4*)&bv[4] = *(const float4*)&bout[n0 + tx * 8 + 4];
#pragma unroll
    for (int i = 0; i < 8; ++i)
#pragma unroll
        for (int j = 0; j < 8; ++j) acc[i][j] += bv[j];

    // per-row local max
#pragma unroll
    for (int i = 0; i < 8; ++i) {
        float lm = acc[i][0];
#pragma unroll
        for (int j = 1; j < 8; ++j) lm = fmaxf(lm, acc[i][j]);
        red[ty * 8 + i][tx] = lm;
    }
    __syncthreads();
    if (tid < 64) {
        float m = red[tid][0];
#pragma unroll
        for (int t = 1; t < 16; ++t) m = fmaxf(m, red[tid][t]);
        rowmax[tid] = m;
    }
    __syncthreads();

    // per-row local sum-exp (relative to row max)
#pragma unroll
    for (int i = 0; i < 8; ++i) {
        float rm = rowmax[ty * 8 + i];
        float s = 0.0f;
#pragma unroll
        for (int j = 0; j < 8; ++j) s += __expf(acc[i][j] - rm);
        red[ty * 8 + i][tx] = s;
    }
    __syncthreads();
    if (tid < 64) {
        float s = 0.0f;
#pragma unroll
        for (int t = 0; t < 16; ++t) s += red[tid][t];
        g_pmax[tid * LOGB + blockIdx.x] = rowmax[tid];
        g_psum[tid * LOGB + blockIdx.x] = s;
    }
}

// ---------------- combine partials -> per-(d,b) loss ----------------
// grid = 64 blocks (1 per batch row), 128 threads
__global__ void combine_loss_kernel(const int* __restrict__ target_lines,
                                    const float* __restrict__ Wout,
                                    const float* __restrict__ bout,
                                    int hsel, int d) {
    __shared__ float sred[128];
    const int b = blockIdx.x;
    const int tid = threadIdx.x;

    // global row max
    float m = -INFINITY;
    for (int p = tid; p < LOGB; p += 128) m = fmaxf(m, g_pmax[b * LOGB + p]);
    sred[tid] = m;
    __syncthreads();
    for (int s = 64; s > 0; s >>= 1) {
        if (tid < s) sred[tid] = fmaxf(sred[tid], sred[tid + s]);
        __syncthreads();
    }
    const float gmax = sred[0];
    __syncthreads();

    // global sum-exp
    float sum = 0.0f;
    for (int p = tid; p < LOGB; p += 128)
        sum += g_psum[b * LOGB + p] * __expf(g_pmax[b * LOGB + p] - gmax);
    sred[tid] = sum;
    __syncthreads();
    for (int s = 64; s > 0; s >>= 1) {
        if (tid < s) sred[tid] += sred[tid + s];
        __syncthreads();
    }
    const float gsum = sred[0];
    __syncthreads();

    // target logit: dot(h[b], Wout[nxt]) + bout[nxt]
    const int nxt = target_lines[(d + 1) * BATCH + b];
    float4 hv = ((const float4*)&g_h[hsel][b * HID])[tid];
    float4 wv = ((const float4*)&Wout[(size_t)nxt * HID])[tid];
    float ds = hv.x * wv.x + hv.y * wv.y + hv.z * wv.z + hv.w * wv.w;
    sred[tid] = ds;
    __syncthreads();
    for (int s = 64; s > 0; s >>= 1) {
        if (tid < s) sred[tid] += sred[tid + s];
        __syncthreads();
    }
    if (tid == 0)
        g_losses[d * BATCH + b] = -(sred[0] + bout[nxt] - gmax - logf(gsum));
}

// ---------------- deterministic final reduction ----------------
__global__ void final_kernel(float* __restrict__ out) {
    __shared__ float sred[256];
    const int tid = threadIdx.x;
    float s = 0.0f;
    for (int i = tid; i < TGT * BATCH; i += 256) s += g_losses[i];
    sred[tid] = s;
    __syncthreads();
    for (int st = 128; st > 0; st >>= 1) {
        if (tid < st) sred[tid] += sred[tid + st];
        __syncthreads();
    }
    if (tid == 0) out[0] = sred[0] * (1.0f / (float)BATCH);
}

// ---------------- host ----------------
extern "C" void kernel_launch(void* const* d_in, const int* in_sizes, int n_in,
                              void* d_out, int out_size) {
    (void)in_sizes; (void)n_in; (void)out_size;
    const int*   input_lines  = (const int*)  d_in[0];
    const int*   target_lines = (const int*)  d_in[1];
    const float* emb_in       = (const float*)d_in[2];
    const float* emb_tgt      = (const float*)d_in[3];
    const float* W_ih_enc     = (const float*)d_in[4];
    const float* W_hh_enc     = (const float*)d_in[5];
    const float* b_ih_enc     = (const float*)d_in[6];
    const float* b_hh_enc     = (const float*)d_in[7];
    const float* W_ih_dec     = (const float*)d_in[8];
    const float* W_hh_dec     = (const float*)d_in[9];
    const float* b_ih_dec     = (const float*)d_in[10];
    const float* b_hh_dec     = (const float*)d_in[11];
    const float* W_out        = (const float*)d_in[12];
    const float* b_out        = (const float*)d_in[13];
    float* out = (float*)d_out;

    init_kernel<<<(BATCH * HID + 255) / 256, 256>>>();

    gx_kernel<<<dim3(G4 / 64, SRC), 256>>>(input_lines,  emb_in,  W_ih_enc, b_ih_enc, b_hh_enc, 0);
    gx_kernel<<<dim3(G4 / 64, TGT), 256>>>(target_lines, emb_tgt, W_ih_dec, b_ih_dec, b_hh_dec, SRC * BATCH);

    for (int p = 0; p < NSTEP; ++p) {
        const float* Whh = (p < SRC) ? W_hh_enc : W_hh_dec;
        lstm_gemm<<<dim3(32, 4), 256>>>(Whh, p & 1);
        lstm_cell<<<128, 256>>>(p * BATCH, (p + 1) & 1);
        if (p >= SRC) {
            int d = p - SRC;
            logits_lse_kernel<<<LOGB, 128>>>((p + 1) & 1, W_out, b_out);
            combine_loss_kernel<<<BATCH, 128>>>(target_lines, W_out, b_out, (p + 1) & 1, d);
        }
    }

    final_kernel<<<1, 256>>>(out);
}

// round 4
// speedup vs baseline: 4.9846x; 2.6572x over previous
#include <cuda_runtime.h>
#include <cuda_bf16.h>
#include <math.h>
#include <stdint.h>

#define HID   512
#define G4    2048
#define BATCH 64
#define VOCAB 32000
#define SRC   50
#define TGT   49
#define NSTEP (SRC + TGT)

#define VTILES 250               // 32000 / 128
#define DROWS  (TGT * BATCH)     // 3136 decode rows
#define DROWS_PAD 3328           // 26 * 128
#define GXROWS (NSTEP * BATCH)

// ---------------- static scratch ----------------
__device__ float g_gx[(size_t)GXROWS * G4];
__device__ float g_h[2][BATCH * HID];
__device__ float g_c[BATCH * HID];
__device__ float g_part[8][BATCH][G4];
__device__ float g_hall_f[(size_t)DROWS * HID];
__device__ __nv_bfloat16 g_hall_b[(size_t)DROWS_PAD * HID];   // pad rows stay zero (.bss)
__device__ __nv_bfloat16 g_wout_b[(size_t)VOCAB * HID];
__device__ float g_pmax[(size_t)DROWS * VTILES];
__device__ float g_psum[(size_t)DROWS * VTILES];
__device__ float g_losses[DROWS];

// ---------------- helpers ----------------
__device__ __forceinline__ uint32_t smem_u32(const void* p) {
    uint32_t a;
    asm("{ .reg .u64 t; cvta.to.shared.u64 t, %1; cvt.u32.u64 %0, t; }" : "=r"(a) : "l"(p));
    return a;
}

__device__ __forceinline__ void ldsm_x4(uint32_t* r, uint32_t addr) {
    asm volatile("ldmatrix.sync.aligned.m8n8.x4.shared.b16 {%0,%1,%2,%3}, [%4];"
        : "=r"(r[0]), "=r"(r[1]), "=r"(r[2]), "=r"(r[3]) : "r"(addr));
}
__device__ __forceinline__ void ldsm_x2t(uint32_t* r, uint32_t addr) {
    asm volatile("ldmatrix.sync.aligned.m8n8.x2.trans.shared.b16 {%0,%1}, [%2];"
        : "=r"(r[0]), "=r"(r[1]) : "r"(addr));
}
__device__ __forceinline__ void mma_bf16(float* c, const uint32_t* a, const uint32_t* b) {
    asm volatile("mma.sync.aligned.m16n8k16.row.col.f32.bf16.bf16.f32 "
        "{%0,%1,%2,%3}, {%4,%5,%6,%7}, {%8,%9}, {%0,%1,%2,%3};"
        : "+f"(c[0]), "+f"(c[1]), "+f"(c[2]), "+f"(c[3])
        : "r"(a[0]), "r"(a[1]), "r"(a[2]), "r"(a[3]), "r"(b[0]), "r"(b[1]));
}

__device__ __forceinline__ float sigmoidf_(float x) { return 1.0f / (1.0f + __expf(-x)); }

// fast exp on the FMA pipe (~2e-6 rel)
__device__ __forceinline__ float fexp(float x) {
    x = fmaxf(x, -87.0f);
    float y = x * 1.44269504088896f;
    float r = rintf(y);
    float f = (y - r) * 0.693147180559945f;
    float p = 1.0f + f * (1.0f + f * (0.5f + f * (0.16666667f + f * (0.041666667f + f * 0.0083333333f))));
    return __int_as_float(((int)r + 127) << 23) * p;
}

// ---------------- init ----------------
__global__ void init_kernel() {
    int i = blockIdx.x * blockDim.x + threadIdx.x;
    if (i < BATCH * HID) {
        g_h[0][i] = 0.0f;
        g_h[1][i] = 0.0f;
        g_c[i]    = 0.0f;
    }
}

// ---------------- W_out fp32 -> bf16 ----------------
__global__ void wout_conv(const float* __restrict__ Wout) {
    size_t i = (size_t)(blockIdx.x * 256 + threadIdx.x) * 4;
    float4 v = *(const float4*)&Wout[i];
    __nv_bfloat162 a = __floats2bfloat162_rn(v.x, v.y);
    __nv_bfloat162 b = __floats2bfloat162_rn(v.z, v.w);
    *(uint32_t*)&g_wout_b[i]     = *(uint32_t*)&a;
    *(uint32_t*)&g_wout_b[i + 2] = *(uint32_t*)&b;
}

// ---------------- gx = emb[tok] @ W_ih^T + b_ih + b_hh (fp32 SIMT, exact) ----------------
__global__ void gx_kernel(const int* __restrict__ toks,
                          const float* __restrict__ emb,
                          const float* __restrict__ Wih,
                          const float* __restrict__ bih,
                          const float* __restrict__ bhh,
                          int gx_row0) {
    __shared__ float As[32][65];
    __shared__ float Bs[32][65];
    __shared__ int   stoks[64];

    const int tid = threadIdx.x;
    const int n0 = blockIdx.x * 64;
    const int m0 = blockIdx.y * 64;

    if (tid < 64) stoks[tid] = toks[m0 + tid];
    __syncthreads();

    const int ty = tid >> 4;
    const int tx = tid & 15;

    float acc[4][4];
#pragma unroll
    for (int i = 0; i < 4; ++i)
#pragma unroll
        for (int j = 0; j < 4; ++j) acc[i][j] = 0.0f;

    for (int kt = 0; kt < HID; kt += 32) {
#pragma unroll
        for (int i = 0; i < 8; ++i) {
            int idx = tid + i * 256;
            int m = idx >> 5;
            int k = idx & 31;
            As[k][m] = emb[(size_t)stoks[m] * HID + kt + k];
            Bs[k][m] = Wih[(size_t)(n0 + m) * HID + kt + k];
        }
        __syncthreads();
#pragma unroll
        for (int k = 0; k < 32; ++k) {
            float a[4], b[4];
#pragma unroll
            for (int i = 0; i < 4; ++i) a[i] = As[k][ty * 4 + i];
#pragma unroll
            for (int j = 0; j < 4; ++j) b[j] = Bs[k][tx * 4 + j];
#pragma unroll
            for (int i = 0; i < 4; ++i)
#pragma unroll
                for (int j = 0; j < 4; ++j) acc[i][j] += a[i] * b[j];
        }
        __syncthreads();
    }

#pragma unroll
    for (int i = 0; i < 4; ++i) {
        int m = m0 + ty * 4 + i;
#pragma unroll
        for (int j = 0; j < 4; ++j) {
            int n = n0 + tx * 4 + j;
            g_gx[(size_t)(gx_row0 + m) * G4 + n] = acc[i][j] + bih[n] + bhh[n];
        }
    }
}

// ---------------- lstm: split-K gemm (KC=64, 8 chunks) ----------------
__global__ void lstm_gemm(const float* __restrict__ Whh, int hin) {
    __shared__ float As[32][65];
    __shared__ float Bs[32][65];
    const int tid = threadIdx.x;
    const int n0 = blockIdx.x * 64;
    const int kc = blockIdx.y;
    const int kbase = kc * 64;
    const int ty = tid >> 4;
    const int tx = tid & 15;
    const float* h = g_h[hin];

    float acc[4][4];
#pragma unroll
    for (int i = 0; i < 4; ++i)
#pragma unroll
        for (int j = 0; j < 4; ++j) acc[i][j] = 0.0f;

#pragma unroll
    for (int kt = 0; kt < 64; kt += 32) {
#pragma unroll
        for (int i = 0; i < 8; ++i) {
            int idx = tid + i * 256;
            int m = idx >> 5;
            int k = idx & 31;
            As[k][m] = h[(size_t)m * HID + kbase + kt + k];
            Bs[k][m] = Whh[(size_t)(n0 + m) * HID + kbase + kt + k];
        }
        __syncthreads();
#pragma unroll
        for (int k = 0; k < 32; ++k) {
            float a[4], b[4];
#pragma unroll
            for (int i = 0; i < 4; ++i) a[i] = As[k][ty * 4 + i];
#pragma unroll
            for (int j = 0; j < 4; ++j) b[j] = Bs[k][tx * 4 + j];
#pragma unroll
            for (int i = 0; i < 4; ++i)
#pragma unroll
                for (int j = 0; j < 4; ++j) acc[i][j] += a[i] * b[j];
        }
        __syncthreads();
    }
#pragma unroll
    for (int i = 0; i < 4; ++i) {
        int m = ty * 4 + i;
#pragma unroll
        for (int j = 0; j < 4; ++j)
            g_part[kc][m][n0 + tx * 4 + j] = acc[i][j];
    }
}

__global__ void lstm_cell(int gxrow, int hout, int hall0) {
    const int idx = blockIdx.x * 256 + threadIdx.x;
    const int b = idx >> 9;
    const int j = idx & 511;
    const float* gxp = g_gx + (size_t)(gxrow + b) * G4;

    float gate[4];
#pragma unroll
    for (int g = 0; g < 4; ++g) {
        int n = g * HID + j;
        float v = gxp[n];
#pragma unroll
        for (int kc = 0; kc < 8; ++kc) v += g_part[kc][b][n];
        gate[g] = v;
    }
    float cc = g_c[idx];
    float cn = sigmoidf_(gate[1]) * cc + sigmoidf_(gate[0]) * tanhf(gate[2]);
    float hn = sigmoidf_(gate[3]) * tanhf(cn);
    g_c[idx] = cn;
    g_h[hout][idx] = hn;
    if (hall0 >= 0) {
        size_t r = (size_t)(hall0 + b) * HID + j;
        g_hall_f[r] = hn;
        g_hall_b[r] = __float2bfloat16(hn);
    }
}

// ================= batched logits GEMM + fused LSE partials (mma.sync bf16) =================
// C[m=decode rows, n=vocab] = hall_b @ wout_b^T. Block tile 128x128, K=512.
// 8 warps: 4 along M (32 rows each) x 2 along N (64 cols each). m16n8k16 HMMA.
#define LG_A    0                 // A tile: 128 x 64 bf16 = 16384
#define LG_B    16384             // B tile: 128 x 64 bf16 = 16384
#define LG_BIAS 32768             // 128 f32 = 512
#define LG_D    33280             // 128 x 132 f32 = 67584
#define LG_SMEM (33280 + 67584)   // 100864

__global__ __launch_bounds__(256) void logits_mma(const float* __restrict__ bout) {
    extern __shared__ char sm[];
    const uint32_t sbase = smem_u32(sm);
    const int tid = threadIdx.x;
    const int l = tid & 31;
    const int w = tid >> 5;
    const int wr = w & 3;          // M warp (32 rows)
    const int wc = w >> 2;         // N warp (64 cols)
    const int n0 = blockIdx.x * 128;
    const int m0 = blockIdx.y * 128;

    float acc[2][8][4];
#pragma unroll
    for (int i = 0; i < 2; ++i)
#pragma unroll
        for (int j = 0; j < 8; ++j)
#pragma unroll
            for (int q = 0; q < 4; ++q) acc[i][j][q] = 0.0f;

    // per-thread ldmatrix row/col components
    const int a_row = wr * 32 + (l & 7) + ((l & 8) ? 8 : 0);
    const int a_k8  = (l & 16) ? 8 : 0;
    const int b_nr  = (l & 7);
    const int b_k8  = (l & 8) ? 8 : 0;

    for (int kb = 0; kb < HID; kb += 64) {
        // stage A (decode rows) and B (vocab rows): 128 rows x 64 k bf16 each, XOR-swizzled
#pragma unroll
        for (int i = 0; i < 4; ++i) {
            int c = tid + i * 256;       // 1024 16B-chunks
            int row = c >> 3;
            int k8 = (c & 7) * 8;
            uint32_t so = (uint32_t)(row * 128 + ((k8 * 2) ^ ((row & 7) << 4)));
            *(uint4*)(sm + LG_A + so) = *(const uint4*)&g_hall_b[(size_t)(m0 + row) * HID + kb + k8];
            *(uint4*)(sm + LG_B + so) = *(const uint4*)&g_wout_b[(size_t)(n0 + row) * HID + kb + k8];
        }
        __syncthreads();

#pragma unroll
        for (int ks = 0; ks < 4; ++ks) {
            uint32_t a[2][4];
#pragma unroll
            for (int i = 0; i < 2; ++i) {
                int ar = a_row + i * 16;
                int ak = ks * 16 + a_k8;
                ldsm_x4(a[i], sbase + LG_A + ar * 128 + ((ak * 2) ^ ((ar & 7) << 4)));
            }
#pragma unroll
            for (int j = 0; j < 8; ++j) {
                int bn = wc * 64 + j * 8 + b_nr;
                int bk = ks * 16 + b_k8;
                uint32_t b[2];
                ldsm_x2t(b, sbase + LG_B + bn * 128 + ((bk * 2) ^ ((bn & 7) << 4)));
                mma_bf16(acc[0][j], a[0], b);
                mma_bf16(acc[1][j], a[1], b);
            }
        }
        __syncthreads();
    }

    // stage C to SMEM [128 m][132]
    float* Ds = (float*)(sm + LG_D);
#pragma unroll
    for (int i = 0; i < 2; ++i)
#pragma unroll
        for (int j = 0; j < 8; ++j) {
            int row = wr * 32 + i * 16 + (l >> 2);
            int col = wc * 64 + j * 8 + (l & 3) * 2;
            Ds[row * 132 + col]           = acc[i][j][0];
            Ds[row * 132 + col + 1]       = acc[i][j][1];
            Ds[(row + 8) * 132 + col]     = acc[i][j][2];
            Ds[(row + 8) * 132 + col + 1] = acc[i][j][3];
        }
    float* bias_s = (float*)(sm + LG_BIAS);
    if (tid < 128) bias_s[tid] = bout[n0 + tid];
    __syncthreads();

    // per decode-row max + sumexp over this block's 128 vocab cols (2 threads/row)
    {
        const int row = tid >> 1;
        const int half = tid & 1;
        const float* dr = &Ds[row * 132 + half * 64];
        const float* bs = &bias_s[half * 64];
        float m = -INFINITY;
#pragma unroll 8
        for (int c = 0; c < 64; ++c) m = fmaxf(m, dr[c] + bs[c]);
        float s = 0.0f;
#pragma unroll 8
        for (int c = 0; c < 64; ++c) s += fexp(dr[c] + bs[c] - m);
        float mo = __shfl_xor_sync(0xffffffffu, m, 1);
        float so = __shfl_xor_sync(0xffffffffu, s, 1);
        float mm = fmaxf(m, mo);
        float ss = s * fexp(m - mm) + so * fexp(mo - mm);
        int gr = m0 + row;
        if (half == 0 && gr < DROWS) {
            g_pmax[(size_t)gr * VTILES + blockIdx.x] = mm;
            g_psum[(size_t)gr * VTILES + blockIdx.x] = ss;
        }
    }
}

// ================= combine partials -> per-(d,b) loss =================
__global__ void combine_loss(const int* __restrict__ target_lines,
                             const float* __restrict__ Wout,
                             const float* __restrict__ bout) {
    __shared__ float sred[128];
    const int b = blockIdx.x;
    const int d = blockIdx.y;
    const int bs = d * BATCH + b;
    const int tid = threadIdx.x;

    float m = -INFINITY;
    for (int p = tid; p < VTILES; p += 128) m = fmaxf(m, g_pmax[(size_t)bs * VTILES + p]);
    sred[tid] = m;
    __syncthreads();
    for (int s = 64; s > 0; s >>= 1) {
        if (tid < s) sred[tid] = fmaxf(sred[tid], sred[tid + s]);
        __syncthreads();
    }
    const float gmax = sred[0];
    __syncthreads();

    float sum = 0.0f;
    for (int p = tid; p < VTILES; p += 128)
        sum += g_psum[(size_t)bs * VTILES + p] * __expf(g_pmax[(size_t)bs * VTILES + p] - gmax);
    sred[tid] = sum;
    __syncthreads();
    for (int s = 64; s > 0; s >>= 1) {
        if (tid < s) sred[tid] += sred[tid + s];
        __syncthreads();
    }
    const float gsum = sred[0];
    __syncthreads();

    // target logit in bf16 (consistent with the GEMM's operand precision)
    const int nxt = target_lines[(d + 1) * BATCH + b];
    float4 hv = ((const float4*)&g_hall_f[(size_t)bs * HID])[tid];
    const __nv_bfloat16* wrow = &g_wout_b[(size_t)nxt * HID];
    float w0 = __bfloat162float(wrow[tid * 4 + 0]);
    float w1 = __bfloat162float(wrow[tid * 4 + 1]);
    float w2 = __bfloat162float(wrow[tid * 4 + 2]);
    float w3 = __bfloat162float(wrow[tid * 4 + 3]);
    float h0 = __bfloat162float(__float2bfloat16(hv.x));
    float h1 = __bfloat162float(__float2bfloat16(hv.y));
    float h2 = __bfloat162float(__float2bfloat16(hv.z));
    float h3 = __bfloat162float(__float2bfloat16(hv.w));
    sred[tid] = h0 * w0 + h1 * w1 + h2 * w2 + h3 * w3;
    __syncthreads();
    for (int s = 64; s > 0; s >>= 1) {
        if (tid < s) sred[tid] += sred[tid + s];
        __syncthreads();
    }
    if (tid == 0)
        g_losses[bs] = -(sred[0] + bout[nxt] - gmax - logf(gsum));
}

// ---------------- final deterministic sum ----------------
__global__ void final_kernel(float* __restrict__ out) {
    __shared__ float sred[256];
    const int tid = threadIdx.x;
    float s = 0.0f;
    for (int i = tid; i < DROWS; i += 256) s += g_losses[i];
    sred[tid] = s;
    __syncthreads();
    for (int st = 128; st > 0; st >>= 1) {
        if (tid < st) sred[tid] += sred[tid + st];
        __syncthreads();
    }
    if (tid == 0) out[0] = sred[0] * (1.0f / (float)BATCH);
}

// ---------------- host ----------------
extern "C" void kernel_launch(void* const* d_in, const int* in_sizes, int n_in,
                              void* d_out, int out_size) {
    (void)in_sizes; (void)n_in; (void)out_size;
    const int*   input_lines  = (const int*)  d_in[0];
    const int*   target_lines = (const int*)  d_in[1];
    const float* emb_in       = (const float*)d_in[2];
    const float* emb_tgt      = (const float*)d_in[3];
    const float* W_ih_enc     = (const float*)d_in[4];
    const float* W_hh_enc     = (const float*)d_in[5];
    const float* b_ih_enc     = (const float*)d_in[6];
    const float* b_hh_enc     = (const float*)d_in[7];
    const float* W_ih_dec     = (const float*)d_in[8];
    const float* W_hh_dec     = (const float*)d_in[9];
    const float* b_ih_dec     = (const float*)d_in[10];
    const float* b_hh_dec     = (const float*)d_in[11];
    const float* W_out        = (const float*)d_in[12];
    const float* b_out        = (const float*)d_in[13];
    float* out = (float*)d_out;

    cudaFuncSetAttribute(logits_mma, cudaFuncAttributeMaxDynamicSharedMemorySize, LG_SMEM);

    init_kernel<<<(BATCH * HID + 255) / 256, 256>>>();
    wout_conv<<<VOCAB * HID / 4 / 256, 256>>>(W_out);

    gx_kernel<<<dim3(G4 / 64, SRC), 256>>>(input_lines,  emb_in,  W_ih_enc, b_ih_enc, b_hh_enc, 0);
    gx_kernel<<<dim3(G4 / 64, TGT), 256>>>(target_lines, emb_tgt, W_ih_dec, b_ih_dec, b_hh_dec, SRC * BATCH);

    for (int p = 0; p < NSTEP; ++p) {
        const float* Whh = (p < SRC) ? W_hh_enc : W_hh_dec;
        lstm_gemm<<<dim3(32, 8), 256>>>(Whh, p & 1);
        int hall0 = (p >= SRC) ? (p - SRC) * BATCH : -1;
        lstm_cell<<<128, 256>>>(p * BATCH, (p + 1) & 1, hall0);
    }

    logits_mma<<<dim3(VTILES, DROWS_PAD / 128), 256, LG_SMEM>>>(b_out);
    combine_loss<<<dim3(BATCH, TGT), 128>>>(target_lines, W_out, b_out);
    final_kernel<<<1, 256>>>(out);
}

// round 5
// speedup vs baseline: 6.8121x; 1.3666x over previous
#include <cuda_runtime.h>
#include <cuda_bf16.h>
#include <math.h>
#include <stdint.h>

#define HID   512
#define G4    2048
#define BATCH 64
#define VOCAB 32000
#define SRC   50
#define TGT   49
#define NSTEP (SRC + TGT)

#define VTILES 250               // 32000 / 128
#define DROWS  (TGT * BATCH)     // 3136 decode rows
#define DROWS_PAD 3328           // 26 * 128
#define GXROWS (NSTEP * BATCH)   // 6336
#define XROWS_PAD 6400           // 50 * 128
#define PCTAS 64

// ---------------- static scratch ----------------
__device__ float g_gx[(size_t)GXROWS * G4];
__device__ __nv_bfloat16 g_x_b[(size_t)XROWS_PAD * HID];
__device__ __nv_bfloat16 g_wih_b[2][(size_t)G4 * HID];
__device__ __nv_bfloat16 g_whh_hi[2][(size_t)G4 * HID];
__device__ __nv_bfloat16 g_whh_lo[2][(size_t)G4 * HID];
__device__ __nv_bfloat16 g_hs[2][128 * HID];          // [hi(64 rows); lo(64 rows)] ping-pong
__device__ float g_hall_f[(size_t)DROWS * HID];
__device__ __nv_bfloat16 g_hall_b[(size_t)DROWS_PAD * HID];  // pad rows stay zero
__device__ __nv_bfloat16 g_wout_b[(size_t)VOCAB * HID];
__device__ float g_pmax[(size_t)DROWS * VTILES];
__device__ float g_psum[(size_t)DROWS * VTILES];
__device__ float g_losses[DROWS];
__device__ unsigned g_cnt;
__device__ volatile unsigned g_gen;

// ---------------- helpers ----------------
__device__ __forceinline__ uint32_t smem_u32(const void* p) {
    uint32_t a;
    asm("{ .reg .u64 t; cvta.to.shared.u64 t, %1; cvt.u32.u64 %0, t; }" : "=r"(a) : "l"(p));
    return a;
}
__device__ __forceinline__ void ldsm_x4(uint32_t* r, uint32_t addr) {
    asm volatile("ldmatrix.sync.aligned.m8n8.x4.shared.b16 {%0,%1,%2,%3}, [%4];"
        : "=r"(r[0]), "=r"(r[1]), "=r"(r[2]), "=r"(r[3]) : "r"(addr));
}
__device__ __forceinline__ void ldsm_x2t(uint32_t* r, uint32_t addr) {
    asm volatile("ldmatrix.sync.aligned.m8n8.x2.trans.shared.b16 {%0,%1}, [%2];"
        : "=r"(r[0]), "=r"(r[1]) : "r"(addr));
}
__device__ __forceinline__ void mma_bf16(float* c, const uint32_t* a, const uint32_t* b) {
    asm volatile("mma.sync.aligned.m16n8k16.row.col.f32.bf16.bf16.f32 "
        "{%0,%1,%2,%3}, {%4,%5,%6,%7}, {%8,%9}, {%0,%1,%2,%3};"
        : "+f"(c[0]), "+f"(c[1]), "+f"(c[2]), "+f"(c[3])
        : "r"(a[0]), "r"(a[1]), "r"(a[2]), "r"(a[3]), "r"(b[0]), "r"(b[1]));
}
__device__ __forceinline__ float sigmoidf_(float x) { return 1.0f / (1.0f + __expf(-x)); }
__device__ __forceinline__ float fexp(float x) {
    x = fmaxf(x, -87.0f);
    float y = x * 1.44269504088896f;
    float r = rintf(y);
    float f = (y - r) * 0.693147180559945f;
    float p = 1.0f + f * (1.0f + f * (0.5f + f * (0.16666667f + f * (0.041666667f + f * 0.0083333333f))));
    return __int_as_float(((int)r + 127) << 23) * p;
}

// ---------------- init: zero h ping-pong, reset barrier ----------------
__global__ void init_kernel() {
    int i = blockIdx.x * blockDim.x + threadIdx.x;
    if (i < 2 * 128 * HID / 2) ((uint32_t*)g_hs)[i] = 0u;
    if (i == 0) { g_cnt = 0u; g_gen = 0u; }
}

// ---------------- fp32 -> bf16 conversions ----------------
__global__ void conv_plain(const float* __restrict__ src, __nv_bfloat16* dst_is_wout, int sel, int side) {
    size_t i = ((size_t)blockIdx.x * 256 + threadIdx.x) * 4;
    float4 v = *(const float4*)&src[i];
    __nv_bfloat16* dst = (sel == 0) ? g_wih_b[side] : g_wout_b;
    __nv_bfloat162 a = __floats2bfloat162_rn(v.x, v.y);
    __nv_bfloat162 b = __floats2bfloat162_rn(v.z, v.w);
    *(uint32_t*)&dst[i]     = *(uint32_t*)&a;
    *(uint32_t*)&dst[i + 2] = *(uint32_t*)&b;
}
__global__ void conv_split(const float* __restrict__ src, int side) {
    size_t i = ((size_t)blockIdx.x * 256 + threadIdx.x) * 4;
    float4 v = *(const float4*)&src[i];
    float f[4] = {v.x, v.y, v.z, v.w};
    __nv_bfloat16 hi[4], lo[4];
#pragma unroll
    for (int j = 0; j < 4; ++j) {
        hi[j] = __float2bfloat16(f[j]);
        lo[j] = __float2bfloat16(f[j] - __bfloat162float(hi[j]));
    }
    *(uint2*)&g_whh_hi[side][i] = *(uint2*)hi;
    *(uint2*)&g_whh_lo[side][i] = *(uint2*)lo;
}

// ---------------- gather emb rows -> bf16 x matrix ----------------
__global__ void prep_x(const int* __restrict__ inl, const int* __restrict__ tgl,
                       const float* __restrict__ embi, const float* __restrict__ embt) {
    int row = blockIdx.x;
    int k = threadIdx.x * 8;
    int tok; const float* e;
    if (row < SRC * BATCH)       { tok = inl[row]; e = embi; }
    else if (row < GXROWS)       { tok = tgl[row - SRC * BATCH]; e = embt; }
    else                         { tok = 0; e = embi; }
    const float4* s = (const float4*)(e + (size_t)tok * HID + k);
    float4 v0 = s[0], v1 = s[1];
    __nv_bfloat162 p0 = __floats2bfloat162_rn(v0.x, v0.y);
    __nv_bfloat162 p1 = __floats2bfloat162_rn(v0.z, v0.w);
    __nv_bfloat162 p2 = __floats2bfloat162_rn(v1.x, v1.y);
    __nv_bfloat162 p3 = __floats2bfloat162_rn(v1.z, v1.w);
    uint4 o = make_uint4(*(uint32_t*)&p0, *(uint32_t*)&p1, *(uint32_t*)&p2, *(uint32_t*)&p3);
    *(uint4*)&g_x_b[(size_t)row * HID + k] = o;
}

// ================= gx GEMM: gx = x @ W_ih^T + b_ih + b_hh (bf16 HMMA) =================
// grid (16 n-tiles, 50 m-tiles), 256 threads, 128x128 tile, K=512
__global__ __launch_bounds__(256) void gx_mma(const float* __restrict__ bihe, const float* __restrict__ bhhe,
                                              const float* __restrict__ bihd, const float* __restrict__ bhhd) {
    __shared__ __align__(16) char sA[128 * 128];
    __shared__ __align__(16) char sB[128 * 128];
    __shared__ float bs[128];
    const uint32_t aB = smem_u32(sA);
    const uint32_t bB = smem_u32(sB);
    const int tid = threadIdx.x;
    const int l = tid & 31;
    const int w = tid >> 5;
    const int wr = w & 3;
    const int wc = w >> 2;
    const int n0 = blockIdx.x * 128;
    const int m0 = blockIdx.y * 128;
    const int side = (m0 >= SRC * BATCH) ? 1 : 0;
    const __nv_bfloat16* Wih = g_wih_b[side];

    if (tid < 128) {
        const float* b1 = side ? bihd : bihe;
        const float* b2 = side ? bhhd : bhhe;
        bs[tid] = b1[n0 + tid] + b2[n0 + tid];
    }

    float acc[2][8][4];
#pragma unroll
    for (int i = 0; i < 2; ++i)
#pragma unroll
        for (int j = 0; j < 8; ++j)
#pragma unroll
            for (int q = 0; q < 4; ++q) acc[i][j][q] = 0.0f;

    const int a_row = wr * 32 + (l & 7) + ((l & 8) ? 8 : 0);
    const int a_k8  = (l & 16) ? 8 : 0;
    const int b_nr  = (l & 7);
    const int b_k8  = (l & 8) ? 8 : 0;

    for (int kb = 0; kb < HID; kb += 64) {
#pragma unroll
        for (int i = 0; i < 4; ++i) {
            int c = tid + i * 256;
            int row = c >> 3;
            int k8 = (c & 7) * 8;
            uint32_t so = (uint32_t)(row * 128 + ((k8 * 2) ^ ((row & 7) << 4)));
            *(uint4*)(sA + so) = *(const uint4*)&g_x_b[(size_t)(m0 + row) * HID + kb + k8];
            *(uint4*)(sB + so) = *(const uint4*)&Wih[(size_t)(n0 + row) * HID + kb + k8];
        }
        __syncthreads();
#pragma unroll
        for (int ks = 0; ks < 4; ++ks) {
            uint32_t a[2][4];
#pragma unroll
            for (int i = 0; i < 2; ++i) {
                int ar = a_row + i * 16;
                int ak = ks * 16 + a_k8;
                ldsm_x4(a[i], aB + ar * 128 + ((ak * 2) ^ ((ar & 7) << 4)));
            }
#pragma unroll
            for (int j = 0; j < 8; ++j) {
                int bn = wc * 64 + j * 8 + b_nr;
                int bk = ks * 16 + b_k8;
                uint32_t b[2];
                ldsm_x2t(b, bB + bn * 128 + ((bk * 2) ^ ((bn & 7) << 4)));
                mma_bf16(acc[0][j], a[0], b);
                mma_bf16(acc[1][j], a[1], b);
            }
        }
        __syncthreads();
    }

    // direct store with bias
#pragma unroll
    for (int i = 0; i < 2; ++i)
#pragma unroll
        for (int j = 0; j < 8; ++j) {
            int row0 = m0 + wr * 32 + i * 16 + (l >> 2);
            int colL = wc * 64 + j * 8 + (l & 3) * 2;
            int col = n0 + colL;
            if (row0 < GXROWS) {
                float2 v0 = make_float2(acc[i][j][0] + bs[colL], acc[i][j][1] + bs[colL + 1]);
                *(float2*)&g_gx[(size_t)row0 * G4 + col] = v0;
            }
            int row1 = row0 + 8;
            if (row1 < GXROWS) {
                float2 v1 = make_float2(acc[i][j][2] + bs[colL], acc[i][j][3] + bs[colL + 1]);
                *(float2*)&g_gx[(size_t)row1 * G4 + col] = v1;
            }
        }
}

// ================= persistent LSTM recurrence =================
// 64 CTAs x 256 threads, 1 grid-barrier per step.
// CTA owns 8 hidden units j0..j0+7 (32 gate rows). Whh slice (hi+lo stacked, 64 rows)
// resident in SMEM. A operand = [h_hi(64); h_lo(64)] stacked, streamed via L2.
#define PS_WS 0                       // 2 sides * 8 kc * 64 rows * 128B = 131072
#define PS_AS 131072                  // 128 * 128B = 16384
#define PS_DS 147456                  // 128 * 68 * 4 = 34816
#define PS_CS 182272                  // 512 * 4 = 2048
#define PS_SMEM 184320

__device__ __forceinline__ void gbar(unsigned target) {
    __syncthreads();
    if (threadIdx.x == 0) {
        __threadfence();
        unsigned arrived = atomicAdd(&g_cnt, 1u) + 1u;
        if (arrived == target) {
            g_gen = target;
        } else {
            while (g_gen < target) {}
            __threadfence();
        }
    }
    __syncthreads();
}

__global__ __launch_bounds__(256, 1) void lstm_persist() {
    extern __shared__ __align__(16) char sm[];
    const uint32_t smb = smem_u32(sm);
    float* Ds = (float*)(sm + PS_DS);
    float* cs = (float*)(sm + PS_CS);
    const int tid = threadIdx.x;
    const int l = tid & 31;
    const int w = tid >> 5;
    const int wr = w & 3;
    const int wc = w >> 2;          // 0..1
    const int j0 = blockIdx.x * 8;

    // stage Whh slices (hi rows 0-31, lo rows 32-63) for enc & dec, swizzled per 64k chunk
#pragma unroll
    for (int it = 0; it < 32; ++it) {
        int u = tid + it * 256;              // 0..8191 uint4
        int sd = u >> 12;
        int kcu = (u >> 9) & 7;
        int rw = (u >> 3) & 63;
        int k8 = (u & 7) * 8;
        int r = rw & 31;
        int grow = (r >> 3) * HID + j0 + (r & 7);
        const __nv_bfloat16* wsrc = (rw < 32) ? g_whh_hi[sd] : g_whh_lo[sd];
        uint4 v = *(const uint4*)&wsrc[(size_t)grow * HID + kcu * 64 + k8];
        uint32_t so = (uint32_t)(rw * 128 + ((k8 * 2) ^ ((rw & 7) << 4)));
        *(uint4*)(sm + PS_WS + sd * 65536 + kcu * 8192 + so) = v;
    }
    // zero cell state
    cs[tid] = 0.0f;
    cs[tid + 256] = 0.0f;
    __syncthreads();

    const int a_row = wr * 32 + (l & 7) + ((l & 8) ? 8 : 0);
    const int a_k8  = (l & 16) ? 8 : 0;
    const int b_nr  = (l & 7);
    const int b_k8  = (l & 8) ? 8 : 0;

    for (int t = 0; t < NSTEP; ++t) {
        const int p = t & 1;
        const uint32_t wbase = smb + PS_WS + ((t < SRC) ? 0 : 65536);
        const __nv_bfloat16* hsrc = g_hs[p];

        float acc[2][4][4];
#pragma unroll
        for (int i = 0; i < 2; ++i)
#pragma unroll
            for (int j = 0; j < 4; ++j)
#pragma unroll
                for (int q = 0; q < 4; ++q) acc[i][j][q] = 0.0f;

        for (int kc = 0; kc < 8; ++kc) {
            // stage A chunk [128 rows][64 k]
#pragma unroll
            for (int i = 0; i < 4; ++i) {
                int c = tid + i * 256;
                int row = c >> 3;
                int k8 = (c & 7) * 8;
                uint4 v = __ldcg((const uint4*)&hsrc[(size_t)row * HID + kc * 64 + k8]);
                uint32_t so = (uint32_t)(row * 128 + ((k8 * 2) ^ ((row & 7) << 4)));
                *(uint4*)(sm + PS_AS + so) = v;
            }
            __syncthreads();
#pragma unroll
            for (int ks = 0; ks < 4; ++ks) {
                uint32_t a[2][4];
#pragma unroll
                for (int i = 0; i < 2; ++i) {
                    int ar = a_row + i * 16;
                    int ak = ks * 16 + a_k8;
                    ldsm_x4(a[i], smb + PS_AS + ar * 128 + ((ak * 2) ^ ((ar & 7) << 4)));
                }
#pragma unroll
                for (int j = 0; j < 4; ++j) {
                    int bn = wc * 32 + j * 8 + b_nr;
                    int bk = ks * 16 + b_k8;
                    uint32_t b[2];
                    ldsm_x2t(b, wbase + kc * 8192 + bn * 128 + ((bk * 2) ^ ((bn & 7) << 4)));
                    mma_bf16(acc[0][j], a[0], b);
                    mma_bf16(acc[1][j], a[1], b);
                }
            }
            __syncthreads();
        }

        // stage C -> Ds [128 m][68]
#pragma unroll
        for (int i = 0; i < 2; ++i)
#pragma unroll
            for (int j = 0; j < 4; ++j) {
                int row = wr * 32 + i * 16 + (l >> 2);
                int col = wc * 32 + j * 8 + (l & 3) * 2;
                Ds[row * 68 + col]           = acc[i][j][0];
                Ds[row * 68 + col + 1]       = acc[i][j][1];
                Ds[(row + 8) * 68 + col]     = acc[i][j][2];
                Ds[(row + 8) * 68 + col + 1] = acc[i][j][3];
            }
        __syncthreads();

        // cell update: 512 (b, jj) elems, 2 per thread
        const int dec = (t >= SRC);
#pragma unroll
        for (int s = 0; s < 2; ++s) {
            int idx = tid + s * 256;
            int b = idx >> 3;
            int jj = idx & 7;
            const float* gxp = &g_gx[(size_t)(t * BATCH + b) * G4 + j0 + jj];
            float gate[4];
#pragma unroll
            for (int g = 0; g < 4; ++g) {
                int r = g * 8 + jj;
                gate[g] = Ds[b * 68 + r] + Ds[b * 68 + r + 32]
                        + Ds[(b + 64) * 68 + r] + Ds[(b + 64) * 68 + r + 32]
                        + gxp[g * HID];
            }
            float cc = cs[idx];
            float cn = sigmoidf_(gate[1]) * cc + sigmoidf_(gate[0]) * tanhf(gate[2]);
            float hn = sigmoidf_(gate[3]) * tanhf(cn);
            cs[idx] = cn;
            __nv_bfloat16 hhi = __float2bfloat16(hn);
            __nv_bfloat16 hlo = __float2bfloat16(hn - __bfloat162float(hhi));
            g_hs[p ^ 1][(size_t)b * HID + j0 + jj] = hhi;
            g_hs[p ^ 1][(size_t)(b + 64) * HID + j0 + jj] = hlo;
            if (dec) {
                size_t dr = (size_t)((t - SRC) * BATCH + b) * HID + j0 + jj;
                g_hall_b[dr] = hhi;
                g_hall_f[dr] = hn;
            }
        }
        gbar((unsigned)(t + 1) * PCTAS);
    }
}

// ================= batched logits GEMM + fused LSE partials (mma.sync bf16) =================
#define LG_A    0
#define LG_B    16384
#define LG_BIAS 32768
#define LG_D    33280
#define LG_SMEM (33280 + 67584)

__global__ __launch_bounds__(256) void logits_mma(const float* __restrict__ bout) {
    extern __shared__ char sm2[];
    const uint32_t sbase = smem_u32(sm2);
    const int tid = threadIdx.x;
    const int l = tid & 31;
    const int w = tid >> 5;
    const int wr = w & 3;
    const int wc = w >> 2;
    const int n0 = blockIdx.x * 128;
    const int m0 = blockIdx.y * 128;

    float acc[2][8][4];
#pragma unroll
    for (int i = 0; i < 2; ++i)
#pragma unroll
        for (int j = 0; j < 8; ++j)
#pragma unroll
            for (int q = 0; q < 4; ++q) acc[i][j][q] = 0.0f;

    const int a_row = wr * 32 + (l & 7) + ((l & 8) ? 8 : 0);
    const int a_k8  = (l & 16) ? 8 : 0;
    const int b_nr  = (l & 7);
    const int b_k8  = (l & 8) ? 8 : 0;

    for (int kb = 0; kb < HID; kb += 64) {
#pragma unroll
        for (int i = 0; i < 4; ++i) {
            int c = tid + i * 256;
            int row = c >> 3;
            int k8 = (c & 7) * 8;
            uint32_t so = (uint32_t)(row * 128 + ((k8 * 2) ^ ((row & 7) << 4)));
            *(uint4*)(sm2 + LG_A + so) = *(const uint4*)&g_hall_b[(size_t)(m0 + row) * HID + kb + k8];
            *(uint4*)(sm2 + LG_B + so) = *(const uint4*)&g_wout_b[(size_t)(n0 + row) * HID + kb + k8];
        }
        __syncthreads();

#pragma unroll
        for (int ks = 0; ks < 4; ++ks) {
            uint32_t a[2][4];
#pragma unroll
            for (int i = 0; i < 2; ++i) {
                int ar = a_row + i * 16;
                int ak = ks * 16 + a_k8;
                ldsm_x4(a[i], sbase + LG_A + ar * 128 + ((ak * 2) ^ ((ar & 7) << 4)));
            }
#pragma unroll
            for (int j = 0; j < 8; ++j) {
                int bn = wc * 64 + j * 8 + b_nr;
                int bk = ks * 16 + b_k8;
                uint32_t b[2];
                ldsm_x2t(b, sbase + LG_B + bn * 128 + ((bk * 2) ^ ((bn & 7) << 4)));
                mma_bf16(acc[0][j], a[0], b);
                mma_bf16(acc[1][j], a[1], b);
            }
        }
        __syncthreads();
    }

    float* Ds = (float*)(sm2 + LG_D);
#pragma unroll
    for (int i = 0; i < 2; ++i)
#pragma unroll
        for (int j = 0; j < 8; ++j) {
            int row = wr * 32 + i * 16 + (l >> 2);
            int col = wc * 64 + j * 8 + (l & 3) * 2;
            Ds[row * 132 + col]           = acc[i][j][0];
            Ds[row * 132 + col + 1]       = acc[i][j][1];
            Ds[(row + 8) * 132 + col]     = acc[i][j][2];
            Ds[(row + 8) * 132 + col + 1] = acc[i][j][3];
        }
    float* bias_s = (float*)(sm2 + LG_BIAS);
    if (tid < 128) bias_s[tid] = bout[n0 + tid];
    __syncthreads();

    {
        const int row = tid >> 1;
        const int half = tid & 1;
        const float* dr = &Ds[row * 132 + half * 64];
        const float* bsx = &bias_s[half * 64];
        float m = -INFINITY;
#pragma unroll 8
        for (int c = 0; c < 64; ++c) m = fmaxf(m, dr[c] + bsx[c]);
        float s = 0.0f;
#pragma unroll 8
        for (int c = 0; c < 64; ++c) s += fexp(dr[c] + bsx[c] - m);
        float mo = __shfl_xor_sync(0xffffffffu, m, 1);
        float so = __shfl_xor_sync(0xffffffffu, s, 1);
        float mm = fmaxf(m, mo);
        float ss = s * fexp(m - mm) + so * fexp(mo - mm);
        int gr = m0 + row;
        if (half == 0 && gr < DROWS) {
            g_pmax[(size_t)gr * VTILES + blockIdx.x] = mm;
            g_psum[(size_t)gr * VTILES + blockIdx.x] = ss;
        }
    }
}

// ================= combine partials -> per-(d,b) loss =================
__global__ void combine_loss(const int* __restrict__ target_lines,
                             const float* __restrict__ bout) {
    __shared__ float sred[128];
    const int b = blockIdx.x;
    const int d = blockIdx.y;
    const int bs = d * BATCH + b;
    const int tid = threadIdx.x;

    float m = -INFINITY;
    for (int p = tid; p < VTILES; p += 128) m = fmaxf(m, g_pmax[(size_t)bs * VTILES + p]);
    sred[tid] = m;
    __syncthreads();
    for (int s = 64; s > 0; s >>= 1) {
        if (tid < s) sred[tid] = fmaxf(sred[tid], sred[tid + s]);
        __syncthreads();
    }
    const float gmax = sred[0];
    __syncthreads();

    float sum = 0.0f;
    for (int p = tid; p < VTILES; p += 128)
        sum += g_psum[(size_t)bs * VTILES + p] * __expf(g_pmax[(size_t)bs * VTILES + p] - gmax);
    sred[tid] = sum;
    __syncthreads();
    for (int s = 64; s > 0; s >>= 1) {
        if (tid < s) sred[tid] += sred[tid + s];
        __syncthreads();
    }
    const float gsum = sred[0];
    __syncthreads();

    const int nxt = target_lines[(d + 1) * BATCH + b];
    float4 hv = ((const float4*)&g_hall_f[(size_t)bs * HID])[tid];
    const __nv_bfloat16* wrow = &g_wout_b[(size_t)nxt * HID];
    float w0 = __bfloat162float(wrow[tid * 4 + 0]);
    float w1 = __bfloat162float(wrow[tid * 4 + 1]);
    float w2 = __bfloat162float(wrow[tid * 4 + 2]);
    float w3 = __bfloat162float(wrow[tid * 4 + 3]);
    float h0 = __bfloat162float(__float2bfloat16(hv.x));
    float h1 = __bfloat162float(__float2bfloat16(hv.y));
    float h2 = __bfloat162float(__float2bfloat16(hv.z));
    float h3 = __bfloat162float(__float2bfloat16(hv.w));
    sred[tid] = h0 * w0 + h1 * w1 + h2 * w2 + h3 * w3;
    __syncthreads();
    for (int s = 64; s > 0; s >>= 1) {
        if (tid < s) sred[tid] += sred[tid + s];
        __syncthreads();
    }
    if (tid == 0)
        g_losses[bs] = -(sred[0] + bout[nxt] - gmax - logf(gsum));
}

// ---------------- final deterministic sum ----------------
__global__ void final_kernel(float* __restrict__ out) {
    __shared__ float sred[256];
    const int tid = threadIdx.x;
    float s = 0.0f;
    for (int i = tid; i < DROWS; i += 256) s += g_losses[i];
    sred[tid] = s;
    __syncthreads();
    for (int st = 128; st > 0; st >>= 1) {
        if (tid < st) sred[tid] += sred[tid + st];
        __syncthreads();
    }
    if (tid == 0) out[0] = sred[0] * (1.0f / (float)BATCH);
}

// ---------------- host ----------------
extern "C" void kernel_launch(void* const* d_in, const int* in_sizes, int n_in,
                              void* d_out, int out_size) {
    (void)in_sizes; (void)n_in; (void)out_size;
    const int*   input_lines  = (const int*)  d_in[0];
    const int*   target_lines = (const int*)  d_in[1];
    const float* emb_in       = (const float*)d_in[2];
    const float* emb_tgt      = (const float*)d_in[3];
    const float* W_ih_enc     = (const float*)d_in[4];
    const float* W_hh_enc     = (const float*)d_in[5];
    const float* b_ih_enc     = (const float*)d_in[6];
    const float* b_hh_enc     = (const float*)d_in[7];
    const float* W_ih_dec     = (const float*)d_in[8];
    const float* W_hh_dec     = (const float*)d_in[9];
    const float* b_ih_dec     = (const float*)d_in[10];
    const float* b_hh_dec     = (const float*)d_in[11];
    const float* W_out        = (const float*)d_in[12];
    const float* b_out        = (const float*)d_in[13];
    float* out = (float*)d_out;

    cudaFuncSetAttribute(lstm_persist, cudaFuncAttributeMaxDynamicSharedMemorySize, PS_SMEM);
    cudaFuncSetAttribute(logits_mma,   cudaFuncAttributeMaxDynamicSharedMemorySize, LG_SMEM);

    init_kernel<<<(128 * HID) / 256, 256>>>();

    const int wblk = G4 * HID / 4 / 256;                 // 1024
    conv_plain<<<wblk, 256>>>(W_ih_enc, nullptr, 0, 0);
    conv_plain<<<wblk, 256>>>(W_ih_dec, nullptr, 0, 1);
    conv_plain<<<VOCAB * HID / 4 / 256, 256>>>(W_out, nullptr, 1, 0);
    conv_split<<<wblk, 256>>>(W_hh_enc, 0);
    conv_split<<<wblk, 256>>>(W_hh_dec, 1);
    prep_x<<<XROWS_PAD, 64>>>(input_lines, target_lines, emb_in, emb_tgt);

    gx_mma<<<dim3(16, XROWS_PAD / 128), 256>>>(b_ih_enc, b_hh_enc, b_ih_dec, b_hh_dec);

    lstm_persist<<<PCTAS, 256, PS_SMEM>>>();

    logits_mma<<<dim3(VTILES, DROWS_PAD / 128), 256, LG_SMEM>>>(b_out);
    combine_loss<<<dim3(BATCH, TGT), 128>>>(target_lines, b_out);
    final_kernel<<<1, 256>>>(out);
}

// round 6
// speedup vs baseline: 8.0792x; 1.1860x over previous
#include <cuda_runtime.h>
#include <cuda_bf16.h>
#include <math.h>
#include <stdint.h>

#define HID   512
#define G4    2048
#define BATCH 64
#define VOCAB 32000
#define SRC   50
#define TGT   49
#define NSTEP (SRC + TGT)

#define VTILES 250               // 32000 / 128
#define DROWS  (TGT * BATCH)     // 3136 decode rows
#define DROWS_PAD 3328           // 26 * 128
#define GXROWS (NSTEP * BATCH)   // 6336
#define XROWS_PAD 6400           // 50 * 128
#define PCTAS 64

// ---------------- static scratch ----------------
__device__ float g_gx[(size_t)GXROWS * G4];
__device__ __nv_bfloat16 g_x_b[(size_t)XROWS_PAD * HID];
__device__ __nv_bfloat16 g_wih_b[2][(size_t)G4 * HID];
__device__ __nv_bfloat16 g_whh_hi[2][(size_t)G4 * HID];
__device__ __nv_bfloat16 g_whh_lo[2][(size_t)G4 * HID];
__device__ __nv_bfloat16 g_hs[2][128 * HID];          // [hi(64 rows); lo(64 rows)] ping-pong
__device__ float g_hall_f[(size_t)DROWS * HID];
__device__ __nv_bfloat16 g_hall_b[(size_t)DROWS_PAD * HID];  // pad rows stay zero
__device__ __nv_bfloat16 g_wout_b[(size_t)VOCAB * HID];
__device__ float g_pmax[(size_t)DROWS * VTILES];
__device__ float g_psum[(size_t)DROWS * VTILES];
__device__ float g_losses[DROWS];
__device__ unsigned g_cnt;
__device__ volatile unsigned g_gen;

// ---------------- helpers ----------------
__device__ __forceinline__ uint32_t smem_u32(const void* p) {
    uint32_t a;
    asm("{ .reg .u64 t; cvta.to.shared.u64 t, %1; cvt.u32.u64 %0, t; }" : "=r"(a) : "l"(p));
    return a;
}
__device__ __forceinline__ void ldsm_x4(uint32_t* r, uint32_t addr) {
    asm volatile("ldmatrix.sync.aligned.m8n8.x4.shared.b16 {%0,%1,%2,%3}, [%4];"
        : "=r"(r[0]), "=r"(r[1]), "=r"(r[2]), "=r"(r[3]) : "r"(addr));
}
__device__ __forceinline__ void ldsm_x2t(uint32_t* r, uint32_t addr) {
    asm volatile("ldmatrix.sync.aligned.m8n8.x2.trans.shared.b16 {%0,%1}, [%2];"
        : "=r"(r[0]), "=r"(r[1]) : "r"(addr));
}
__device__ __forceinline__ void mma_bf16(float* c, const uint32_t* a, const uint32_t* b) {
    asm volatile("mma.sync.aligned.m16n8k16.row.col.f32.bf16.bf16.f32 "
        "{%0,%1,%2,%3}, {%4,%5,%6,%7}, {%8,%9}, {%0,%1,%2,%3};"
        : "+f"(c[0]), "+f"(c[1]), "+f"(c[2]), "+f"(c[3])
        : "r"(a[0]), "r"(a[1]), "r"(a[2]), "r"(a[3]), "r"(b[0]), "r"(b[1]));
}
__device__ __forceinline__ void cp16(uint32_t sdst, const void* gsrc) {
    asm volatile("cp.async.cg.shared.global [%0], [%1], 16;" :: "r"(sdst), "l"(gsrc) : "memory");
}
#define CP_COMMIT() asm volatile("cp.async.commit_group;" ::: "memory")
#define CP_WAIT1()  asm volatile("cp.async.wait_group 1;" ::: "memory")
#define CP_WAIT0()  asm volatile("cp.async.wait_group 0;" ::: "memory")

__device__ __forceinline__ float sigmoidf_(float x) { return 1.0f / (1.0f + __expf(-x)); }
__device__ __forceinline__ float fexp(float x) {
    x = fmaxf(x, -87.0f);
    float y = x * 1.44269504088896f;
    float r = rintf(y);
    float f = (y - r) * 0.693147180559945f;
    float p = 1.0f + f * (1.0f + f * (0.5f + f * (0.16666667f + f * (0.041666667f + f * 0.0083333333f))));
    return __int_as_float(((int)r + 127) << 23) * p;
}

// ---------------- init ----------------
__global__ void init_kernel() {
    int i = blockIdx.x * blockDim.x + threadIdx.x;
    if (i < 2 * 128 * HID / 2) ((uint32_t*)g_hs)[i] = 0u;
    if (i == 0) { g_cnt = 0u; g_gen = 0u; }
}

// ---------------- fp32 -> bf16 conversions ----------------
__global__ void conv_plain(const float* __restrict__ src, int sel, int side) {
    size_t i = ((size_t)blockIdx.x * 256 + threadIdx.x) * 4;
    float4 v = *(const float4*)&src[i];
    __nv_bfloat16* dst = (sel == 0) ? g_wih_b[side] : g_wout_b;
    __nv_bfloat162 a = __floats2bfloat162_rn(v.x, v.y);
    __nv_bfloat162 b = __floats2bfloat162_rn(v.z, v.w);
    *(uint32_t*)&dst[i]     = *(uint32_t*)&a;
    *(uint32_t*)&dst[i + 2] = *(uint32_t*)&b;
}
__global__ void conv_split(const float* __restrict__ src, int side) {
    size_t i = ((size_t)blockIdx.x * 256 + threadIdx.x) * 4;
    float4 v = *(const float4*)&src[i];
    float f[4] = {v.x, v.y, v.z, v.w};
    __nv_bfloat16 hi[4], lo[4];
#pragma unroll
    for (int j = 0; j < 4; ++j) {
        hi[j] = __float2bfloat16(f[j]);
        lo[j] = __float2bfloat16(f[j] - __bfloat162float(hi[j]));
    }
    *(uint2*)&g_whh_hi[side][i] = *(uint2*)hi;
    *(uint2*)&g_whh_lo[side][i] = *(uint2*)lo;
}

// ---------------- gather emb rows -> bf16 x matrix ----------------
__global__ void prep_x(const int* __restrict__ inl, const int* __restrict__ tgl,
                       const float* __restrict__ embi, const float* __restrict__ embt) {
    int row = blockIdx.x;
    int k = threadIdx.x * 8;
    int tok; const float* e;
    if (row < SRC * BATCH)       { tok = inl[row]; e = embi; }
    else if (row < GXROWS)       { tok = tgl[row - SRC * BATCH]; e = embt; }
    else                         { tok = 0; e = embi; }
    const float4* s = (const float4*)(e + (size_t)tok * HID + k);
    float4 v0 = s[0], v1 = s[1];
    __nv_bfloat162 p0 = __floats2bfloat162_rn(v0.x, v0.y);
    __nv_bfloat162 p1 = __floats2bfloat162_rn(v0.z, v0.w);
    __nv_bfloat162 p2 = __floats2bfloat162_rn(v1.x, v1.y);
    __nv_bfloat162 p3 = __floats2bfloat162_rn(v1.z, v1.w);
    uint4 o = make_uint4(*(uint32_t*)&p0, *(uint32_t*)&p1, *(uint32_t*)&p2, *(uint32_t*)&p3);
    *(uint4*)&g_x_b[(size_t)row * HID + k] = o;
}

// ================= gx GEMM (bf16 HMMA, cp.async 2-stage pipeline) =================
// stage layout: stage s: A @ s*32768, B @ s*32768+16384; bias @ 65536. total 66048
#define GX_SMEM 66048

__global__ __launch_bounds__(256) void gx_mma(const float* __restrict__ bihe, const float* __restrict__ bhhe,
                                              const float* __restrict__ bihd, const float* __restrict__ bhhd) {
    extern __shared__ __align__(16) char sm[];
    const uint32_t sb = smem_u32(sm);
    const int tid = threadIdx.x;
    const int l = tid & 31;
    const int w = tid >> 5;
    const int wr = w & 3;
    const int wc = w >> 2;
    const int n0 = blockIdx.x * 128;
    const int m0 = blockIdx.y * 128;
    const int side = (m0 >= SRC * BATCH) ? 1 : 0;
    const __nv_bfloat16* Wih = g_wih_b[side];
    float* bs = (float*)(sm + 65536);

    if (tid < 128) {
        const float* b1 = side ? bihd : bihe;
        const float* b2 = side ? bhhd : bhhe;
        bs[tid] = b1[n0 + tid] + b2[n0 + tid];
    }

    float acc[2][8][4];
#pragma unroll
    for (int i = 0; i < 2; ++i)
#pragma unroll
        for (int j = 0; j < 8; ++j)
#pragma unroll
            for (int q = 0; q < 4; ++q) acc[i][j][q] = 0.0f;

    const int a_row = wr * 32 + (l & 7) + ((l & 8) ? 8 : 0);
    const int a_k8  = (l & 16) ? 8 : 0;
    const int b_nr  = (l & 7);
    const int b_k8  = (l & 8) ? 8 : 0;

    // per-thread staging coords
    const int st_row = tid >> 1;                 // 2 chunks of 16B per row pair? no:
    // 1024 16B chunks per matrix, 4 per thread
#define GX_STAGE(kb, s) do {                                                          \
        uint32_t base = sb + (s) * 32768;                                             \
        _Pragma("unroll")                                                             \
        for (int i_ = 0; i_ < 4; ++i_) {                                              \
            int c_ = tid + i_ * 256;                                                  \
            int row_ = c_ >> 3;                                                       \
            int k8_ = (c_ & 7) * 8;                                                   \
            uint32_t so_ = (uint32_t)(row_ * 128 + ((k8_ * 2) ^ ((row_ & 7) << 4)));  \
            cp16(base + so_,         &g_x_b[(size_t)(m0 + row_) * HID + (kb) + k8_]); \
            cp16(base + 16384 + so_, &Wih[(size_t)(n0 + row_) * HID + (kb) + k8_]);   \
        }                                                                             \
        CP_COMMIT();                                                                  \
    } while (0)

    GX_STAGE(0, 0);
    for (int c = 0; c < 8; ++c) {
        const int s = c & 1;
        if (c < 7) { GX_STAGE((c + 1) * 64, s ^ 1); CP_WAIT1(); }
        else       { CP_WAIT0(); }
        __syncthreads();
        const uint32_t aB = sb + s * 32768;
        const uint32_t bB = aB + 16384;
#pragma unroll
        for (int ks = 0; ks < 4; ++ks) {
            uint32_t a[2][4];
#pragma unroll
            for (int i = 0; i < 2; ++i) {
                int ar = a_row + i * 16;
                int ak = ks * 16 + a_k8;
                ldsm_x4(a[i], aB + ar * 128 + ((ak * 2) ^ ((ar & 7) << 4)));
            }
#pragma unroll
            for (int j = 0; j < 8; ++j) {
                int bn = wc * 64 + j * 8 + b_nr;
                int bk = ks * 16 + b_k8;
                uint32_t b[2];
                ldsm_x2t(b, bB + bn * 128 + ((bk * 2) ^ ((bn & 7) << 4)));
                mma_bf16(acc[0][j], a[0], b);
                mma_bf16(acc[1][j], a[1], b);
            }
        }
        __syncthreads();
    }

#pragma unroll
    for (int i = 0; i < 2; ++i)
#pragma unroll
        for (int j = 0; j < 8; ++j) {
            int row0 = m0 + wr * 32 + i * 16 + (l >> 2);
            int colL = wc * 64 + j * 8 + (l & 3) * 2;
            int col = n0 + colL;
            if (row0 < GXROWS) {
                float2 v0 = make_float2(acc[i][j][0] + bs[colL], acc[i][j][1] + bs[colL + 1]);
                *(float2*)&g_gx[(size_t)row0 * G4 + col] = v0;
            }
            int row1 = row0 + 8;
            if (row1 < GXROWS) {
                float2 v1 = make_float2(acc[i][j][2] + bs[colL], acc[i][j][3] + bs[colL + 1]);
                *(float2*)&g_gx[(size_t)row1 * G4 + col] = v1;
            }
        }
}

// ================= persistent LSTM recurrence (A double-buffered via cp.async) =================
#define PS_WS 0                       // 131072
#define PS_AS 131072                  // 2 x 16384
#define PS_DS 163840                  // 128 * 68 * 4 = 34816
#define PS_CS 198656                  // 2048
#define PS_SMEM 200704

__device__ __forceinline__ void gbar(unsigned target) {
    __syncthreads();
    if (threadIdx.x == 0) {
        __threadfence();
        unsigned arrived = atomicAdd(&g_cnt, 1u) + 1u;
        if (arrived == target) {
            g_gen = target;
        } else {
            while (g_gen < target) {}
            __threadfence();
        }
    }
    __syncthreads();
}

__global__ __launch_bounds__(256, 1) void lstm_persist() {
    extern __shared__ __align__(16) char sm[];
    const uint32_t smb = smem_u32(sm);
    float* Ds = (float*)(sm + PS_DS);
    float* cs = (float*)(sm + PS_CS);
    const int tid = threadIdx.x;
    const int l = tid & 31;
    const int w = tid >> 5;
    const int wr = w & 3;
    const int wc = w >> 2;          // 0..1
    const int j0 = blockIdx.x * 8;

    // stage Whh slices (hi rows 0-31, lo rows 32-63) for enc & dec
#pragma unroll
    for (int it = 0; it < 32; ++it) {
        int u = tid + it * 256;
        int sd = u >> 12;
        int kcu = (u >> 9) & 7;
        int rw = (u >> 3) & 63;
        int k8 = (u & 7) * 8;
        int r = rw & 31;
        int grow = (r >> 3) * HID + j0 + (r & 7);
        const __nv_bfloat16* wsrc = (rw < 32) ? g_whh_hi[sd] : g_whh_lo[sd];
        uint4 v = *(const uint4*)&wsrc[(size_t)grow * HID + kcu * 64 + k8];
        uint32_t so = (uint32_t)(rw * 128 + ((k8 * 2) ^ ((rw & 7) << 4)));
        *(uint4*)(sm + PS_WS + sd * 65536 + kcu * 8192 + so) = v;
    }
    cs[tid] = 0.0f;
    cs[tid + 256] = 0.0f;
    __syncthreads();

    const int a_row = wr * 32 + (l & 7) + ((l & 8) ? 8 : 0);
    const int a_k8  = (l & 16) ? 8 : 0;
    const int b_nr  = (l & 7);
    const int b_k8  = (l & 8) ? 8 : 0;

#define PS_STAGE(hsrc, kc, s) do {                                                    \
        uint32_t base = smb + PS_AS + (s) * 16384;                                    \
        _Pragma("unroll")                                                             \
        for (int i_ = 0; i_ < 4; ++i_) {                                              \
            int c_ = tid + i_ * 256;                                                  \
            int row_ = c_ >> 3;                                                       \
            int k8_ = (c_ & 7) * 8;                                                   \
            uint32_t so_ = (uint32_t)(row_ * 128 + ((k8_ * 2) ^ ((row_ & 7) << 4)));  \
            cp16(base + so_, &(hsrc)[(size_t)row_ * HID + (kc) * 64 + k8_]);          \
        }                                                                             \
        CP_COMMIT();                                                                  \
    } while (0)

    for (int t = 0; t < NSTEP; ++t) {
        const int p = t & 1;
        const uint32_t wbase = smb + PS_WS + ((t < SRC) ? 0 : 65536);
        const __nv_bfloat16* hsrc = g_hs[p];

        float acc[2][4][4];
#pragma unroll
        for (int i = 0; i < 2; ++i)
#pragma unroll
            for (int j = 0; j < 4; ++j)
#pragma unroll
                for (int q = 0; q < 4; ++q) acc[i][j][q] = 0.0f;

        PS_STAGE(hsrc, 0, 0);
        for (int kc = 0; kc < 8; ++kc) {
            const int s = kc & 1;
            if (kc < 7) { PS_STAGE(hsrc, kc + 1, s ^ 1); CP_WAIT1(); }
            else        { CP_WAIT0(); }
            __syncthreads();
            const uint32_t aBs = smb + PS_AS + s * 16384;
#pragma unroll
            for (int ks = 0; ks < 4; ++ks) {
                uint32_t a[2][4];
#pragma unroll
                for (int i = 0; i < 2; ++i) {
                    int ar = a_row + i * 16;
                    int ak = ks * 16 + a_k8;
                    ldsm_x4(a[i], aBs + ar * 128 + ((ak * 2) ^ ((ar & 7) << 4)));
                }
#pragma unroll
                for (int j = 0; j < 4; ++j) {
                    int bn = wc * 32 + j * 8 + b_nr;
                    int bk = ks * 16 + b_k8;
                    uint32_t b[2];
                    ldsm_x2t(b, wbase + kc * 8192 + bn * 128 + ((bk * 2) ^ ((bn & 7) << 4)));
                    mma_bf16(acc[0][j], a[0], b);
                    mma_bf16(acc[1][j], a[1], b);
                }
            }
            __syncthreads();
        }

#pragma unroll
        for (int i = 0; i < 2; ++i)
#pragma unroll
            for (int j = 0; j < 4; ++j) {
                int row = wr * 32 + i * 16 + (l >> 2);
                int col = wc * 32 + j * 8 + (l & 3) * 2;
                Ds[row * 68 + col]           = acc[i][j][0];
                Ds[row * 68 + col + 1]       = acc[i][j][1];
                Ds[(row + 8) * 68 + col]     = acc[i][j][2];
                Ds[(row + 8) * 68 + col + 1] = acc[i][j][3];
            }
        __syncthreads();

        const int dec = (t >= SRC);
#pragma unroll
        for (int s2 = 0; s2 < 2; ++s2) {
            int idx = tid + s2 * 256;
            int b = idx >> 3;
            int jj = idx & 7;
            const float* gxp = &g_gx[(size_t)(t * BATCH + b) * G4 + j0 + jj];
            float gate[4];
#pragma unroll
            for (int g = 0; g < 4; ++g) {
                int r = g * 8 + jj;
                gate[g] = Ds[b * 68 + r] + Ds[b * 68 + r + 32]
                        + Ds[(b + 64) * 68 + r] + Ds[(b + 64) * 68 + r + 32]
                        + gxp[g * HID];
            }
            float cc = cs[idx];
            float cn = sigmoidf_(gate[1]) * cc + sigmoidf_(gate[0]) * tanhf(gate[2]);
            float hn = sigmoidf_(gate[3]) * tanhf(cn);
            cs[idx] = cn;
            __nv_bfloat16 hhi = __float2bfloat16(hn);
            __nv_bfloat16 hlo = __float2bfloat16(hn - __bfloat162float(hhi));
            g_hs[p ^ 1][(size_t)b * HID + j0 + jj] = hhi;
            g_hs[p ^ 1][(size_t)(b + 64) * HID + j0 + jj] = hlo;
            if (dec) {
                size_t dr = (size_t)((t - SRC) * BATCH + b) * HID + j0 + jj;
                g_hall_b[dr] = hhi;
                g_hall_f[dr] = hn;
            }
        }
        gbar((unsigned)(t + 1) * PCTAS);
    }
}

// ================= batched logits GEMM + fused LSE (cp.async 2-stage pipeline) =================
// stage s: A @ s*32768, B @ s*32768+16384; bias @ 65536 (512B); Ds @ 66560 (67584)
#define LG_BIAS 65536
#define LG_D    66560
#define LG_SMEM (66560 + 67584)

__global__ __launch_bounds__(256) void logits_mma(const float* __restrict__ bout) {
    extern __shared__ __align__(16) char sm2[];
    const uint32_t sbase = smem_u32(sm2);
    const int tid = threadIdx.x;
    const int l = tid & 31;
    const int w = tid >> 5;
    const int wr = w & 3;
    const int wc = w >> 2;
    const int n0 = blockIdx.x * 128;
    const int m0 = blockIdx.y * 128;

    float acc[2][8][4];
#pragma unroll
    for (int i = 0; i < 2; ++i)
#pragma unroll
        for (int j = 0; j < 8; ++j)
#pragma unroll
            for (int q = 0; q < 4; ++q) acc[i][j][q] = 0.0f;

    const int a_row = wr * 32 + (l & 7) + ((l & 8) ? 8 : 0);
    const int a_k8  = (l & 16) ? 8 : 0;
    const int b_nr  = (l & 7);
    const int b_k8  = (l & 8) ? 8 : 0;

#define LG_STAGE(kb, s) do {                                                          \
        uint32_t base = sbase + (s) * 32768;                                          \
        _Pragma("unroll")                                                             \
        for (int i_ = 0; i_ < 4; ++i_) {                                              \
            int c_ = tid + i_ * 256;                                                  \
            int row_ = c_ >> 3;                                                       \
            int k8_ = (c_ & 7) * 8;                                                   \
            uint32_t so_ = (uint32_t)(row_ * 128 + ((k8_ * 2) ^ ((row_ & 7) << 4)));  \
            cp16(base + so_,         &g_hall_b[(size_t)(m0 + row_) * HID + (kb) + k8_]); \
            cp16(base + 16384 + so_, &g_wout_b[(size_t)(n0 + row_) * HID + (kb) + k8_]); \
        }                                                                             \
        CP_COMMIT();                                                                  \
    } while (0)

    LG_STAGE(0, 0);
    for (int c = 0; c < 8; ++c) {
        const int s = c & 1;
        if (c < 7) { LG_STAGE((c + 1) * 64, s ^ 1); CP_WAIT1(); }
        else       { CP_WAIT0(); }
        __syncthreads();
        const uint32_t aB = sbase + s * 32768;
        const uint32_t bB = aB + 16384;
#pragma unroll
        for (int ks = 0; ks < 4; ++ks) {
            uint32_t a[2][4];
#pragma unroll
            for (int i = 0; i < 2; ++i) {
                int ar = a_row + i * 16;
                int ak = ks * 16 + a_k8;
                ldsm_x4(a[i], aB + ar * 128 + ((ak * 2) ^ ((ar & 7) << 4)));
            }
#pragma unroll
            for (int j = 0; j < 8; ++j) {
                int bn = wc * 64 + j * 8 + b_nr;
                int bk = ks * 16 + b_k8;
                uint32_t b[2];
                ldsm_x2t(b, bB + bn * 128 + ((bk * 2) ^ ((bn & 7) << 4)));
                mma_bf16(acc[0][j], a[0], b);
                mma_bf16(acc[1][j], a[1], b);
            }
        }
        __syncthreads();
    }

    float* Ds = (float*)(sm2 + LG_D);
#pragma unroll
    for (int i = 0; i < 2; ++i)
#pragma unroll
        for (int j = 0; j < 8; ++j) {
            int row = wr * 32 + i * 16 + (l >> 2);
            int col = wc * 64 + j * 8 + (l & 3) * 2;
            Ds[row * 132 + col]           = acc[i][j][0];
            Ds[row * 132 + col + 1]       = acc[i][j][1];
            Ds[(row + 8) * 132 + col]     = acc[i][j][2];
            Ds[(row + 8) * 132 + col + 1] = acc[i][j][3];
        }
    float* bias_s = (float*)(sm2 + LG_BIAS);
    if (tid < 128) bias_s[tid] = bout[n0 + tid];
    __syncthreads();

    {
        const int row = tid >> 1;
        const int half = tid & 1;
        const float* dr = &Ds[row * 132 + half * 64];
        const float* bsx = &bias_s[half * 64];
        float m = -INFINITY;
#pragma unroll 8
        for (int c = 0; c < 64; ++c) m = fmaxf(m, dr[c] + bsx[c]);
        float s = 0.0f;
#pragma unroll 8
        for (int c = 0; c < 64; ++c) s += fexp(dr[c] + bsx[c] - m);
        float mo = __shfl_xor_sync(0xffffffffu, m, 1);
        float so = __shfl_xor_sync(0xffffffffu, s, 1);
        float mm = fmaxf(m, mo);
        float ss = s * fexp(m - mm) + so * fexp(mo - mm);
        int gr = m0 + row;
        if (half == 0 && gr < DROWS) {
            g_pmax[(size_t)gr * VTILES + blockIdx.x] = mm;
            g_psum[(size_t)gr * VTILES + blockIdx.x] = ss;
        }
    }
}

// ================= combine partials -> per-(d,b) loss =================
__global__ void combine_loss(const int* __restrict__ target_lines,
                             const float* __restrict__ bout) {
    __shared__ float sred[128];
    const int b = blockIdx.x;
    const int d = blockIdx.y;
    const int bs = d * BATCH + b;
    const int tid = threadIdx.x;

    float m = -INFINITY;
    for (int p = tid; p < VTILES; p += 128) m = fmaxf(m, g_pmax[(size_t)bs * VTILES + p]);
    sred[tid] = m;
    __syncthreads();
    for (int s = 64; s > 0; s >>= 1) {
        if (tid < s) sred[tid] = fmaxf(sred[tid], sred[tid + s]);
        __syncthreads();
    }
    const float gmax = sred[0];
    __syncthreads();

    float sum = 0.0f;
    for (int p = tid; p < VTILES; p += 128)
        sum += g_psum[(size_t)bs * VTILES + p] * __expf(g_pmax[(size_t)bs * VTILES + p] - gmax);
    sred[tid] = sum;
    __syncthreads();
    for (int s = 64; s > 0; s >>= 1) {
        if (tid < s) sred[tid] += sred[tid + s];
        __syncthreads();
    }
    const float gsum = sred[0];
    __syncthreads();

    const int nxt = target_lines[(d + 1) * BATCH + b];
    float4 hv = ((const float4*)&g_hall_f[(size_t)bs * HID])[tid];
    const __nv_bfloat16* wrow = &g_wout_b[(size_t)nxt * HID];
    float w0 = __bfloat162float(wrow[tid * 4 + 0]);
    float w1 = __bfloat162float(wrow[tid * 4 + 1]);
    float w2 = __bfloat162float(wrow[tid * 4 + 2]);
    float w3 = __bfloat162float(wrow[tid * 4 + 3]);
    float h0 = __bfloat162float(__float2bfloat16(hv.x));
    float h1 = __bfloat162float(__float2bfloat16(hv.y));
    float h2 = __bfloat162float(__float2bfloat16(hv.z));
    float h3 = __bfloat162float(__float2bfloat16(hv.w));
    sred[tid] = h0 * w0 + h1 * w1 + h2 * w2 + h3 * w3;
    __syncthreads();
    for (int s = 64; s > 0; s >>= 1) {
        if (tid < s) sred[tid] += sred[tid + s];
        __syncthreads();
    }
    if (tid == 0)
        g_losses[bs] = -(sred[0] + bout[nxt] - gmax - logf(gsum));
}

// ---------------- final deterministic sum ----------------
__global__ void final_kernel(float* __restrict__ out) {
    __shared__ float sred[256];
    const int tid = threadIdx.x;
    float s = 0.0f;
    for (int i = tid; i < DROWS; i += 256) s += g_losses[i];
    sred[tid] = s;
    __syncthreads();
    for (int st = 128; st > 0; st >>= 1) {
        if (tid < st) sred[tid] += sred[tid + st];
        __syncthreads();
    }
    if (tid == 0) out[0] = sred[0] * (1.0f / (float)BATCH);
}

// ---------------- host ----------------
extern "C" void kernel_launch(void* const* d_in, const int* in_sizes, int n_in,
                              void* d_out, int out_size) {
    (void)in_sizes; (void)n_in; (void)out_size;
    const int*   input_lines  = (const int*)  d_in[0];
    const int*   target_lines = (const int*)  d_in[1];
    const float* emb_in       = (const float*)d_in[2];
    const float* emb_tgt      = (const float*)d_in[3];
    const float* W_ih_enc     = (const float*)d_in[4];
    const float* W_hh_enc     = (const float*)d_in[5];
    const float* b_ih_enc     = (const float*)d_in[6];
    const float* b_hh_enc     = (const float*)d_in[7];
    const float* W_ih_dec     = (const float*)d_in[8];
    const float* W_hh_dec     = (const float*)d_in[9];
    const float* b_ih_dec     = (const float*)d_in[10];
    const float* b_hh_dec     = (const float*)d_in[11];
    const float* W_out        = (const float*)d_in[12];
    const float* b_out        = (const float*)d_in[13];
    float* out = (float*)d_out;

    cudaFuncSetAttribute(gx_mma,       cudaFuncAttributeMaxDynamicSharedMemorySize, GX_SMEM);
    cudaFuncSetAttribute(lstm_persist, cudaFuncAttributeMaxDynamicSharedMemorySize, PS_SMEM);
    cudaFuncSetAttribute(logits_mma,   cudaFuncAttributeMaxDynamicSharedMemorySize, LG_SMEM);

    init_kernel<<<(128 * HID) / 256, 256>>>();

    const int wblk = G4 * HID / 4 / 256;                 // 1024
    conv_plain<<<wblk, 256>>>(W_ih_enc, 0, 0);
    conv_plain<<<wblk, 256>>>(W_ih_dec, 0, 1);
    conv_plain<<<VOCAB * HID / 4 / 256, 256>>>(W_out, 1, 0);
    conv_split<<<wblk, 256>>>(W_hh_enc, 0);
    conv_split<<<wblk, 256>>>(W_hh_dec, 1);
    prep_x<<<XROWS_PAD, 64>>>(input_lines, target_lines, emb_in, emb_tgt);

    gx_mma<<<dim3(16, XROWS_PAD / 128), 256, GX_SMEM>>>(b_ih_enc, b_hh_enc, b_ih_dec, b_hh_dec);

    lstm_persist<<<PCTAS, 256, PS_SMEM>>>();

    logits_mma<<<dim3(VTILES, DROWS_PAD / 128), 256, LG_SMEM>>>(b_out);
    combine_loss<<<dim3(BATCH, TGT), 128>>>(target_lines, b_out);
    final_kernel<<<1, 256>>>(out);
}

// round 7
// speedup vs baseline: 10.7228x; 1.3272x over previous
#include <cuda_runtime.h>
#include <cuda_bf16.h>
#include <cuda_fp16.h>
#include <math.h>
#include <stdint.h>

#define HID   512
#define G4    2048
#define BATCH 64
#define VOCAB 32000
#define SRC   50
#define TGT   49
#define NSTEP (SRC + TGT)

#define VT2    125               // 32000 / 256
#define DROWS  (TGT * BATCH)     // 3136 decode rows
#define DROWS_PAD 3328           // 26 * 128
#define GXROWS (NSTEP * BATCH)   // 6336
#define XROWS_PAD 6400
#define PCTAS 64

// ---------------- static scratch ----------------
__device__ float g_gx[(size_t)GXROWS * G4];
__device__ __nv_bfloat16 g_x_b[(size_t)XROWS_PAD * HID];
__device__ __nv_bfloat16 g_wih_b[2][(size_t)G4 * HID];
__device__ __half g_whh_h[2][(size_t)G4 * HID];
__device__ __half g_hs[2][BATCH * HID];                      // h ping-pong (fp16)
__device__ float g_hall_f[(size_t)DROWS * HID];
__device__ __nv_bfloat16 g_hall_b[(size_t)DROWS_PAD * HID];  // pad rows stay zero
__device__ __nv_bfloat16 g_wout_b[(size_t)VOCAB * HID];
__device__ float g_pmax[(size_t)DROWS * VT2];
__device__ float g_psum[(size_t)DROWS * VT2];
__device__ float g_losses[DROWS];
__device__ unsigned g_cnt;
__device__ volatile unsigned g_gen;

// ---------------- helpers ----------------
__device__ __forceinline__ uint32_t smem_u32(const void* p) {
    uint32_t a;
    asm("{ .reg .u64 t; cvta.to.shared.u64 t, %1; cvt.u32.u64 %0, t; }" : "=r"(a) : "l"(p));
    return a;
}
__device__ __forceinline__ void ldsm_x4(uint32_t* r, uint32_t addr) {
    asm volatile("ldmatrix.sync.aligned.m8n8.x4.shared.b16 {%0,%1,%2,%3}, [%4];"
        : "=r"(r[0]), "=r"(r[1]), "=r"(r[2]), "=r"(r[3]) : "r"(addr));
}
__device__ __forceinline__ void ldsm_x4t(uint32_t* r, uint32_t addr) {
    asm volatile("ldmatrix.sync.aligned.m8n8.x4.trans.shared.b16 {%0,%1,%2,%3}, [%2_ignore];" :: "r"(0));
}
// (real one below — keep name unique)
__device__ __forceinline__ void ldsm_x4_trans(uint32_t* r, uint32_t addr) {
    asm volatile("ldmatrix.sync.aligned.m8n8.x4.trans.shared.b16 {%0,%1,%2,%3}, [%4];"
        : "=r"(r[0]), "=r"(r[1]), "=r"(r[2]), "=r"(r[3]) : "r"(addr));
}
__device__ __forceinline__ void mma_bf16(float* c, const uint32_t* a, const uint32_t* b) {
    asm volatile("mma.sync.aligned.m16n8k16.row.col.f32.bf16.bf16.f32 "
        "{%0,%1,%2,%3}, {%4,%5,%6,%7}, {%8,%9}, {%0,%1,%2,%3};"
        : "+f"(c[0]), "+f"(c[1]), "+f"(c[2]), "+f"(c[3])
        : "r"(a[0]), "r"(a[1]), "r"(a[2]), "r"(a[3]), "r"(b[0]), "r"(b[1]));
}
__device__ __forceinline__ void mma_f16(float* c, const uint32_t* a, const uint32_t* b) {
    asm volatile("mma.sync.aligned.m16n8k16.row.col.f32.f16.f16.f32 "
        "{%0,%1,%2,%3}, {%4,%5,%6,%7}, {%8,%9}, {%0,%1,%2,%3};"
        : "+f"(c[0]), "+f"(c[1]), "+f"(c[2]), "+f"(c[3])
        : "r"(a[0]), "r"(a[1]), "r"(a[2]), "r"(a[3]), "r"(b[0]), "r"(b[1]));
}
__device__ __forceinline__ void cp16(uint32_t sdst, const void* gsrc) {
    asm volatile("cp.async.cg.shared.global [%0], [%1], 16;" :: "r"(sdst), "l"(gsrc) : "memory");
}
#define CP_COMMIT() asm volatile("cp.async.commit_group;" ::: "memory")
#define CP_WAIT1()  asm volatile("cp.async.wait_group 1;" ::: "memory")
#define CP_WAIT0()  asm volatile("cp.async.wait_group 0;" ::: "memory")

__device__ __forceinline__ float sigmoidf_(float x) { return 1.0f / (1.0f + __expf(-x)); }
__device__ __forceinline__ float fexp(float x) {
    x = fmaxf(x, -87.0f);
    float y = x * 1.44269504088896f;
    float r = rintf(y);
    float f = (y - r) * 0.693147180559945f;
    float p = 1.0f + f * (1.0f + f * (0.5f + f * (0.16666667f + f * (0.041666667f + f * 0.0083333333f))));
    return __int_as_float(((int)r + 127) << 23) * p;
}

// ---------------- init ----------------
__global__ void init_kernel() {
    int i = blockIdx.x * blockDim.x + threadIdx.x;
    if (i < 2 * BATCH * HID / 2) ((uint32_t*)g_hs)[i] = 0u;
    if (i == 0) { g_cnt = 0u; g_gen = 0u; }
}

// ---------------- conversions ----------------
__global__ void conv_plain(const float* __restrict__ src, int sel, int side) {
    size_t i = ((size_t)blockIdx.x * 256 + threadIdx.x) * 4;
    float4 v = *(const float4*)&src[i];
    __nv_bfloat16* dst = (sel == 0) ? g_wih_b[side] : g_wout_b;
    __nv_bfloat162 a = __floats2bfloat162_rn(v.x, v.y);
    __nv_bfloat162 b = __floats2bfloat162_rn(v.z, v.w);
    *(uint32_t*)&dst[i]     = *(uint32_t*)&a;
    *(uint32_t*)&dst[i + 2] = *(uint32_t*)&b;
}
__global__ void conv_whh(const float* __restrict__ src, int side) {
    size_t i = ((size_t)blockIdx.x * 256 + threadIdx.x) * 4;
    float4 v = *(const float4*)&src[i];
    __half2 a = __floats2half2_rn(v.x, v.y);
    __half2 b = __floats2half2_rn(v.z, v.w);
    *(uint32_t*)&g_whh_h[side][i]     = *(uint32_t*)&a;
    *(uint32_t*)&g_whh_h[side][i + 2] = *(uint32_t*)&b;
}

// ---------------- gather emb rows -> bf16 x matrix ----------------
__global__ void prep_x(const int* __restrict__ inl, const int* __restrict__ tgl,
                       const float* __restrict__ embi, const float* __restrict__ embt) {
    int row = blockIdx.x;
    int k = threadIdx.x * 8;
    int tok; const float* e;
    if (row < SRC * BATCH)       { tok = inl[row]; e = embi; }
    else if (row < GXROWS)       { tok = tgl[row - SRC * BATCH]; e = embt; }
    else                         { tok = 0; e = embi; }
    const float4* s = (const float4*)(e + (size_t)tok * HID + k);
    float4 v0 = s[0], v1 = s[1];
    __nv_bfloat162 p0 = __floats2bfloat162_rn(v0.x, v0.y);
    __nv_bfloat162 p1 = __floats2bfloat162_rn(v0.z, v0.w);
    __nv_bfloat162 p2 = __floats2bfloat162_rn(v1.x, v1.y);
    __nv_bfloat162 p3 = __floats2bfloat162_rn(v1.z, v1.w);
    uint4 o = make_uint4(*(uint32_t*)&p0, *(uint32_t*)&p1, *(uint32_t*)&p2, *(uint32_t*)&p3);
    *(uint4*)&g_x_b[(size_t)row * HID + k] = o;
}

// ================= gx GEMM (bf16 HMMA, cp.async 2-stage pipeline) =================
#define GX_SMEM 66048

__global__ __launch_bounds__(256) void gx_mma(const float* __restrict__ bihe, const float* __restrict__ bhhe,
                                              const float* __restrict__ bihd, const float* __restrict__ bhhd) {
    extern __shared__ __align__(16) char sm[];
    const uint32_t sb = smem_u32(sm);
    const int tid = threadIdx.x;
    const int l = tid & 31;
    const int w = tid >> 5;
    const int wr = w & 3;
    const int wc = w >> 2;
    const int n0 = blockIdx.x * 128;
    const int m0 = blockIdx.y * 128;
    const int side = (m0 >= SRC * BATCH) ? 1 : 0;
    const __nv_bfloat16* Wih = g_wih_b[side];
    float* bs = (float*)(sm + 65536);

    if (tid < 128) {
        const float* b1 = side ? bihd : bihe;
        const float* b2 = side ? bhhd : bhhe;
        bs[tid] = b1[n0 + tid] + b2[n0 + tid];
    }

    float acc[2][8][4];
#pragma unroll
    for (int i = 0; i < 2; ++i)
#pragma unroll
        for (int j = 0; j < 8; ++j)
#pragma unroll
            for (int q = 0; q < 4; ++q) acc[i][j][q] = 0.0f;

    const int a_row = wr * 32 + (l & 7) + ((l & 8) ? 8 : 0);
    const int a_k8  = (l & 16) ? 8 : 0;
    const int b4_n  = (l & 7) + ((l & 16) ? 8 : 0);
    const int b4_k8 = (l & 8) ? 8 : 0;

#define GX_STAGE(kb, s) do {                                                          \
        uint32_t base = sb + (s) * 32768;                                             \
        _Pragma("unroll")                                                             \
        for (int i_ = 0; i_ < 4; ++i_) {                                              \
            int c_ = tid + i_ * 256;                                                  \
            int row_ = c_ >> 3;                                                       \
            int k8_ = (c_ & 7) * 8;                                                   \
            uint32_t so_ = (uint32_t)(row_ * 128 + ((k8_ * 2) ^ ((row_ & 7) << 4)));  \
            cp16(base + so_,         &g_x_b[(size_t)(m0 + row_) * HID + (kb) + k8_]); \
            cp16(base + 16384 + so_, &Wih[(size_t)(n0 + row_) * HID + (kb) + k8_]);   \
        }                                                                             \
        CP_COMMIT();                                                                  \
    } while (0)

    GX_STAGE(0, 0);
    for (int c = 0; c < 8; ++c) {
        const int s = c & 1;
        if (c < 7) { GX_STAGE((c + 1) * 64, s ^ 1); CP_WAIT1(); }
        else       { CP_WAIT0(); }
        __syncthreads();
        const uint32_t aB = sb + s * 32768;
        const uint32_t bB = aB + 16384;
#pragma unroll
        for (int ks = 0; ks < 4; ++ks) {
            uint32_t a[2][4];
#pragma unroll
            for (int i = 0; i < 2; ++i) {
                int ar = a_row + i * 16;
                int ak = ks * 16 + a_k8;
                ldsm_x4(a[i], aB + ar * 128 + ((ak * 2) ^ ((ar & 7) << 4)));
            }
#pragma unroll
            for (int j16 = 0; j16 < 4; ++j16) {
                int bn = wc * 64 + j16 * 16 + b4_n;
                int bk = ks * 16 + b4_k8;
                uint32_t b[4];
                ldsm_x4_trans(b, bB + bn * 128 + ((bk * 2) ^ ((bn & 7) << 4)));
                mma_bf16(acc[0][j16 * 2],     a[0], b);
                mma_bf16(acc[1][j16 * 2],     a[1], b);
                mma_bf16(acc[0][j16 * 2 + 1], a[0], b + 2);
                mma_bf16(acc[1][j16 * 2 + 1], a[1], b + 2);
            }
        }
        __syncthreads();
    }

#pragma unroll
    for (int i = 0; i < 2; ++i)
#pragma unroll
        for (int j = 0; j < 8; ++j) {
            int row0 = m0 + wr * 32 + i * 16 + (l >> 2);
            int colL = wc * 64 + j * 8 + (l & 3) * 2;
            int col = n0 + colL;
            if (row0 < GXROWS) {
                float2 v0 = make_float2(acc[i][j][0] + bs[colL], acc[i][j][1] + bs[colL + 1]);
                *(float2*)&g_gx[(size_t)row0 * G4 + col] = v0;
            }
            int row1 = row0 + 8;
            if (row1 < GXROWS) {
                float2 v1 = make_float2(acc[i][j][2] + bs[colL], acc[i][j][3] + bs[colL + 1]);
                *(float2*)&g_gx[(size_t)row1 * G4 + col] = v1;
            }
        }
}

// ================= persistent LSTM recurrence (fp16 HMMA) =================
// CTA owns 8 hidden units (32 gate rows). W fp16 in SMEM. A = h fp16 (64 rows).
#define PS_WS 0                       // 2 sides * 8 kc * 32 rows * 128B = 65536
#define PS_AS 65536                   // 2 x 8192
#define PS_DS 81920                   // 64 * 36 * 4 = 9216
#define PS_CS 91136                   // 2048
#define PS_SMEM 93184

__device__ __forceinline__ void gbar(unsigned target) {
    __syncthreads();
    if (threadIdx.x == 0) {
        __threadfence();
        unsigned arrived = atomicAdd(&g_cnt, 1u) + 1u;
        if (arrived == target) {
            g_gen = target;
        } else {
            while (g_gen < target) {}
            __threadfence();
        }
    }
    __syncthreads();
}

__global__ __launch_bounds__(256, 1) void lstm_persist() {
    extern __shared__ __align__(16) char sm[];
    const uint32_t smb = smem_u32(sm);
    float* Ds = (float*)(sm + PS_DS);
    float* cs = (float*)(sm + PS_CS);
    const int tid = threadIdx.x;
    const int l = tid & 31;
    const int w = tid >> 5;
    const int wr = w & 3;           // m (batch) 16-tile
    const int wc = w >> 2;          // n half (16 cols)
    const int j0 = blockIdx.x * 8;

    // stage Whh fp16 slices: 2 sides x 8 kc x 32 rows x 128B
#pragma unroll
    for (int it = 0; it < 16; ++it) {
        int u = tid + it * 256;              // 0..4095 uint4
        int sd = u >> 11;
        int rem = u & 2047;
        int kcu = rem >> 8;
        int r2 = rem & 255;
        int rw = r2 >> 3;                    // 0..31 (g*8+jj)
        int k8 = (r2 & 7) * 8;
        int grow = (rw >> 3) * HID + j0 + (rw & 7);
        uint4 v = *(const uint4*)&g_whh_h[sd][(size_t)grow * HID + kcu * 64 + k8];
        uint32_t so = (uint32_t)(rw * 128 + ((k8 * 2) ^ ((rw & 7) << 4)));
        *(uint4*)(sm + PS_WS + sd * 32768 + kcu * 4096 + so) = v;
    }
    cs[tid] = 0.0f;
    cs[tid + 256] = 0.0f;
    __syncthreads();

    const int a_row = wr * 16 + (l & 7) + ((l & 8) ? 8 : 0);
    const int a_k8  = (l & 16) ? 8 : 0;
    const int b4_n  = (l & 7) + ((l & 16) ? 8 : 0);
    const int b4_k8 = (l & 8) ? 8 : 0;

#define PS_STAGE(hsrc, kc, s) do {                                                    \
        uint32_t base = smb + PS_AS + (s) * 8192;                                     \
        _Pragma("unroll")                                                             \
        for (int i_ = 0; i_ < 2; ++i_) {                                              \
            int c_ = tid + i_ * 256;                                                  \
            int row_ = c_ >> 3;                                                       \
            int k8_ = (c_ & 7) * 8;                                                   \
            uint32_t so_ = (uint32_t)(row_ * 128 + ((k8_ * 2) ^ ((row_ & 7) << 4)));  \
            cp16(base + so_, &(hsrc)[(size_t)row_ * HID + (kc) * 64 + k8_]);          \
        }                                                                             \
        CP_COMMIT();                                                                  \
    } while (0)

    for (int t = 0; t < NSTEP; ++t) {
        const int p = t & 1;
        const uint32_t wbase = smb + PS_WS + ((t < SRC) ? 0 : 32768);
        const __half* hsrc = g_hs[p];

        float acc[2][4];
#pragma unroll
        for (int j = 0; j < 2; ++j)
#pragma unroll
            for (int q = 0; q < 4; ++q) acc[j][q] = 0.0f;

        PS_STAGE(hsrc, 0, 0);
        for (int kc = 0; kc < 8; ++kc) {
            const int s = kc & 1;
            if (kc < 7) { PS_STAGE(hsrc, kc + 1, s ^ 1); CP_WAIT1(); }
            else        { CP_WAIT0(); }
            __syncthreads();
            const uint32_t aBs = smb + PS_AS + s * 8192;
#pragma unroll
            for (int ks = 0; ks < 4; ++ks) {
                uint32_t a[4];
                int ak = ks * 16 + a_k8;
                ldsm_x4(a, aBs + a_row * 128 + ((ak * 2) ^ ((a_row & 7) << 4)));
                int bn = wc * 16 + b4_n;
                int bk = ks * 16 + b4_k8;
                uint32_t b[4];
                ldsm_x4_trans(b, wbase + kc * 4096 + bn * 128 + ((bk * 2) ^ ((bn & 7) << 4)));
                mma_f16(acc[0], a, b);
                mma_f16(acc[1], a, b + 2);
            }
            __syncthreads();
        }

        // stage C -> Ds [64 m][36]
#pragma unroll
        for (int j = 0; j < 2; ++j) {
            int row = wr * 16 + (l >> 2);
            int col = wc * 16 + j * 8 + (l & 3) * 2;
            Ds[row * 36 + col]           = acc[j][0];
            Ds[row * 36 + col + 1]       = acc[j][1];
            Ds[(row + 8) * 36 + col]     = acc[j][2];
            Ds[(row + 8) * 36 + col + 1] = acc[j][3];
        }
        __syncthreads();

        const int dec = (t >= SRC);
#pragma unroll
        for (int s2 = 0; s2 < 2; ++s2) {
            int idx = tid + s2 * 256;
            int b = idx >> 3;
            int jj = idx & 7;
            const float* gxp = &g_gx[(size_t)(t * BATCH + b) * G4 + j0 + jj];
            float gate[4];
#pragma unroll
            for (int g = 0; g < 4; ++g)
                gate[g] = Ds[b * 36 + g * 8 + jj] + gxp[g * HID];
            float cc = cs[idx];
            float cn = sigmoidf_(gate[1]) * cc + sigmoidf_(gate[0]) * tanhf(gate[2]);
            float hn = sigmoidf_(gate[3]) * tanhf(cn);
            cs[idx] = cn;
            g_hs[p ^ 1][(size_t)b * HID + j0 + jj] = __float2half(hn);
            if (dec) {
                size_t dr = (size_t)((t - SRC) * BATCH + b) * HID + j0 + jj;
                g_hall_b[dr] = __float2bfloat16(hn);
                g_hall_f[dr] = hn;
            }
        }
        gbar((unsigned)(t + 1) * PCTAS);
    }
}

// ================= logits GEMM 128x256 + register-LSE (bf16 HMMA) =================
// 512 threads: 4 m-warps x 4 n-warps. stages: A 16K + B 32K per stage, 2 stages.
#define LGB_STAGE 49152
#define LGB_BIAS  98304              // 256 f32 = 1024
#define LGB_PM    99328              // 128*4 f32 = 2048
#define LGB_PSUM  101376             // 2048
#define LGB_SMEM  103424

__global__ __launch_bounds__(512) void logits_mma(const float* __restrict__ bout) {
    extern __shared__ __align__(16) char sm2[];
    const uint32_t sbase = smem_u32(sm2);
    const int tid = threadIdx.x;
    const int l = tid & 31;
    const int w = tid >> 5;
    const int wr = w & 3;            // m warp (32 rows)
    const int wc = w >> 2;           // n warp (64 cols)
    const int n0 = blockIdx.x * 256;
    const int m0 = blockIdx.y * 128;

    float* bias_s = (float*)(sm2 + LGB_BIAS);
    float* pm = (float*)(sm2 + LGB_PM);
    float* ps = (float*)(sm2 + LGB_PSUM);
    if (tid < 256) bias_s[tid] = bout[n0 + tid];

    float acc[2][8][4];
#pragma unroll
    for (int i = 0; i < 2; ++i)
#pragma unroll
        for (int j = 0; j < 8; ++j)
#pragma unroll
            for (int q = 0; q < 4; ++q) acc[i][j][q] = 0.0f;

    const int a_row = wr * 32 + (l & 7) + ((l & 8) ? 8 : 0);
    const int a_k8  = (l & 16) ? 8 : 0;
    const int b4_n  = (l & 7) + ((l & 16) ? 8 : 0);
    const int b4_k8 = (l & 8) ? 8 : 0;

#define LGB_STAGE_LD(kb, s) do {                                                      \
        uint32_t base = sbase + (s) * LGB_STAGE;                                      \
        _Pragma("unroll")                                                             \
        for (int i_ = 0; i_ < 2; ++i_) {                                              \
            int c_ = tid + i_ * 512;                                                  \
            int row_ = c_ >> 3;                                                       \
            int k8_ = (c_ & 7) * 8;                                                   \
            uint32_t so_ = (uint32_t)(row_ * 128 + ((k8_ * 2) ^ ((row_ & 7) << 4)));  \
            cp16(base + so_, &g_hall_b[(size_t)(m0 + row_) * HID + (kb) + k8_]);      \
        }                                                                             \
        _Pragma("unroll")                                                             \
        for (int i_ = 0; i_ < 4; ++i_) {                                              \
            int c_ = tid + i_ * 512;                                                  \
            int row_ = c_ >> 3;                                                       \
            int k8_ = (c_ & 7) * 8;                                                   \
            uint32_t so_ = (uint32_t)(row_ * 128 + ((k8_ * 2) ^ ((row_ & 7) << 4)));  \
            cp16(base + 16384 + so_, &g_wout_b[(size_t)(n0 + row_) * HID + (kb) + k8_]); \
        }                                                                             \
        CP_COMMIT();                                                                  \
    } while (0)

    LGB_STAGE_LD(0, 0);
    for (int c = 0; c < 8; ++c) {
        const int s = c & 1;
        if (c < 7) { LGB_STAGE_LD((c + 1) * 64, s ^ 1); CP_WAIT1(); }
        else       { CP_WAIT0(); }
        __syncthreads();
        const uint32_t aB = sbase + s * LGB_STAGE;
        const uint32_t bB = aB + 16384;
#pragma unroll
        for (int ks = 0; ks < 4; ++ks) {
            uint32_t a[2][4];
#pragma unroll
            for (int i = 0; i < 2; ++i) {
                int ar = a_row + i * 16;
                int ak = ks * 16 + a_k8;
                ldsm_x4(a[i], aB + ar * 128 + ((ak * 2) ^ ((ar & 7) << 4)));
            }
#pragma unroll
            for (int j16 = 0; j16 < 4; ++j16) {
                int bn = wc * 64 + j16 * 16 + b4_n;
                int bk = ks * 16 + b4_k8;
                uint32_t b[4];
                ldsm_x4_trans(b, bB + bn * 128 + ((bk * 2) ^ ((bn & 7) << 4)));
                mma_bf16(acc[0][j16 * 2],     a[0], b);
                mma_bf16(acc[1][j16 * 2],     a[1], b);
                mma_bf16(acc[0][j16 * 2 + 1], a[0], b + 2);
                mma_bf16(acc[1][j16 * 2 + 1], a[1], b + 2);
            }
        }
        __syncthreads();
    }

    // register LSE: each thread reduces its 4 row-groups of 16 elems, quad-shuffle, smem partials
#pragma unroll
    for (int i = 0; i < 2; ++i) {
#pragma unroll
        for (int half = 0; half < 2; ++half) {
            int row = wr * 32 + i * 16 + (l >> 2) + half * 8;
            float m = -INFINITY;
#pragma unroll
            for (int j = 0; j < 8; ++j) {
                int colL = wc * 64 + j * 8 + (l & 3) * 2;
                float v0 = acc[i][j][half * 2]     + bias_s[colL];
                float v1 = acc[i][j][half * 2 + 1] + bias_s[colL + 1];
                m = fmaxf(m, fmaxf(v0, v1));
            }
            float sx = 0.0f;
#pragma unroll
            for (int j = 0; j < 8; ++j) {
                int colL = wc * 64 + j * 8 + (l & 3) * 2;
                sx += fexp(acc[i][j][half * 2]     + bias_s[colL]     - m);
                sx += fexp(acc[i][j][half * 2 + 1] + bias_s[colL + 1] - m);
            }
#pragma unroll
            for (int d = 1; d < 4; d <<= 1) {
                float mo = __shfl_xor_sync(0xffffffffu, m, d);
                float so = __shfl_xor_sync(0xffffffffu, sx, d);
                float mm = fmaxf(m, mo);
                sx = sx * fexp(m - mm) + so * fexp(mo - mm);
                m = mm;
            }
            if ((l & 3) == 0) {
                pm[row * 4 + wc] = m;
                ps[row * 4 + wc] = sx;
            }
        }
    }
    __syncthreads();

    if (tid < 128) {
        float m = pm[tid * 4];
#pragma unroll
        for (int q = 1; q < 4; ++q) m = fmaxf(m, pm[tid * 4 + q]);
        float sx = 0.0f;
#pragma unroll
        for (int q = 0; q < 4; ++q) sx += ps[tid * 4 + q] * fexp(pm[tid * 4 + q] - m);
        int gr = m0 + tid;
        if (gr < DROWS) {
            g_pmax[(size_t)gr * VT2 + blockIdx.x] = m;
            g_psum[(size_t)gr * VT2 + blockIdx.x] = sx;
        }
    }
}

// ================= combine partials -> per-(d,b) loss =================
__global__ void combine_loss(const int* __restrict__ target_lines,
                             const float* __restrict__ bout) {
    __shared__ float sred[128];
    const int b = blockIdx.x;
    const int d = blockIdx.y;
    const int bs = d * BATCH + b;
    const int tid = threadIdx.x;

    float m = -INFINITY;
    for (int p = tid; p < VT2; p += 128) m = fmaxf(m, g_pmax[(size_t)bs * VT2 + p]);
    sred[tid] = m;
    __syncthreads();
    for (int s = 64; s > 0; s >>= 1) {
        if (tid < s) sred[tid] = fmaxf(sred[tid], sred[tid + s]);
        __syncthreads();
    }
    const float gmax = sred[0];
    __syncthreads();

    float sum = 0.0f;
    for (int p = tid; p < VT2; p += 128)
        sum += g_psum[(size_t)bs * VT2 + p] * __expf(g_pmax[(size_t)bs * VT2 + p] - gmax);
    sred[tid] = sum;
    __syncthreads();
    for (int s = 64; s > 0; s >>= 1) {
        if (tid < s) sred[tid] += sred[tid + s];
        __syncthreads();
    }
    const float gsum = sred[0];
    __syncthreads();

    const int nxt = target_lines[(d + 1) * BATCH + b];
    float4 hv = ((const float4*)&g_hall_f[(size_t)bs * HID])[tid];
    const __nv_bfloat16* wrow = &g_wout_b[(size_t)nxt * HID];
    float w0 = __bfloat162float(wrow[tid * 4 + 0]);
    float w1 = __bfloat162float(wrow[tid * 4 + 1]);
    float w2 = __bfloat162float(wrow[tid * 4 + 2]);
    float w3 = __bfloat162float(wrow[tid * 4 + 3]);
    float h0 = __bfloat162float(__float2bfloat16(hv.x));
    float h1 = __bfloat162float(__float2bfloat16(hv.y));
    float h2 = __bfloat162float(__float2bfloat16(hv.z));
    float h3 = __bfloat162float(__float2bfloat16(hv.w));
    sred[tid] = h0 * w0 + h1 * w1 + h2 * w2 + h3 * w3;
    __syncthreads();
    for (int s = 64; s > 0; s >>= 1) {
        if (tid < s) sred[tid] += sred[tid + s];
        __syncthreads();
    }
    if (tid == 0)
        g_losses[bs] = -(sred[0] + bout[nxt] - gmax - logf(gsum));
}

// ---------------- final deterministic sum ----------------
__global__ void final_kernel(float* __restrict__ out) {
    __shared__ float sred[256];
    const int tid = threadIdx.x;
    float s = 0.0f;
    for (int i = tid; i < DROWS; i += 256) s += g_losses[i];
    sred[tid] = s;
    __syncthreads();
    for (int st = 128; st > 0; st >>= 1) {
        if (tid < st) sred[tid] += sred[tid + st];
        __syncthreads();
    }
    if (tid == 0) out[0] = sred[0] * (1.0f / (float)BATCH);
}

// ---------------- host ----------------
extern "C" void kernel_launch(void* const* d_in, const int* in_sizes, int n_in,
                              void* d_out, int out_size) {
    (void)in_sizes; (void)n_in; (void)out_size;
    const int*   input_lines  = (const int*)  d_in[0];
    const int*   target_lines = (const int*)  d_in[1];
    const float* emb_in       = (const float*)d_in[2];
    const float* emb_tgt      = (const float*)d_in[3];
    const float* W_ih_enc     = (const float*)d_in[4];
    const float* W_hh_enc     = (const float*)d_in[5];
    const float* b_ih_enc     = (const float*)d_in[6];
    const float* b_hh_enc     = (const float*)d_in[7];
    const float* W_ih_dec     = (const float*)d_in[8];
    const float* W_hh_dec     = (const float*)d_in[9];
    const float* b_ih_dec     = (const float*)d_in[10];
    const float* b_hh_dec     = (const float*)d_in[11];
    const float* W_out        = (const float*)d_in[12];
    const float* b_out        = (const float*)d_in[13];
    float* out = (float*)d_out;

    cudaFuncSetAttribute(gx_mma,       cudaFuncAttributeMaxDynamicSharedMemorySize, GX_SMEM);
    cudaFuncSetAttribute(lstm_persist, cudaFuncAttributeMaxDynamicSharedMemorySize, PS_SMEM);
    cudaFuncSetAttribute(logits_mma,   cudaFuncAttributeMaxDynamicSharedMemorySize, LGB_SMEM);

    init_kernel<<<256, 256>>>();

    const int wblk = G4 * HID / 4 / 256;                 // 1024
    conv_plain<<<wblk, 256>>>(W_ih_enc, 0, 0);
    conv_plain<<<wblk, 256>>>(W_ih_dec, 0, 1);
    conv_plain<<<VOCAB * HID / 4 / 256, 256>>>(W_out, 1, 0);
    conv_whh<<<wblk, 256>>>(W_hh_enc, 0);
    conv_whh<<<wblk, 256>>>(W_hh_dec, 1);
    prep_x<<<XROWS_PAD, 64>>>(input_lines, target_lines, emb_in, emb_tgt);

    gx_mma<<<dim3(16, XROWS_PAD / 128), 256, GX_SMEM>>>(b_ih_enc, b_hh_enc, b_ih_dec, b_hh_dec);

    lstm_persist<<<PCTAS, 256, PS_SMEM>>>();

    logits_mma<<<dim3(VT2, DROWS_PAD / 128), 512, LGB_SMEM>>>(b_out);
    combine_loss<<<dim3(BATCH, TGT), 128>>>(target_lines, b_out);
    final_kernel<<<1, 256>>>(out);
}

// round 8
// speedup vs baseline: 11.8094x; 1.1013x over previous
#include <cuda_runtime.h>
#include <cuda_bf16.h>
#include <cuda_fp16.h>
#include <math.h>
#include <stdint.h>

#define HID   512
#define G4    2048
#define BATCH 64
#define VOCAB 32000
#define SRC   50
#define TGT   49
#define NSTEP (SRC + TGT)

#define VT2    125               // 32000 / 256
#define DROWS  (TGT * BATCH)     // 3136 decode rows
#define DROWS_PAD 3328           // 26 * 128
#define GXROWS (NSTEP * BATCH)   // 6336
#define XROWS_PAD 6400
#define PCTAS 64

// ---------------- static scratch ----------------
__device__ float g_gx[(size_t)GXROWS * G4];
__device__ __nv_bfloat16 g_x_b[(size_t)XROWS_PAD * HID];
__device__ __nv_bfloat16 g_wih_b[2][(size_t)G4 * HID];
__device__ __half g_whh_h[2][(size_t)G4 * HID];
__device__ __half g_hs[2][BATCH * HID];                      // h ping-pong (fp16)
__device__ float g_hall_f[(size_t)DROWS * HID];
__device__ __nv_bfloat16 g_hall_b[(size_t)DROWS_PAD * HID];  // pad rows stay zero
__device__ __nv_bfloat16 g_wout_b[(size_t)VOCAB * HID];
__device__ float g_pmax[(size_t)DROWS * VT2];
__device__ float g_psum[(size_t)DROWS * VT2];
__device__ float g_losses[DROWS];
__device__ unsigned g_cnt;
__device__ volatile unsigned g_gen;

// ---------------- helpers ----------------
__device__ __forceinline__ uint32_t smem_u32(const void* p) {
    uint32_t a;
    asm("{ .reg .u64 t; cvta.to.shared.u64 t, %1; cvt.u32.u64 %0, t; }" : "=r"(a) : "l"(p));
    return a;
}
__device__ __forceinline__ void ldsm_x4(uint32_t* r, uint32_t addr) {
    asm volatile("ldmatrix.sync.aligned.m8n8.x4.shared.b16 {%0,%1,%2,%3}, [%4];"
        : "=r"(r[0]), "=r"(r[1]), "=r"(r[2]), "=r"(r[3]) : "r"(addr));
}
__device__ __forceinline__ void ldsm_x4_trans(uint32_t* r, uint32_t addr) {
    asm volatile("ldmatrix.sync.aligned.m8n8.x4.trans.shared.b16 {%0,%1,%2,%3}, [%4];"
        : "=r"(r[0]), "=r"(r[1]), "=r"(r[2]), "=r"(r[3]) : "r"(addr));
}
__device__ __forceinline__ void mma_bf16(float* c, const uint32_t* a, const uint32_t* b) {
    asm volatile("mma.sync.aligned.m16n8k16.row.col.f32.bf16.bf16.f32 "
        "{%0,%1,%2,%3}, {%4,%5,%6,%7}, {%8,%9}, {%0,%1,%2,%3};"
        : "+f"(c[0]), "+f"(c[1]), "+f"(c[2]), "+f"(c[3])
        : "r"(a[0]), "r"(a[1]), "r"(a[2]), "r"(a[3]), "r"(b[0]), "r"(b[1]));
}
__device__ __forceinline__ void mma_f16(float* c, const uint32_t* a, const uint32_t* b) {
    asm volatile("mma.sync.aligned.m16n8k16.row.col.f32.f16.f16.f32 "
        "{%0,%1,%2,%3}, {%4,%5,%6,%7}, {%8,%9}, {%0,%1,%2,%3};"
        : "+f"(c[0]), "+f"(c[1]), "+f"(c[2]), "+f"(c[3])
        : "r"(a[0]), "r"(a[1]), "r"(a[2]), "r"(a[3]), "r"(b[0]), "r"(b[1]));
}
__device__ __forceinline__ void cp16(uint32_t sdst, const void* gsrc) {
    asm volatile("cp.async.cg.shared.global [%0], [%1], 16;" :: "r"(sdst), "l"(gsrc) : "memory");
}
#define CP_COMMIT() asm volatile("cp.async.commit_group;" ::: "memory")
#define CP_WAIT1()  asm volatile("cp.async.wait_group 1;" ::: "memory")
#define CP_WAIT0()  asm volatile("cp.async.wait_group 0;" ::: "memory")

__device__ __forceinline__ float sigmoidf_(float x) { return 1.0f / (1.0f + __expf(-x)); }
__device__ __forceinline__ float fexp(float x) {
    x = fmaxf(x, -87.0f);
    float y = x * 1.44269504088896f;
    float r = rintf(y);
    float f = (y - r) * 0.693147180559945f;
    float p = 1.0f + f * (1.0f + f * (0.5f + f * (0.16666667f + f * (0.041666667f + f * 0.0083333333f))));
    return __int_as_float(((int)r + 127) << 23) * p;
}

// ---------------- init ----------------
__global__ void init_kernel() {
    int i = blockIdx.x * blockDim.x + threadIdx.x;
    if (i < 2 * BATCH * HID / 2) ((uint32_t*)g_hs)[i] = 0u;
    if (i == 0) { g_cnt = 0u; g_gen = 0u; }
}

// ---------------- merged small-weight conversions (4 x 4MB) ----------------
__global__ void conv_weights(const float* __restrict__ wie, const float* __restrict__ wid,
                             const float* __restrict__ whe, const float* __restrict__ whd) {
    int id = blockIdx.x >> 10;
    size_t i = ((size_t)(blockIdx.x & 1023) * 256 + threadIdx.x) * 4;
    const float* src = (id == 0) ? wie : (id == 1) ? wid : (id == 2) ? whe : whd;
    float4 v = *(const float4*)&src[i];
    if (id < 2) {
        __nv_bfloat162 a = __floats2bfloat162_rn(v.x, v.y);
        __nv_bfloat162 b = __floats2bfloat162_rn(v.z, v.w);
        __nv_bfloat16* dst = g_wih_b[id];
        *(uint32_t*)&dst[i]     = *(uint32_t*)&a;
        *(uint32_t*)&dst[i + 2] = *(uint32_t*)&b;
    } else {
        __half2 a = __floats2half2_rn(v.x, v.y);
        __half2 b = __floats2half2_rn(v.z, v.w);
        __half* dst = g_whh_h[id - 2];
        *(uint32_t*)&dst[i]     = *(uint32_t*)&a;
        *(uint32_t*)&dst[i + 2] = *(uint32_t*)&b;
    }
}
__global__ void conv_wout(const float* __restrict__ src) {
    size_t i = ((size_t)blockIdx.x * 256 + threadIdx.x) * 4;
    float4 v = *(const float4*)&src[i];
    __nv_bfloat162 a = __floats2bfloat162_rn(v.x, v.y);
    __nv_bfloat162 b = __floats2bfloat162_rn(v.z, v.w);
    *(uint32_t*)&g_wout_b[i]     = *(uint32_t*)&a;
    *(uint32_t*)&g_wout_b[i + 2] = *(uint32_t*)&b;
}

// ---------------- gather emb rows -> bf16 x matrix ----------------
__global__ void prep_x(const int* __restrict__ inl, const int* __restrict__ tgl,
                       const float* __restrict__ embi, const float* __restrict__ embt) {
    int row = blockIdx.x;
    int k = threadIdx.x * 8;
    int tok; const float* e;
    if (row < SRC * BATCH)       { tok = inl[row]; e = embi; }
    else if (row < GXROWS)       { tok = tgl[row - SRC * BATCH]; e = embt; }
    else                         { tok = 0; e = embi; }
    const float4* s = (const float4*)(e + (size_t)tok * HID + k);
    float4 v0 = s[0], v1 = s[1];
    __nv_bfloat162 p0 = __floats2bfloat162_rn(v0.x, v0.y);
    __nv_bfloat162 p1 = __floats2bfloat162_rn(v0.z, v0.w);
    __nv_bfloat162 p2 = __floats2bfloat162_rn(v1.x, v1.y);
    __nv_bfloat162 p3 = __floats2bfloat162_rn(v1.z, v1.w);
    uint4 o = make_uint4(*(uint32_t*)&p0, *(uint32_t*)&p1, *(uint32_t*)&p2, *(uint32_t*)&p3);
    *(uint4*)&g_x_b[(size_t)row * HID + k] = o;
}

// ================= gx GEMM (bf16 HMMA, cp.async 2-stage pipeline) =================
#define GX_SMEM 66048

__global__ __launch_bounds__(256) void gx_mma(const float* __restrict__ bihe, const float* __restrict__ bhhe,
                                              const float* __restrict__ bihd, const float* __restrict__ bhhd) {
    extern __shared__ __align__(16) char sm[];
    const uint32_t sb = smem_u32(sm);
    const int tid = threadIdx.x;
    const int l = tid & 31;
    const int w = tid >> 5;
    const int wr = w & 3;
    const int wc = w >> 2;
    const int n0 = blockIdx.x * 128;
    const int m0 = blockIdx.y * 128;
    const int side = (m0 >= SRC * BATCH) ? 1 : 0;
    const __nv_bfloat16* Wih = g_wih_b[side];
    float* bs = (float*)(sm + 65536);

    if (tid < 128) {
        const float* b1 = side ? bihd : bihe;
        const float* b2 = side ? bhhd : bhhe;
        bs[tid] = b1[n0 + tid] + b2[n0 + tid];
    }

    float acc[2][8][4];
#pragma unroll
    for (int i = 0; i < 2; ++i)
#pragma unroll
        for (int j = 0; j < 8; ++j)
#pragma unroll
            for (int q = 0; q < 4; ++q) acc[i][j][q] = 0.0f;

    const int a_row = wr * 32 + (l & 7) + ((l & 8) ? 8 : 0);
    const int a_k8  = (l & 16) ? 8 : 0;
    const int b4_n  = (l & 7) + ((l & 16) ? 8 : 0);
    const int b4_k8 = (l & 8) ? 8 : 0;

#define GX_STAGE(kb, s) do {                                                          \
        uint32_t base = sb + (s) * 32768;                                             \
        _Pragma("unroll")                                                             \
        for (int i_ = 0; i_ < 4; ++i_) {                                              \
            int c_ = tid + i_ * 256;                                                  \
            int row_ = c_ >> 3;                                                       \
            int k8_ = (c_ & 7) * 8;                                                   \
            uint32_t so_ = (uint32_t)(row_ * 128 + ((k8_ * 2) ^ ((row_ & 7) << 4)));  \
            cp16(base + so_,         &g_x_b[(size_t)(m0 + row_) * HID + (kb) + k8_]); \
            cp16(base + 16384 + so_, &Wih[(size_t)(n0 + row_) * HID + (kb) + k8_]);   \
        }                                                                             \
        CP_COMMIT();                                                                  \
    } while (0)

    GX_STAGE(0, 0);
    for (int c = 0; c < 8; ++c) {
        const int s = c & 1;
        if (c < 7) { GX_STAGE((c + 1) * 64, s ^ 1); CP_WAIT1(); }
        else       { CP_WAIT0(); }
        __syncthreads();
        const uint32_t aB = sb + s * 32768;
        const uint32_t bB = aB + 16384;
#pragma unroll
        for (int ks = 0; ks < 4; ++ks) {
            uint32_t a[2][4];
#pragma unroll
            for (int i = 0; i < 2; ++i) {
                int ar = a_row + i * 16;
                int ak = ks * 16 + a_k8;
                ldsm_x4(a[i], aB + ar * 128 + ((ak * 2) ^ ((ar & 7) << 4)));
            }
#pragma unroll
            for (int j16 = 0; j16 < 4; ++j16) {
                int bn = wc * 64 + j16 * 16 + b4_n;
                int bk = ks * 16 + b4_k8;
                uint32_t b[4];
                ldsm_x4_trans(b, bB + bn * 128 + ((bk * 2) ^ ((bn & 7) << 4)));
                mma_bf16(acc[0][j16 * 2],     a[0], b);
                mma_bf16(acc[1][j16 * 2],     a[1], b);
                mma_bf16(acc[0][j16 * 2 + 1], a[0], b + 2);
                mma_bf16(acc[1][j16 * 2 + 1], a[1], b + 2);
            }
        }
        __syncthreads();
    }

#pragma unroll
    for (int i = 0; i < 2; ++i)
#pragma unroll
        for (int j = 0; j < 8; ++j) {
            int row0 = m0 + wr * 32 + i * 16 + (l >> 2);
            int colL = wc * 64 + j * 8 + (l & 3) * 2;
            int col = n0 + colL;
            if (row0 < GXROWS) {
                float2 v0 = make_float2(acc[i][j][0] + bs[colL], acc[i][j][1] + bs[colL + 1]);
                *(float2*)&g_gx[(size_t)row0 * G4 + col] = v0;
            }
            int row1 = row0 + 8;
            if (row1 < GXROWS) {
                float2 v1 = make_float2(acc[i][j][2] + bs[colL], acc[i][j][3] + bs[colL + 1]);
                *(float2*)&g_gx[(size_t)row1 * G4 + col] = v1;
            }
        }
}

// ================= persistent LSTM recurrence (fp16 HMMA, 512 thr, split-K warpgroups) =================
// CTA owns 8 hidden units (32 gate rows). W fp16 resident in SMEM.
// Per step: single-shot A staging (all K) + gx prefetch, 2 cp groups, split-K across 2 warpgroups.
#define PS_WS 0                       // 2 sides * 8 kc * 32 rows * 128B = 65536
#define PS_AS 65536                   // 8 kc * 64 rows * 128B = 65536
#define PS_GX 131072                  // 64*4*8 f32 = 8192
#define PS_DS 139264                  // 2 * 64*36*4 = 18432
#define PS_CS 157696                  // 512 f32 = 2048
#define PS_SMEM 159744

__device__ __forceinline__ void gbar(unsigned target) {
    __syncthreads();
    if (threadIdx.x == 0) {
        __threadfence();
        unsigned arrived = atomicAdd(&g_cnt, 1u) + 1u;
        if (arrived == target) {
            g_gen = target;
        } else {
            while (g_gen < target) {}
            __threadfence();
        }
    }
    __syncthreads();
}

__global__ __launch_bounds__(512, 1) void lstm_persist() {
    extern __shared__ __align__(16) char sm[];
    const uint32_t smb = smem_u32(sm);
    float* gxs = (float*)(sm + PS_GX);
    float* Ds0 = (float*)(sm + PS_DS);
    float* Ds1 = (float*)(sm + PS_DS + 9216);
    float* cs  = (float*)(sm + PS_CS);
    const int tid = threadIdx.x;
    const int l = tid & 31;
    const int w = tid >> 5;
    const int wg = w >> 3;           // K warp-group (kc 0-3 / 4-7)
    const int wr = w & 3;            // m (batch) 16-row tile
    const int wc = (w >> 2) & 1;     // n half (16 cols)
    const int j0 = blockIdx.x * 8;

    // stage Whh fp16 slices: 2 sides x 8 kc x 32 rows x 128B
#pragma unroll
    for (int it = 0; it < 16; ++it) {
        int u = tid + it * 512;              // 0..8191 uint4
        int sd = u >> 12;
        int rem = u & 4095;
        int kcu = rem >> 9;
        int r2 = rem & 511;
        int rw = r2 >> 4;                    // 0..31 (g*8+jj)
        int k8 = (r2 & 15) * 8;
        // careful: per kc chunk = 32 rows * 128B = 4096B = 256 uint4; redo decode:
        (void)rw; (void)k8; (void)kcu; (void)sd;
        break;
    }
    // (clean version below)
    for (int u = tid; u < 8192; u += 512) {
        int sd = u >> 12;                    // 0..1
        int rem = u & 4095;                  // 4096 uint4 per side
        int kcu = rem >> 8;                  // 256 uint4 per kc chunk
        int r2 = rem & 255;
        int rw = r2 >> 3;                    // 0..31
        int k8 = (r2 & 7) * 8;
        int grow = (rw >> 3) * HID + j0 + (rw & 7);
        uint4 v = *(const uint4*)&g_whh_h[sd][(size_t)grow * HID + kcu * 64 + k8];
        uint32_t so = (uint32_t)(rw * 128 + ((k8 * 2) ^ ((rw & 7) << 4)));
        *(uint4*)(sm + PS_WS + sd * 32768 + kcu * 4096 + so) = v;
    }
    cs[tid] = 0.0f;
    __syncthreads();

    const int a_row = wr * 16 + (l & 7) + ((l & 8) ? 8 : 0);
    const int a_k8  = (l & 16) ? 8 : 0;
    const int b4_n  = (l & 7) + ((l & 16) ? 8 : 0);
    const int b4_k8 = (l & 8) ? 8 : 0;
    const int cb = tid >> 3;         // batch for cell update
    const int cjj = tid & 7;

    for (int t = 0; t < NSTEP; ++t) {
        const int p = t & 1;
        const uint32_t wbase = smb + PS_WS + ((t < SRC) ? 0 : 32768) + wg * 4 * 4096;
        const __half* hsrc = g_hs[p];

        // group 1: A kc 0-3 + gx prefetch
#pragma unroll
        for (int i = 0; i < 4; ++i) {
            int u = tid + i * 512;           // 0..2047 -> kc 0..3
            int kc = u >> 9;
            int v2 = u & 511;
            int row = v2 >> 3;
            int k8 = (v2 & 7) * 8;
            uint32_t so = (uint32_t)(kc * 8192 + row * 128 + ((k8 * 2) ^ ((row & 7) << 4)));
            cp16(smb + PS_AS + so, &hsrc[(size_t)row * HID + kc * 64 + k8]);
        }
        {
            int b = tid >> 3;
            int r = tid & 7;
            int g = r >> 1;
            int half = r & 1;
            cp16(smb + PS_GX + (uint32_t)(b * 128 + g * 32 + half * 16),
                 &g_gx[(size_t)(t * BATCH + b) * G4 + g * 512 + j0 + half * 4]);
        }
        CP_COMMIT();
        // group 2: A kc 4-7
#pragma unroll
        for (int i = 4; i < 8; ++i) {
            int u = tid + i * 512;
            int kc = u >> 9;
            int v2 = u & 511;
            int row = v2 >> 3;
            int k8 = (v2 & 7) * 8;
            uint32_t so = (uint32_t)(kc * 8192 + row * 128 + ((k8 * 2) ^ ((row & 7) << 4)));
            cp16(smb + PS_AS + so, &hsrc[(size_t)row * HID + kc * 64 + k8]);
        }
        CP_COMMIT();
        CP_WAIT0();
        __syncthreads();

        float acc[2][4];
#pragma unroll
        for (int j = 0; j < 2; ++j)
#pragma unroll
            for (int q = 0; q < 4; ++q) acc[j][q] = 0.0f;

#pragma unroll
        for (int kq = 0; kq < 4; ++kq) {
            const int kc = wg * 4 + kq;
#pragma unroll
            for (int ks = 0; ks < 4; ++ks) {
                uint32_t a[4];
                int ak = ks * 16 + a_k8;
                ldsm_x4(a, smb + PS_AS + kc * 8192 + a_row * 128 + ((ak * 2) ^ ((a_row & 7) << 4)));
                int bn = wc * 16 + b4_n;
                int bk = ks * 16 + b4_k8;
                uint32_t b[4];
                ldsm_x4_trans(b, wbase + kq * 4096 + bn * 128 + ((bk * 2) ^ ((bn & 7) << 4)));
                mma_f16(acc[0], a, b);
                mma_f16(acc[1], a, b + 2);
            }
        }

        // stage C -> Ds[wg] [64 m][36]
        float* Dsw = wg ? Ds1 : Ds0;
#pragma unroll
        for (int j = 0; j < 2; ++j) {
            int row = wr * 16 + (l >> 2);
            int col = wc * 16 + j * 8 + (l & 3) * 2;
            Dsw[row * 36 + col]           = acc[j][0];
            Dsw[row * 36 + col + 1]       = acc[j][1];
            Dsw[(row + 8) * 36 + col]     = acc[j][2];
            Dsw[(row + 8) * 36 + col + 1] = acc[j][3];
        }
        __syncthreads();

        // cell update: 512 elems, 1 per thread
        {
            float gate[4];
#pragma unroll
            for (int g = 0; g < 4; ++g)
                gate[g] = Ds0[cb * 36 + g * 8 + cjj] + Ds1[cb * 36 + g * 8 + cjj]
                        + gxs[cb * 32 + g * 8 + cjj];
            float cc = cs[tid];
            float cn = sigmoidf_(gate[1]) * cc + sigmoidf_(gate[0]) * tanhf(gate[2]);
            float hn = sigmoidf_(gate[3]) * tanhf(cn);
            cs[tid] = cn;
            g_hs[p ^ 1][(size_t)cb * HID + j0 + cjj] = __float2half(hn);
            if (t >= SRC) {
                size_t dr = (size_t)((t - SRC) * BATCH + cb) * HID + j0 + cjj;
                g_hall_b[dr] = __float2bfloat16(hn);
                g_hall_f[dr] = hn;
            }
        }
        gbar((unsigned)(t + 1) * PCTAS);
    }
}

// ================= logits GEMM 128x256 + register-LSE (bf16 HMMA) =================
#define LGB_STAGE 49152
#define LGB_BIAS  98304
#define LGB_PM    99328
#define LGB_PSUM  101376
#define LGB_SMEM  103424

__global__ __launch_bounds__(512) void logits_mma(const float* __restrict__ bout) {
    extern __shared__ __align__(16) char sm2[];
    const uint32_t sbase = smem_u32(sm2);
    const int tid = threadIdx.x;
    const int l = tid & 31;
    const int w = tid >> 5;
    const int wr = w & 3;
    const int wc = w >> 2;
    const int n0 = blockIdx.x * 256;
    const int m0 = blockIdx.y * 128;

    float* bias_s = (float*)(sm2 + LGB_BIAS);
    float* pm = (float*)(sm2 + LGB_PM);
    float* ps = (float*)(sm2 + LGB_PSUM);
    if (tid < 256) bias_s[tid] = bout[n0 + tid];

    float acc[2][8][4];
#pragma unroll
    for (int i = 0; i < 2; ++i)
#pragma unroll
        for (int j = 0; j < 8; ++j)
#pragma unroll
            for (int q = 0; q < 4; ++q) acc[i][j][q] = 0.0f;

    const int a_row = wr * 32 + (l & 7) + ((l & 8) ? 8 : 0);
    const int a_k8  = (l & 16) ? 8 : 0;
    const int b4_n  = (l & 7) + ((l & 16) ? 8 : 0);
    const int b4_k8 = (l & 8) ? 8 : 0;

#define LGB_STAGE_LD(kb, s) do {                                                      \
        uint32_t base = sbase + (s) * LGB_STAGE;                                      \
        _Pragma("unroll")                                                             \
        for (int i_ = 0; i_ < 2; ++i_) {                                              \
            int c_ = tid + i_ * 512;                                                  \
            int row_ = c_ >> 3;                                                       \
            int k8_ = (c_ & 7) * 8;                                                   \
            uint32_t so_ = (uint32_t)(row_ * 128 + ((k8_ * 2) ^ ((row_ & 7) << 4)));  \
            cp16(base + so_, &g_hall_b[(size_t)(m0 + row_) * HID + (kb) + k8_]);      \
        }                                                                             \
        _Pragma("unroll")                                                             \
        for (int i_ = 0; i_ < 4; ++i_) {                                              \
            int c_ = tid + i_ * 512;                                                  \
            int row_ = c_ >> 3;                                                       \
            int k8_ = (c_ & 7) * 8;                                                   \
            uint32_t so_ = (uint32_t)(row_ * 128 + ((k8_ * 2) ^ ((row_ & 7) << 4)));  \
            cp16(base + 16384 + so_, &g_wout_b[(size_t)(n0 + row_) * HID + (kb) + k8_]); \
        }                                                                             \
        CP_COMMIT();                                                                  \
    } while (0)

    LGB_STAGE_LD(0, 0);
    for (int c = 0; c < 8; ++c) {
        const int s = c & 1;
        if (c < 7) { LGB_STAGE_LD((c + 1) * 64, s ^ 1); CP_WAIT1(); }
        else       { CP_WAIT0(); }
        __syncthreads();
        const uint32_t aB = sbase + s * LGB_STAGE;
        const uint32_t bB = aB + 16384;
#pragma unroll
        for (int ks = 0; ks < 4; ++ks) {
            uint32_t a[2][4];
#pragma unroll
            for (int i = 0; i < 2; ++i) {
                int ar = a_row + i * 16;
                int ak = ks * 16 + a_k8;
                ldsm_x4(a[i], aB + ar * 128 + ((ak * 2) ^ ((ar & 7) << 4)));
            }
#pragma unroll
            for (int j16 = 0; j16 < 4; ++j16) {
                int bn = wc * 64 + j16 * 16 + b4_n;
                int bk = ks * 16 + b4_k8;
                uint32_t b[4];
                ldsm_x4_trans(b, bB + bn * 128 + ((bk * 2) ^ ((bn & 7) << 4)));
                mma_bf16(acc[0][j16 * 2],     a[0], b);
                mma_bf16(acc[1][j16 * 2],     a[1], b);
                mma_bf16(acc[0][j16 * 2 + 1], a[0], b + 2);
                mma_bf16(acc[1][j16 * 2 + 1], a[1], b + 2);
            }
        }
        __syncthreads();
    }

#pragma unroll
    for (int i = 0; i < 2; ++i) {
#pragma unroll
        for (int half = 0; half < 2; ++half) {
            int row = wr * 32 + i * 16 + (l >> 2) + half * 8;
            float m = -INFINITY;
#pragma unroll
            for (int j = 0; j < 8; ++j) {
                int colL = wc * 64 + j * 8 + (l & 3) * 2;
                float v0 = acc[i][j][half * 2]     + bias_s[colL];
                float v1 = acc[i][j][half * 2 + 1] + bias_s[colL + 1];
                m = fmaxf(m, fmaxf(v0, v1));
            }
            float sx = 0.0f;
#pragma unroll
            for (int j = 0; j < 8; ++j) {
                int colL = wc * 64 + j * 8 + (l & 3) * 2;
                sx += fexp(acc[i][j][half * 2]     + bias_s[colL]     - m);
                sx += fexp(acc[i][j][half * 2 + 1] + bias_s[colL + 1] - m);
            }
#pragma unroll
            for (int d = 1; d < 4; d <<= 1) {
                float mo = __shfl_xor_sync(0xffffffffu, m, d);
                float so = __shfl_xor_sync(0xffffffffu, sx, d);
                float mm = fmaxf(m, mo);
                sx = sx * fexp(m - mm) + so * fexp(mo - mm);
                m = mm;
            }
            if ((l & 3) == 0) {
                pm[row * 4 + wc] = m;
                ps[row * 4 + wc] = sx;
            }
        }
    }
    __syncthreads();

    if (tid < 128) {
        float m = pm[tid * 4];
#pragma unroll
        for (int q = 1; q < 4; ++q) m = fmaxf(m, pm[tid * 4 + q]);
        float sx = 0.0f;
#pragma unroll
        for (int q = 0; q < 4; ++q) sx += ps[tid * 4 + q] * fexp(pm[tid * 4 + q] - m);
        int gr = m0 + tid;
        if (gr < DROWS) {
            g_pmax[(size_t)gr * VT2 + blockIdx.x] = m;
            g_psum[(size_t)gr * VT2 + blockIdx.x] = sx;
        }
    }
}

// ================= combine partials -> per-(d,b) loss =================
__global__ void combine_loss(const int* __restrict__ target_lines,
                             const float* __restrict__ bout) {
    __shared__ float sred[128];
    const int b = blockIdx.x;
    const int d = blockIdx.y;
    const int bs = d * BATCH + b;
    const int tid = threadIdx.x;

    float m = -INFINITY;
    for (int p = tid; p < VT2; p += 128) m = fmaxf(m, g_pmax[(size_t)bs * VT2 + p]);
    sred[tid] = m;
    __syncthreads();
    for (int s = 64; s > 0; s >>= 1) {
        if (tid < s) sred[tid] = fmaxf(sred[tid], sred[tid + s]);
        __syncthreads();
    }
    const float gmax = sred[0];
    __syncthreads();

    float sum = 0.0f;
    for (int p = tid; p < VT2; p += 128)
        sum += g_psum[(size_t)bs * VT2 + p] * __expf(g_pmax[(size_t)bs * VT2 + p] - gmax);
    sred[tid] = sum;
    __syncthreads();
    for (int s = 64; s > 0; s >>= 1) {
        if (tid < s) sred[tid] += sred[tid + s];
        __syncthreads();
    }
    const float gsum = sred[0];
    __syncthreads();

    const int nxt = target_lines[(d + 1) * BATCH + b];
    float4 hv = ((const float4*)&g_hall_f[(size_t)bs * HID])[tid];
    const __nv_bfloat16* wrow = &g_wout_b[(size_t)nxt * HID];
    float w0 = __bfloat162float(wrow[tid * 4 + 0]);
    float w1 = __bfloat162float(wrow[tid * 4 + 1]);
    float w2 = __bfloat162float(wrow[tid * 4 + 2]);
    float w3 = __bfloat162float(wrow[tid * 4 + 3]);
    float h0 = __bfloat162float(__float2bfloat16(hv.x));
    float h1 = __bfloat162float(__float2bfloat16(hv.y));
    float h2 = __bfloat162float(__float2bfloat16(hv.z));
    float h3 = __bfloat162float(__float2bfloat16(hv.w));
    sred[tid] = h0 * w0 + h1 * w1 + h2 * w2 + h3 * w3;
    __syncthreads();
    for (int s = 64; s > 0; s >>= 1) {
        if (tid < s) sred[tid] += sred[tid + s];
        __syncthreads();
    }
    if (tid == 0)
        g_losses[bs] = -(sred[0] + bout[nxt] - gmax - logf(gsum));
}

// ---------------- final deterministic sum ----------------
__global__ void final_kernel(float* __restrict__ out) {
    __shared__ float sred[256];
    const int tid = threadIdx.x;
    float s = 0.0f;
    for (int i = tid; i < DROWS; i += 256) s += g_losses[i];
    sred[tid] = s;
    __syncthreads();
    for (int st = 128; st > 0; st >>= 1) {
        if (tid < st) sred[tid] += sred[tid + st];
        __syncthreads();
    }
    if (tid == 0) out[0] = sred[0] * (1.0f / (float)BATCH);
}

// ---------------- host ----------------
extern "C" void kernel_launch(void* const* d_in, const int* in_sizes, int n_in,
                              void* d_out, int out_size) {
    (void)in_sizes; (void)n_in; (void)out_size;
    const int*   input_lines  = (const int*)  d_in[0];
    const int*   target_lines = (const int*)  d_in[1];
    const float* emb_in       = (const float*)d_in[2];
    const float* emb_tgt      = (const float*)d_in[3];
    const float* W_ih_enc     = (const float*)d_in[4];
    const float* W_hh_enc     = (const float*)d_in[5];
    const float* b_ih_enc     = (const float*)d_in[6];
    const float* b_hh_enc     = (const float*)d_in[7];
    const float* W_ih_dec     = (const float*)d_in[8];
    const float* W_hh_dec     = (const float*)d_in[9];
    const float* b_ih_dec     = (const float*)d_in[10];
    const float* b_hh_dec     = (const float*)d_in[11];
    const float* W_out        = (const float*)d_in[12];
    const float* b_out        = (const float*)d_in[13];
    float* out = (float*)d_out;

    cudaFuncSetAttribute(gx_mma,       cudaFuncAttributeMaxDynamicSharedMemorySize, GX_SMEM);
    cudaFuncSetAttribute(lstm_persist, cudaFuncAttributeMaxDynamicSharedMemorySize, PS_SMEM);
    cudaFuncSetAttribute(logits_mma,   cudaFuncAttributeMaxDynamicSharedMemorySize, LGB_SMEM);

    init_kernel<<<256, 256>>>();

    conv_weights<<<4096, 256>>>(W_ih_enc, W_ih_dec, W_hh_enc, W_hh_dec);
    conv_wout<<<VOCAB * HID / 4 / 256, 256>>>(W_out);
    prep_x<<<XROWS_PAD, 64>>>(input_lines, target_lines, emb_in, emb_tgt);

    gx_mma<<<dim3(16, XROWS_PAD / 128), 256, GX_SMEM>>>(b_ih_enc, b_hh_enc, b_ih_dec, b_hh_dec);

    lstm_persist<<<PCTAS, 512, PS_SMEM>>>();

    logits_mma<<<dim3(VT2, DROWS_PAD / 128), 512, LGB_SMEM>>>(b_out);
    combine_loss<<<dim3(BATCH, TGT), 128>>>(target_lines, b_out);
    final_kernel<<<1, 256>>>(out);
}

// round 9
// speedup vs baseline: 11.8715x; 1.0053x over previous
#include <cuda_runtime.h>
#include <cuda_bf16.h>
#include <cuda_fp16.h>
#include <math.h>
#include <stdint.h>

#define HID   512
#define G4    2048
#define BATCH 64
#define VOCAB 32000
#define SRC   50
#define TGT   49
#define NSTEP (SRC + TGT)

#define VT2    125               // 32000 / 256
#define MT2    26                // 3328 / 128
#define DROWS  (TGT * BATCH)     // 3136 decode rows
#define DROWS_PAD 3328           // 26 * 128
#define GXROWS (NSTEP * BATCH)   // 6336
#define XROWS_PAD 6400
#define PCTAS 64

// ---------------- static scratch ----------------
__device__ float g_gx[(size_t)GXROWS * G4];
__device__ __nv_bfloat16 g_x_b[(size_t)XROWS_PAD * HID];
__device__ __nv_bfloat16 g_wih_b[2][(size_t)G4 * HID];
__device__ __half g_whh_h[2][(size_t)G4 * HID];
__device__ __half g_hs[2][BATCH * HID];                      // h ping-pong (fp16)
__device__ __nv_bfloat16 g_hall_b[(size_t)DROWS_PAD * HID];  // pad rows stay zero
__device__ __nv_bfloat16 g_wout_b[(size_t)VOCAB * HID];
__device__ float g_pmax[(size_t)DROWS * VT2];
__device__ float g_psum[(size_t)DROWS * VT2];
__device__ float g_losses[DROWS];
__device__ unsigned g_cnt;
__device__ volatile unsigned g_gen;

// ---------------- helpers ----------------
__device__ __forceinline__ uint32_t smem_u32(const void* p) {
    uint32_t a;
    asm("{ .reg .u64 t; cvta.to.shared.u64 t, %1; cvt.u32.u64 %0, t; }" : "=r"(a) : "l"(p));
    return a;
}
__device__ __forceinline__ void ldsm_x4(uint32_t* r, uint32_t addr) {
    asm volatile("ldmatrix.sync.aligned.m8n8.x4.shared.b16 {%0,%1,%2,%3}, [%4];"
        : "=r"(r[0]), "=r"(r[1]), "=r"(r[2]), "=r"(r[3]) : "r"(addr));
}
__device__ __forceinline__ void ldsm_x4_trans(uint32_t* r, uint32_t addr) {
    asm volatile("ldmatrix.sync.aligned.m8n8.x4.trans.shared.b16 {%0,%1,%2,%3}, [%4];"
        : "=r"(r[0]), "=r"(r[1]), "=r"(r[2]), "=r"(r[3]) : "r"(addr));
}
__device__ __forceinline__ void mma_bf16(float* c, const uint32_t* a, const uint32_t* b) {
    asm volatile("mma.sync.aligned.m16n8k16.row.col.f32.bf16.bf16.f32 "
        "{%0,%1,%2,%3}, {%4,%5,%6,%7}, {%8,%9}, {%0,%1,%2,%3};"
        : "+f"(c[0]), "+f"(c[1]), "+f"(c[2]), "+f"(c[3])
        : "r"(a[0]), "r"(a[1]), "r"(a[2]), "r"(a[3]), "r"(b[0]), "r"(b[1]));
}
__device__ __forceinline__ void mma_f16(float* c, const uint32_t* a, const uint32_t* b) {
    asm volatile("mma.sync.aligned.m16n8k16.row.col.f32.f16.f16.f32 "
        "{%0,%1,%2,%3}, {%4,%5,%6,%7}, {%8,%9}, {%0,%1,%2,%3};"
        : "+f"(c[0]), "+f"(c[1]), "+f"(c[2]), "+f"(c[3])
        : "r"(a[0]), "r"(a[1]), "r"(a[2]), "r"(a[3]), "r"(b[0]), "r"(b[1]));
}
__device__ __forceinline__ void cp16(uint32_t sdst, const void* gsrc) {
    asm volatile("cp.async.cg.shared.global [%0], [%1], 16;" :: "r"(sdst), "l"(gsrc) : "memory");
}
#define CP_COMMIT() asm volatile("cp.async.commit_group;" ::: "memory")
#define CP_WAIT1()  asm volatile("cp.async.wait_group 1;" ::: "memory")
#define CP_WAIT0()  asm volatile("cp.async.wait_group 0;" ::: "memory")

__device__ __forceinline__ float sigmoidf_(float x) { return 1.0f / (1.0f + __expf(-x)); }
__device__ __forceinline__ float fexp(float x) {
    x = fmaxf(x, -87.0f);
    float y = x * 1.44269504088896f;
    float r = rintf(y);
    float f = (y - r) * 0.693147180559945f;
    float p = 1.0f + f * (1.0f + f * (0.5f + f * (0.16666667f + f * (0.041666667f + f * 0.0083333333f))));
    return __int_as_float(((int)r + 127) << 23) * p;
}

// ---------------- init ----------------
__global__ void init_kernel() {
    int i = blockIdx.x * blockDim.x + threadIdx.x;
    if (i < 2 * BATCH * HID / 2) ((uint32_t*)g_hs)[i] = 0u;
    if (i == 0) { g_cnt = 0u; g_gen = 0u; }
}

// ---------------- merged small-weight conversions ----------------
__global__ void conv_weights(const float* __restrict__ wie, const float* __restrict__ wid,
                             const float* __restrict__ whe, const float* __restrict__ whd) {
    int id = blockIdx.x >> 10;
    size_t i = ((size_t)(blockIdx.x & 1023) * 256 + threadIdx.x) * 4;
    const float* src = (id == 0) ? wie : (id == 1) ? wid : (id == 2) ? whe : whd;
    float4 v = *(const float4*)&src[i];
    if (id < 2) {
        __nv_bfloat162 a = __floats2bfloat162_rn(v.x, v.y);
        __nv_bfloat162 b = __floats2bfloat162_rn(v.z, v.w);
        __nv_bfloat16* dst = g_wih_b[id];
        *(uint32_t*)&dst[i]     = *(uint32_t*)&a;
        *(uint32_t*)&dst[i + 2] = *(uint32_t*)&b;
    } else {
        __half2 a = __floats2half2_rn(v.x, v.y);
        __half2 b = __floats2half2_rn(v.z, v.w);
        __half* dst = g_whh_h[id - 2];
        *(uint32_t*)&dst[i]     = *(uint32_t*)&a;
        *(uint32_t*)&dst[i + 2] = *(uint32_t*)&b;
    }
}
__global__ void conv_wout(const float* __restrict__ src) {
    size_t i = ((size_t)blockIdx.x * 256 + threadIdx.x) * 4;
    float4 v = *(const float4*)&src[i];
    __nv_bfloat162 a = __floats2bfloat162_rn(v.x, v.y);
    __nv_bfloat162 b = __floats2bfloat162_rn(v.z, v.w);
    *(uint32_t*)&g_wout_b[i]     = *(uint32_t*)&a;
    *(uint32_t*)&g_wout_b[i + 2] = *(uint32_t*)&b;
}

// ---------------- gather emb rows -> bf16 x matrix ----------------
__global__ void prep_x(const int* __restrict__ inl, const int* __restrict__ tgl,
                       const float* __restrict__ embi, const float* __restrict__ embt) {
    int row = blockIdx.x;
    int k = threadIdx.x * 8;
    int tok; const float* e;
    if (row < SRC * BATCH)       { tok = inl[row]; e = embi; }
    else if (row < GXROWS)       { tok = tgl[row - SRC * BATCH]; e = embt; }
    else                         { tok = 0; e = embi; }
    const float4* s = (const float4*)(e + (size_t)tok * HID + k);
    float4 v0 = s[0], v1 = s[1];
    __nv_bfloat162 p0 = __floats2bfloat162_rn(v0.x, v0.y);
    __nv_bfloat162 p1 = __floats2bfloat162_rn(v0.z, v0.w);
    __nv_bfloat162 p2 = __floats2bfloat162_rn(v1.x, v1.y);
    __nv_bfloat162 p3 = __floats2bfloat162_rn(v1.z, v1.w);
    uint4 o = make_uint4(*(uint32_t*)&p0, *(uint32_t*)&p1, *(uint32_t*)&p2, *(uint32_t*)&p3);
    *(uint4*)&g_x_b[(size_t)row * HID + k] = o;
}

// ================= gx GEMM (bf16 HMMA, cp.async 3-stage, 1 sync/chunk) =================
#define GX_SMEM 98816            // 3 x 32768 + 512 bias

__global__ __launch_bounds__(256) void gx_mma(const float* __restrict__ bihe, const float* __restrict__ bhhe,
                                              const float* __restrict__ bihd, const float* __restrict__ bhhd) {
    extern __shared__ __align__(16) char sm[];
    const uint32_t sb = smem_u32(sm);
    const int tid = threadIdx.x;
    const int l = tid & 31;
    const int w = tid >> 5;
    const int wr = w & 3;
    const int wc = w >> 2;
    const int n0 = blockIdx.x * 128;
    const int m0 = blockIdx.y * 128;
    const int side = (m0 >= SRC * BATCH) ? 1 : 0;
    const __nv_bfloat16* Wih = g_wih_b[side];
    float* bs = (float*)(sm + 98304);

    if (tid < 128) {
        const float* b1 = side ? bihd : bihe;
        const float* b2 = side ? bhhd : bhhe;
        bs[tid] = b1[n0 + tid] + b2[n0 + tid];
    }

    float acc[2][8][4];
#pragma unroll
    for (int i = 0; i < 2; ++i)
#pragma unroll
        for (int j = 0; j < 8; ++j)
#pragma unroll
            for (int q = 0; q < 4; ++q) acc[i][j][q] = 0.0f;

    const int a_row = wr * 32 + (l & 7) + ((l & 8) ? 8 : 0);
    const int a_k8  = (l & 16) ? 8 : 0;
    const int b4_n  = (l & 7) + ((l & 16) ? 8 : 0);
    const int b4_k8 = (l & 8) ? 8 : 0;

#define GX_STAGE(kb, s) do {                                                          \
        uint32_t base = sb + (s) * 32768;                                             \
        _Pragma("unroll")                                                             \
        for (int i_ = 0; i_ < 4; ++i_) {                                              \
            int c_ = tid + i_ * 256;                                                  \
            int row_ = c_ >> 3;                                                       \
            int k8_ = (c_ & 7) * 8;                                                   \
            uint32_t so_ = (uint32_t)(row_ * 128 + ((k8_ * 2) ^ ((row_ & 7) << 4)));  \
            cp16(base + so_,         &g_x_b[(size_t)(m0 + row_) * HID + (kb) + k8_]); \
            cp16(base + 16384 + so_, &Wih[(size_t)(n0 + row_) * HID + (kb) + k8_]);   \
        }                                                                             \
        CP_COMMIT();                                                                  \
    } while (0)

    GX_STAGE(0, 0);
    GX_STAGE(64, 1);
    for (int c = 0; c < 8; ++c) {
        if (c < 7) { CP_WAIT1(); } else { CP_WAIT0(); }
        __syncthreads();
        if (c < 6) GX_STAGE((c + 2) * 64, (c + 2) % 3);
        const uint32_t aB = sb + (c % 3) * 32768;
        const uint32_t bB = aB + 16384;
#pragma unroll
        for (int ks = 0; ks < 4; ++ks) {
            uint32_t a[2][4];
#pragma unroll
            for (int i = 0; i < 2; ++i) {
                int ar = a_row + i * 16;
                int ak = ks * 16 + a_k8;
                ldsm_x4(a[i], aB + ar * 128 + ((ak * 2) ^ ((ar & 7) << 4)));
            }
#pragma unroll
            for (int j16 = 0; j16 < 4; ++j16) {
                int bn = wc * 64 + j16 * 16 + b4_n;
                int bk = ks * 16 + b4_k8;
                uint32_t b[4];
                ldsm_x4_trans(b, bB + bn * 128 + ((bk * 2) ^ ((bn & 7) << 4)));
                mma_bf16(acc[0][j16 * 2],     a[0], b);
                mma_bf16(acc[1][j16 * 2],     a[1], b);
                mma_bf16(acc[0][j16 * 2 + 1], a[0], b + 2);
                mma_bf16(acc[1][j16 * 2 + 1], a[1], b + 2);
            }
        }
    }

#pragma unroll
    for (int i = 0; i < 2; ++i)
#pragma unroll
        for (int j = 0; j < 8; ++j) {
            int row0 = m0 + wr * 32 + i * 16 + (l >> 2);
            int colL = wc * 64 + j * 8 + (l & 3) * 2;
            int col = n0 + colL;
            if (row0 < GXROWS) {
                float2 v0 = make_float2(acc[i][j][0] + bs[colL], acc[i][j][1] + bs[colL + 1]);
                *(float2*)&g_gx[(size_t)row0 * G4 + col] = v0;
            }
            int row1 = row0 + 8;
            if (row1 < GXROWS) {
                float2 v1 = make_float2(acc[i][j][2] + bs[colL], acc[i][j][3] + bs[colL + 1]);
                *(float2*)&g_gx[(size_t)row1 * G4 + col] = v1;
            }
        }
}

// ================= persistent LSTM recurrence (fp16 HMMA, 512 thr, split-K warpgroups) =================
#define PS_WS 0                       // 2 sides * 8 kc * 32 rows * 128B = 65536
#define PS_AS 65536                   // 8 kc * 64 rows * 128B = 65536
#define PS_GX 131072                  // 2 x 8192 (double-buffered gx)
#define PS_DS 147456                  // 2 * 64*36*4 = 18432
#define PS_CS 165888                  // 512 f32 = 2048
#define PS_SMEM 167936

__device__ __forceinline__ void gbar(unsigned target) {
    __syncthreads();
    if (threadIdx.x == 0) {
        __threadfence();
        unsigned arrived = atomicAdd(&g_cnt, 1u) + 1u;
        if (arrived == target) {
            g_gen = target;
        } else {
            while (g_gen < target) { __nanosleep(32); }
            __threadfence();
        }
    }
    __syncthreads();
}

__global__ __launch_bounds__(512, 1) void lstm_persist() {
    extern __shared__ __align__(16) char sm[];
    const uint32_t smb = smem_u32(sm);
    float* gxs = (float*)(sm + PS_GX);
    float* Ds0 = (float*)(sm + PS_DS);
    float* Ds1 = (float*)(sm + PS_DS + 9216);
    float* cs  = (float*)(sm + PS_CS);
    const int tid = threadIdx.x;
    const int l = tid & 31;
    const int w = tid >> 5;
    const int wg = w >> 3;           // K warp-group (kc 0-3 / 4-7)
    const int wr = w & 3;            // m (batch) 16-row tile
    const int wc = (w >> 2) & 1;     // n half (16 cols)
    const int j0 = blockIdx.x * 8;

    // stage Whh fp16 slices: 2 sides x 8 kc x 32 rows x 128B
    for (int u = tid; u < 8192; u += 512) {
        int sd = u >> 12;
        int rem = u & 4095;
        int kcu = rem >> 8;
        int r2 = rem & 255;
        int rw = r2 >> 3;
        int k8 = (r2 & 7) * 8;
        int grow = (rw >> 3) * HID + j0 + (rw & 7);
        uint4 v = *(const uint4*)&g_whh_h[sd][(size_t)grow * HID + kcu * 64 + k8];
        uint32_t so = (uint32_t)(rw * 128 + ((k8 * 2) ^ ((rw & 7) << 4)));
        *(uint4*)(sm + PS_WS + sd * 32768 + kcu * 4096 + so) = v;
    }
    cs[tid] = 0.0f;
    __syncthreads();

    const int a_row = wr * 16 + (l & 7) + ((l & 8) ? 8 : 0);
    const int a_k8  = (l & 16) ? 8 : 0;
    const int b4_n  = (l & 7) + ((l & 16) ? 8 : 0);
    const int b4_k8 = (l & 8) ? 8 : 0;
    const int cb = tid >> 3;
    const int cjj = tid & 7;
    const int gx_b = tid >> 3;
    const int gx_g = (tid & 7) >> 1;
    const int gx_h = tid & 1;

    // prologue: prefetch gx(0) into buf 0
    cp16(smb + PS_GX + (uint32_t)(gx_b * 128 + gx_g * 32 + gx_h * 16),
         &g_gx[(size_t)(0 * BATCH + gx_b) * G4 + gx_g * 512 + j0 + gx_h * 4]);
    CP_COMMIT();

    for (int t = 0; t < NSTEP; ++t) {
        const int p = t & 1;
        const uint32_t wbase = smb + PS_WS + ((t < SRC) ? 0 : 32768) + wg * 4 * 4096;
        const __half* hsrc = g_hs[p];

        // stage A (all 8 kc) as one group
#pragma unroll
        for (int i = 0; i < 8; ++i) {
            int u = tid + i * 512;
            int kc = u >> 9;
            int v2 = u & 511;
            int row = v2 >> 3;
            int k8 = (v2 & 7) * 8;
            uint32_t so = (uint32_t)(kc * 8192 + row * 128 + ((k8 * 2) ^ ((row & 7) << 4)));
            cp16(smb + PS_AS + so, &hsrc[(size_t)row * HID + kc * 64 + k8]);
        }
        CP_COMMIT();
        CP_WAIT0();                  // waits A(t) and gx(t) prefetch
        __syncthreads();

        float acc[2][4];
#pragma unroll
        for (int j = 0; j < 2; ++j)
#pragma unroll
            for (int q = 0; q < 4; ++q) acc[j][q] = 0.0f;

#pragma unroll
        for (int kq = 0; kq < 4; ++kq) {
            const int kc = wg * 4 + kq;
#pragma unroll
            for (int ks = 0; ks < 4; ++ks) {
                uint32_t a[4];
                int ak = ks * 16 + a_k8;
                ldsm_x4(a, smb + PS_AS + kc * 8192 + a_row * 128 + ((ak * 2) ^ ((a_row & 7) << 4)));
                int bn = wc * 16 + b4_n;
                int bk = ks * 16 + b4_k8;
                uint32_t b[4];
                ldsm_x4_trans(b, wbase + kq * 4096 + bn * 128 + ((bk * 2) ^ ((bn & 7) << 4)));
                mma_f16(acc[0], a, b);
                mma_f16(acc[1], a, b + 2);
            }
        }

        float* Dsw = wg ? Ds1 : Ds0;
#pragma unroll
        for (int j = 0; j < 2; ++j) {
            int row = wr * 16 + (l >> 2);
            int col = wc * 16 + j * 8 + (l & 3) * 2;
            Dsw[row * 36 + col]           = acc[j][0];
            Dsw[row * 36 + col + 1]       = acc[j][1];
            Dsw[(row + 8) * 36 + col]     = acc[j][2];
            Dsw[(row + 8) * 36 + col + 1] = acc[j][3];
        }
        __syncthreads();

        // cell update: 512 elems, 1 per thread
        {
            const float* gxb = gxs + (t & 1) * 2048;
            float gate[4];
#pragma unroll
            for (int g = 0; g < 4; ++g)
                gate[g] = Ds0[cb * 36 + g * 8 + cjj] + Ds1[cb * 36 + g * 8 + cjj]
                        + gxb[cb * 32 + g * 8 + cjj];
            float cc = cs[tid];
            float cn = sigmoidf_(gate[1]) * cc + sigmoidf_(gate[0]) * tanhf(gate[2]);
            float hn = sigmoidf_(gate[3]) * tanhf(cn);
            cs[tid] = cn;
            g_hs[p ^ 1][(size_t)cb * HID + j0 + cjj] = __float2half(hn);
            if (t >= SRC) {
                size_t dr = (size_t)((t - SRC) * BATCH + cb) * HID + j0 + cjj;
                g_hall_b[dr] = __float2bfloat16(hn);
            }
        }

        // prefetch gx(t+1) into the other buffer (independent of the barrier)
        if (t + 1 < NSTEP) {
            cp16(smb + PS_GX + (uint32_t)(((t + 1) & 1) * 8192 + gx_b * 128 + gx_g * 32 + gx_h * 16),
                 &g_gx[(size_t)((t + 1) * BATCH + gx_b) * G4 + gx_g * 512 + j0 + gx_h * 4]);
            CP_COMMIT();
        }
        gbar((unsigned)(t + 1) * PCTAS);
    }
}

// ================= logits GEMM 128x256 + register-LSE (bf16 HMMA, 3-stage, 1 sync/chunk) =================
#define LGB_STG   49152
#define LGB_BIAS  147456             // 256 f32 = 1024
#define LGB_PM    148480             // 2048
#define LGB_PSUM  150528             // 2048
#define LGB_SMEM  152576

__global__ __launch_bounds__(512) void logits_mma(const float* __restrict__ bout) {
    extern __shared__ __align__(16) char sm2[];
    const uint32_t sbase = smem_u32(sm2);
    const int tid = threadIdx.x;
    const int l = tid & 31;
    const int w = tid >> 5;
    const int wr = w & 3;
    const int wc = w >> 2;
    const int m0 = blockIdx.x * 128;     // m fastest: wave reuses Wout tiles in L2
    const int n0 = blockIdx.y * 256;
    const int ntile = blockIdx.y;

    float* bias_s = (float*)(sm2 + LGB_BIAS);
    float* pm = (float*)(sm2 + LGB_PM);
    float* ps = (float*)(sm2 + LGB_PSUM);
    if (tid < 256) bias_s[tid] = bout[n0 + tid];

    float acc[2][8][4];
#pragma unroll
    for (int i = 0; i < 2; ++i)
#pragma unroll
        for (int j = 0; j < 8; ++j)
#pragma unroll
            for (int q = 0; q < 4; ++q) acc[i][j][q] = 0.0f;

    const int a_row = wr * 32 + (l & 7) + ((l & 8) ? 8 : 0);
    const int a_k8  = (l & 16) ? 8 : 0;
    const int b4_n  = (l & 7) + ((l & 16) ? 8 : 0);
    const int b4_k8 = (l & 8) ? 8 : 0;

#define LGB_STAGE_LD(kb, s) do {                                                      \
        uint32_t base = sbase + (s) * LGB_STG;                                        \
        _Pragma("unroll")                                                             \
        for (int i_ = 0; i_ < 2; ++i_) {                                              \
            int c_ = tid + i_ * 512;                                                  \
            int row_ = c_ >> 3;                                                       \
            int k8_ = (c_ & 7) * 8;                                                   \
            uint32_t so_ = (uint32_t)(row_ * 128 + ((k8_ * 2) ^ ((row_ & 7) << 4)));  \
            cp16(base + so_, &g_hall_b[(size_t)(m0 + row_) * HID + (kb) + k8_]);      \
        }                                                                             \
        _Pragma("unroll")                                                             \
        for (int i_ = 0; i_ < 4; ++i_) {                                              \
            int c_ = tid + i_ * 512;                                                  \
            int row_ = c_ >> 3;                                                       \
            int k8_ = (c_ & 7) * 8;                                                   \
            uint32_t so_ = (uint32_t)(row_ * 128 + ((k8_ * 2) ^ ((row_ & 7) << 4)));  \
            cp16(base + 16384 + so_, &g_wout_b[(size_t)(n0 + row_) * HID + (kb) + k8_]); \
        }                                                                             \
        CP_COMMIT();                                                                  \
    } while (0)

    LGB_STAGE_LD(0, 0);
    LGB_STAGE_LD(64, 1);
    for (int c = 0; c < 8; ++c) {
        if (c < 7) { CP_WAIT1(); } else { CP_WAIT0(); }
        __syncthreads();
        if (c < 6) LGB_STAGE_LD((c + 2) * 64, (c + 2) % 3);
        const uint32_t aB = sbase + (c % 3) * LGB_STG;
        const uint32_t bB = aB + 16384;
#pragma unroll
        for (int ks = 0; ks < 4; ++ks) {
            uint32_t a[2][4];
#pragma unroll
            for (int i = 0; i < 2; ++i) {
                int ar = a_row + i * 16;
                int ak = ks * 16 + a_k8;
                ldsm_x4(a[i], aB + ar * 128 + ((ak * 2) ^ ((ar & 7) << 4)));
            }
#pragma unroll
            for (int j16 = 0; j16 < 4; ++j16) {
                int bn = wc * 64 + j16 * 16 + b4_n;
                int bk = ks * 16 + b4_k8;
                uint32_t b[4];
                ldsm_x4_trans(b, bB + bn * 128 + ((bk * 2) ^ ((bn & 7) << 4)));
                mma_bf16(acc[0][j16 * 2],     a[0], b);
                mma_bf16(acc[1][j16 * 2],     a[1], b);
                mma_bf16(acc[0][j16 * 2 + 1], a[0], b + 2);
                mma_bf16(acc[1][j16 * 2 + 1], a[1], b + 2);
            }
        }
    }

#pragma unroll
    for (int i = 0; i < 2; ++i) {
#pragma unroll
        for (int half = 0; half < 2; ++half) {
            int row = wr * 32 + i * 16 + (l >> 2) + half * 8;
            float m = -INFINITY;
#pragma unroll
            for (int j = 0; j < 8; ++j) {
                int colL = wc * 64 + j * 8 + (l & 3) * 2;
                float v0 = acc[i][j][half * 2]     + bias_s[colL];
                float v1 = acc[i][j][half * 2 + 1] + bias_s[colL + 1];
                m = fmaxf(m, fmaxf(v0, v1));
            }
            float sx = 0.0f;
#pragma unroll
            for (int j = 0; j < 8; ++j) {
                int colL = wc * 64 + j * 8 + (l & 3) * 2;
                sx += fexp(acc[i][j][half * 2]     + bias_s[colL]     - m);
                sx += fexp(acc[i][j][half * 2 + 1] + bias_s[colL + 1] - m);
            }
#pragma unroll
            for (int d = 1; d < 4; d <<= 1) {
                float mo = __shfl_xor_sync(0xffffffffu, m, d);
                float so = __shfl_xor_sync(0xffffffffu, sx, d);
                float mm = fmaxf(m, mo);
                sx = sx * fexp(m - mm) + so * fexp(mo - mm);
                m = mm;
            }
            if ((l & 3) == 0) {
                pm[row * 4 + wc] = m;
                ps[row * 4 + wc] = sx;
            }
        }
    }
    __syncthreads();

    if (tid < 128) {
        float m = pm[tid * 4];
#pragma unroll
        for (int q = 1; q < 4; ++q) m = fmaxf(m, pm[tid * 4 + q]);
        float sx = 0.0f;
#pragma unroll
        for (int q = 0; q < 4; ++q) sx += ps[tid * 4 + q] * fexp(pm[tid * 4 + q] - m);
        int gr = m0 + tid;
        if (gr < DROWS) {
            g_pmax[(size_t)gr * VT2 + ntile] = m;
            g_psum[(size_t)gr * VT2 + ntile] = sx;
        }
    }
}

// ================= combine partials -> per-(d,b) loss =================
__global__ void combine_loss(const int* __restrict__ target_lines,
                             const float* __restrict__ bout) {
    __shared__ float sred[128];
    const int b = blockIdx.x;
    const int d = blockIdx.y;
    const int bs = d * BATCH + b;
    const int tid = threadIdx.x;

    float m = -INFINITY;
    for (int p = tid; p < VT2; p += 128) m = fmaxf(m, g_pmax[(size_t)bs * VT2 + p]);
    sred[tid] = m;
    __syncthreads();
    for (int s = 64; s > 0; s >>= 1) {
        if (tid < s) sred[tid] = fmaxf(sred[tid], sred[tid + s]);
        __syncthreads();
    }
    const float gmax = sred[0];
    __syncthreads();

    float sum = 0.0f;
    for (int p = tid; p < VT2; p += 128)
        sum += g_psum[(size_t)bs * VT2 + p] * __expf(g_pmax[(size_t)bs * VT2 + p] - gmax);
    sred[tid] = sum;
    __syncthreads();
    for (int s = 64; s > 0; s >>= 1) {
        if (tid < s) sred[tid] += sred[tid + s];
        __syncthreads();
    }
    const float gsum = sred[0];
    __syncthreads();

    const int nxt = target_lines[(d + 1) * BATCH + b];
    const __nv_bfloat16* hrow = &g_hall_b[(size_t)bs * HID];
    const __nv_bfloat16* wrow = &g_wout_b[(size_t)nxt * HID];
    float ds = 0.0f;
#pragma unroll
    for (int q = 0; q < 4; ++q)
        ds += __bfloat162float(hrow[tid * 4 + q]) * __bfloat162float(wrow[tid * 4 + q]);
    sred[tid] = ds;
    __syncthreads();
    for (int s = 64; s > 0; s >>= 1) {
        if (tid < s) sred[tid] += sred[tid + s];
        __syncthreads();
    }
    if (tid == 0)
        g_losses[bs] = -(sred[0] + bout[nxt] - gmax - logf(gsum));
}

// ---------------- final deterministic sum ----------------
__global__ void final_kernel(float* __restrict__ out) {
    __shared__ float sred[256];
    const int tid = threadIdx.x;
    float s = 0.0f;
    for (int i = tid; i < DROWS; i += 256) s += g_losses[i];
    sred[tid] = s;
    __syncthreads();
    for (int st = 128; st > 0; st >>= 1) {
        if (tid < st) sred[tid] += sred[tid + st];
        __syncthreads();
    }
    if (tid == 0) out[0] = sred[0] * (1.0f / (float)BATCH);
}

// ---------------- host ----------------
extern "C" void kernel_launch(void* const* d_in, const int* in_sizes, int n_in,
                              void* d_out, int out_size) {
    (void)in_sizes; (void)n_in; (void)out_size;
    const int*   input_lines  = (const int*)  d_in[0];
    const int*   target_lines = (const int*)  d_in[1];
    const float* emb_in       = (const float*)d_in[2];
    const float* emb_tgt      = (const float*)d_in[3];
    const float* W_ih_enc     = (const float*)d_in[4];
    const float* W_hh_enc     = (const float*)d_in[5];
    const float* b_ih_enc     = (const float*)d_in[6];
    const float* b_hh_enc     = (const float*)d_in[7];
    const float* W_ih_dec     = (const float*)d_in[8];
    const float* W_hh_dec     = (const float*)d_in[9];
    const float* b_ih_dec     = (const float*)d_in[10];
    const float* b_hh_dec     = (const float*)d_in[11];
    const float* W_out        = (const float*)d_in[12];
    const float* b_out        = (const float*)d_in[13];
    float* out = (float*)d_out;

    cudaFuncSetAttribute(gx_mma,       cudaFuncAttributeMaxDynamicSharedMemorySize, GX_SMEM);
    cudaFuncSetAttribute(lstm_persist, cudaFuncAttributeMaxDynamicSharedMemorySize, PS_SMEM);
    cudaFuncSetAttribute(logits_mma,   cudaFuncAttributeMaxDynamicSharedMemorySize, LGB_SMEM);

    init_kernel<<<256, 256>>>();

    conv_weights<<<4096, 256>>>(W_ih_enc, W_ih_dec, W_hh_enc, W_hh_dec);
    conv_wout<<<VOCAB * HID / 4 / 256, 256>>>(W_out);
    prep_x<<<XROWS_PAD, 64>>>(input_lines, target_lines, emb_in, emb_tgt);

    gx_mma<<<dim3(16, XROWS_PAD / 128), 256, GX_SMEM>>>(b_ih_enc, b_hh_enc, b_ih_dec, b_hh_dec);

    lstm_persist<<<PCTAS, 512, PS_SMEM>>>();

    logits_mma<<<dim3(MT2, VT2), 512, LGB_SMEM>>>(b_out);
    combine_loss<<<dim3(BATCH, TGT), 128>>>(target_lines, b_out);
    final_kernel<<<1, 256>>>(out);
}

// round 10
// speedup vs baseline: 13.2782x; 1.1185x over previous
#include <cuda_runtime.h>
#include <cuda_bf16.h>
#include <cuda_fp16.h>
#include <math.h>
#include <stdint.h>

#define HID   512
#define G4    2048
#define BATCH 64
#define VOCAB 32000
#define SRC   50
#define TGT   49
#define NSTEP (SRC + TGT)

#define VT2    125               // 32000 / 256
#define MT2    26                // 3328 / 128
#define NTILES (MT2 * VT2)       // 3250 logits tiles
#define DROWS  (TGT * BATCH)     // 3136 decode rows
#define DROWS_PAD 3328
#define GXROWS (NSTEP * BATCH)   // 6336
#define XROWS_PAD 6400
#define PCTAS 64                 // recurrence CTAs
#define FCTAS 148                // total fused CTAs

// ---------------- static scratch ----------------
__device__ float g_gx[(size_t)GXROWS * G4];
__device__ __nv_bfloat16 g_x_b[(size_t)XROWS_PAD * HID];
__device__ __nv_bfloat16 g_wih_b[2][(size_t)G4 * HID];
__device__ __half g_whh_h[2][(size_t)G4 * HID];
__device__ __half g_hs[2][BATCH * HID];
__device__ __nv_bfloat16 g_hall_b[(size_t)DROWS_PAD * HID];  // pad rows stay zero
__device__ __nv_bfloat16 g_wout_b[(size_t)VOCAB * HID];
__device__ float g_pmax[(size_t)DROWS * VT2];
__device__ float g_psum[(size_t)DROWS * VT2];
__device__ float g_losses[DROWS];
__device__ volatile int g_arrivev[PCTAS];
__device__ volatile int g_genv;
__device__ unsigned g_tile;

// ---------------- helpers ----------------
__device__ __forceinline__ uint32_t smem_u32(const void* p) {
    uint32_t a;
    asm("{ .reg .u64 t; cvta.to.shared.u64 t, %1; cvt.u32.u64 %0, t; }" : "=r"(a) : "l"(p));
    return a;
}
__device__ __forceinline__ void ldsm_x4(uint32_t* r, uint32_t addr) {
    asm volatile("ldmatrix.sync.aligned.m8n8.x4.shared.b16 {%0,%1,%2,%3}, [%4];"
        : "=r"(r[0]), "=r"(r[1]), "=r"(r[2]), "=r"(r[3]) : "r"(addr));
}
__device__ __forceinline__ void ldsm_x4_trans(uint32_t* r, uint32_t addr) {
    asm volatile("ldmatrix.sync.aligned.m8n8.x4.trans.shared.b16 {%0,%1,%2,%3}, [%4];"
        : "=r"(r[0]), "=r"(r[1]), "=r"(r[2]), "=r"(r[3]) : "r"(addr));
}
__device__ __forceinline__ void mma_bf16(float* c, const uint32_t* a, const uint32_t* b) {
    asm volatile("mma.sync.aligned.m16n8k16.row.col.f32.bf16.bf16.f32 "
        "{%0,%1,%2,%3}, {%4,%5,%6,%7}, {%8,%9}, {%0,%1,%2,%3};"
        : "+f"(c[0]), "+f"(c[1]), "+f"(c[2]), "+f"(c[3])
        : "r"(a[0]), "r"(a[1]), "r"(a[2]), "r"(a[3]), "r"(b[0]), "r"(b[1]));
}
__device__ __forceinline__ void mma_f16(float* c, const uint32_t* a, const uint32_t* b) {
    asm volatile("mma.sync.aligned.m16n8k16.row.col.f32.f16.f16.f32 "
        "{%0,%1,%2,%3}, {%4,%5,%6,%7}, {%8,%9}, {%0,%1,%2,%3};"
        : "+f"(c[0]), "+f"(c[1]), "+f"(c[2]), "+f"(c[3])
        : "r"(a[0]), "r"(a[1]), "r"(a[2]), "r"(a[3]), "r"(b[0]), "r"(b[1]));
}
__device__ __forceinline__ void cp16(uint32_t sdst, const void* gsrc) {
    asm volatile("cp.async.cg.shared.global [%0], [%1], 16;" :: "r"(sdst), "l"(gsrc) : "memory");
}
#define CP_COMMIT() asm volatile("cp.async.commit_group;" ::: "memory")
#define CP_WAIT1()  asm volatile("cp.async.wait_group 1;" ::: "memory")
#define CP_WAIT0()  asm volatile("cp.async.wait_group 0;" ::: "memory")

__device__ __forceinline__ float sigmoidf_(float x) { return 1.0f / (1.0f + __expf(-x)); }
__device__ __forceinline__ float fexp(float x) {
    x = fmaxf(x, -87.0f);
    float y = x * 1.44269504088896f;
    float r = rintf(y);
    float f = (y - r) * 0.693147180559945f;
    float p = 1.0f + f * (1.0f + f * (0.5f + f * (0.16666667f + f * (0.041666667f + f * 0.0083333333f))));
    return __int_as_float(((int)r + 127) << 23) * p;
}

// ---------------- init ----------------
__global__ void init_kernel() {
    int i = blockIdx.x * blockDim.x + threadIdx.x;
    if (i < 2 * BATCH * HID / 2) ((uint32_t*)g_hs)[i] = 0u;
    if (i < PCTAS) g_arrivev[i] = 0;
    if (i == 0) { g_genv = 0; g_tile = 0u; }
}

// ---------------- merged small-weight conversions ----------------
__global__ void conv_weights(const float* __restrict__ wie, const float* __restrict__ wid,
                             const float* __restrict__ whe, const float* __restrict__ whd) {
    int id = blockIdx.x >> 10;
    size_t i = ((size_t)(blockIdx.x & 1023) * 256 + threadIdx.x) * 4;
    const float* src = (id == 0) ? wie : (id == 1) ? wid : (id == 2) ? whe : whd;
    float4 v = *(const float4*)&src[i];
    if (id < 2) {
        __nv_bfloat162 a = __floats2bfloat162_rn(v.x, v.y);
        __nv_bfloat162 b = __floats2bfloat162_rn(v.z, v.w);
        __nv_bfloat16* dst = g_wih_b[id];
        *(uint32_t*)&dst[i]     = *(uint32_t*)&a;
        *(uint32_t*)&dst[i + 2] = *(uint32_t*)&b;
    } else {
        __half2 a = __floats2half2_rn(v.x, v.y);
        __half2 b = __floats2half2_rn(v.z, v.w);
        __half* dst = g_whh_h[id - 2];
        *(uint32_t*)&dst[i]     = *(uint32_t*)&a;
        *(uint32_t*)&dst[i + 2] = *(uint32_t*)&b;
    }
}
__global__ void conv_wout(const float* __restrict__ src) {
    size_t i = ((size_t)blockIdx.x * 256 + threadIdx.x) * 4;
    float4 v = *(const float4*)&src[i];
    __nv_bfloat162 a = __floats2bfloat162_rn(v.x, v.y);
    __nv_bfloat162 b = __floats2bfloat162_rn(v.z, v.w);
    *(uint32_t*)&g_wout_b[i]     = *(uint32_t*)&a;
    *(uint32_t*)&g_wout_b[i + 2] = *(uint32_t*)&b;
}

// ---------------- gather emb rows -> bf16 x matrix ----------------
__global__ void prep_x(const int* __restrict__ inl, const int* __restrict__ tgl,
                       const float* __restrict__ embi, const float* __restrict__ embt) {
    int row = blockIdx.x;
    int k = threadIdx.x * 8;
    int tok; const float* e;
    if (row < SRC * BATCH)       { tok = inl[row]; e = embi; }
    else if (row < GXROWS)       { tok = tgl[row - SRC * BATCH]; e = embt; }
    else                         { tok = 0; e = embi; }
    const float4* s = (const float4*)(e + (size_t)tok * HID + k);
    float4 v0 = s[0], v1 = s[1];
    __nv_bfloat162 p0 = __floats2bfloat162_rn(v0.x, v0.y);
    __nv_bfloat162 p1 = __floats2bfloat162_rn(v0.z, v0.w);
    __nv_bfloat162 p2 = __floats2bfloat162_rn(v1.x, v1.y);
    __nv_bfloat162 p3 = __floats2bfloat162_rn(v1.z, v1.w);
    uint4 o = make_uint4(*(uint32_t*)&p0, *(uint32_t*)&p1, *(uint32_t*)&p2, *(uint32_t*)&p3);
    *(uint4*)&g_x_b[(size_t)row * HID + k] = o;
}

// ================= gx GEMM (bf16 HMMA, cp.async 3-stage, 1 sync/chunk) =================
#define GX_SMEM 98816            // 3 x 32768 + 512 bias

__global__ __launch_bounds__(256) void gx_mma(const float* __restrict__ bihe, const float* __restrict__ bhhe,
                                              const float* __restrict__ bihd, const float* __restrict__ bhhd) {
    extern __shared__ __align__(16) char sm[];
    const uint32_t sb = smem_u32(sm);
    const int tid = threadIdx.x;
    const int l = tid & 31;
    const int w = tid >> 5;
    const int wr = w & 3;
    const int wc = w >> 2;
    const int n0 = blockIdx.x * 128;
    const int m0 = blockIdx.y * 128;
    const int side = (m0 >= SRC * BATCH) ? 1 : 0;
    const __nv_bfloat16* Wih = g_wih_b[side];
    float* bs = (float*)(sm + 98304);

    if (tid < 128) {
        const float* b1 = side ? bihd : bihe;
        const float* b2 = side ? bhhd : bhhe;
        bs[tid] = b1[n0 + tid] + b2[n0 + tid];
    }

    float acc[2][8][4];
#pragma unroll
    for (int i = 0; i < 2; ++i)
#pragma unroll
        for (int j = 0; j < 8; ++j)
#pragma unroll
            for (int q = 0; q < 4; ++q) acc[i][j][q] = 0.0f;

    const int a_row = wr * 32 + (l & 7) + ((l & 8) ? 8 : 0);
    const int a_k8  = (l & 16) ? 8 : 0;
    const int b4_n  = (l & 7) + ((l & 16) ? 8 : 0);
    const int b4_k8 = (l & 8) ? 8 : 0;

#define GX_STAGE(kb, s) do {                                                          \
        uint32_t base = sb + (s) * 32768;                                             \
        _Pragma("unroll")                                                             \
        for (int i_ = 0; i_ < 4; ++i_) {                                              \
            int c_ = tid + i_ * 256;                                                  \
            int row_ = c_ >> 3;                                                       \
            int k8_ = (c_ & 7) * 8;                                                   \
            uint32_t so_ = (uint32_t)(row_ * 128 + ((k8_ * 2) ^ ((row_ & 7) << 4)));  \
            cp16(base + so_,         &g_x_b[(size_t)(m0 + row_) * HID + (kb) + k8_]); \
            cp16(base + 16384 + so_, &Wih[(size_t)(n0 + row_) * HID + (kb) + k8_]);   \
        }                                                                             \
        CP_COMMIT();                                                                  \
    } while (0)

    GX_STAGE(0, 0);
    GX_STAGE(64, 1);
    for (int c = 0; c < 8; ++c) {
        if (c < 7) { CP_WAIT1(); } else { CP_WAIT0(); }
        __syncthreads();
        if (c < 6) GX_STAGE((c + 2) * 64, (c + 2) % 3);
        const uint32_t aB = sb + (c % 3) * 32768;
        const uint32_t bB = aB + 16384;
#pragma unroll
        for (int ks = 0; ks < 4; ++ks) {
            uint32_t a[2][4];
#pragma unroll
            for (int i = 0; i < 2; ++i) {
                int ar = a_row + i * 16;
                int ak = ks * 16 + a_k8;
                ldsm_x4(a[i], aB + ar * 128 + ((ak * 2) ^ ((ar & 7) << 4)));
            }
#pragma unroll
            for (int j16 = 0; j16 < 4; ++j16) {
                int bn = wc * 64 + j16 * 16 + b4_n;
                int bk = ks * 16 + b4_k8;
                uint32_t b[4];
                ldsm_x4_trans(b, bB + bn * 128 + ((bk * 2) ^ ((bn & 7) << 4)));
                mma_bf16(acc[0][j16 * 2],     a[0], b);
                mma_bf16(acc[1][j16 * 2],     a[1], b);
                mma_bf16(acc[0][j16 * 2 + 1], a[0], b + 2);
                mma_bf16(acc[1][j16 * 2 + 1], a[1], b + 2);
            }
        }
    }

#pragma unroll
    for (int i = 0; i < 2; ++i)
#pragma unroll
        for (int j = 0; j < 8; ++j) {
            int row0 = m0 + wr * 32 + i * 16 + (l >> 2);
            int colL = wc * 64 + j * 8 + (l & 3) * 2;
            int col = n0 + colL;
            if (row0 < GXROWS) {
                float2 v0 = make_float2(acc[i][j][0] + bs[colL], acc[i][j][1] + bs[colL + 1]);
                *(float2*)&g_gx[(size_t)row0 * G4 + col] = v0;
            }
            int row1 = row0 + 8;
            if (row1 < GXROWS) {
                float2 v1 = make_float2(acc[i][j][2] + bs[colL], acc[i][j][3] + bs[colL + 1]);
                *(float2*)&g_gx[(size_t)row1 * G4 + col] = v1;
            }
        }
}

// ================= fused persistent kernel: LSTM recurrence + logits workers =================
// SMEM layouts (temporally disjoint per CTA):
//   recurrence: PS_* (0..167936)
//   logits tile: LGB_* (0..152576)
//   worker slot: FS_SLOT
#define PS_WS 0
#define PS_AS 65536
#define PS_GX 131072
#define PS_DS 147456
#define PS_CS 165888
#define PS_SMEM 167936

#define LGB_STG   49152
#define LGB_BIAS  147456
#define LGB_PM    148480
#define LGB_PSUM  150528
#define FS_SLOT   152576
#define FS_SMEM   PS_SMEM

// ---- recurrence body (CTAs 0..63) ----
__device__ void lstm_recur(char* sm) {
    const uint32_t smb = smem_u32(sm);
    float* gxs = (float*)(sm + PS_GX);
    float* Ds0 = (float*)(sm + PS_DS);
    float* Ds1 = (float*)(sm + PS_DS + 9216);
    float* cs  = (float*)(sm + PS_CS);
    const int tid = threadIdx.x;
    const int l = tid & 31;
    const int w = tid >> 5;
    const int wg = w >> 3;
    const int wr = w & 3;
    const int wc = (w >> 2) & 1;
    const int bid = blockIdx.x;
    const int j0 = bid * 8;

    for (int u = tid; u < 8192; u += 512) {
        int sd = u >> 12;
        int rem = u & 4095;
        int kcu = rem >> 8;
        int r2 = rem & 255;
        int rw = r2 >> 3;
        int k8 = (r2 & 7) * 8;
        int grow = (rw >> 3) * HID + j0 + (rw & 7);
        uint4 v = *(const uint4*)&g_whh_h[sd][(size_t)grow * HID + kcu * 64 + k8];
        uint32_t so = (uint32_t)(rw * 128 + ((k8 * 2) ^ ((rw & 7) << 4)));
        *(uint4*)(sm + PS_WS + sd * 32768 + kcu * 4096 + so) = v;
    }
    cs[tid] = 0.0f;
    __syncthreads();

    const int a_row = wr * 16 + (l & 7) + ((l & 8) ? 8 : 0);
    const int a_k8  = (l & 16) ? 8 : 0;
    const int b4_n  = (l & 7) + ((l & 16) ? 8 : 0);
    const int b4_k8 = (l & 8) ? 8 : 0;
    const int cb = tid >> 3;
    const int cjj = tid & 7;
    const int gx_b = tid >> 3;
    const int gx_g = (tid & 7) >> 1;
    const int gx_h = tid & 1;

    cp16(smb + PS_GX + (uint32_t)(gx_b * 128 + gx_g * 32 + gx_h * 16),
         &g_gx[(size_t)gx_b * G4 + gx_g * 512 + j0 + gx_h * 4]);
    CP_COMMIT();

    for (int t = 0; t < NSTEP; ++t) {
        const int p = t & 1;
        const uint32_t wbase = smb + PS_WS + ((t < SRC) ? 0 : 32768) + wg * 4 * 4096;
        const __half* hsrc = g_hs[p];

#pragma unroll
        for (int i = 0; i < 8; ++i) {
            int u = tid + i * 512;
            int kc = u >> 9;
            int v2 = u & 511;
            int row = v2 >> 3;
            int k8 = (v2 & 7) * 8;
            uint32_t so = (uint32_t)(kc * 8192 + row * 128 + ((k8 * 2) ^ ((row & 7) << 4)));
            cp16(smb + PS_AS + so, &hsrc[(size_t)row * HID + kc * 64 + k8]);
        }
        CP_COMMIT();
        CP_WAIT0();
        __syncthreads();

        float acc[2][4];
#pragma unroll
        for (int j = 0; j < 2; ++j)
#pragma unroll
            for (int q = 0; q < 4; ++q) acc[j][q] = 0.0f;

#pragma unroll
        for (int kq = 0; kq < 4; ++kq) {
            const int kc = wg * 4 + kq;
#pragma unroll
            for (int ks = 0; ks < 4; ++ks) {
                uint32_t a[4];
                int ak = ks * 16 + a_k8;
                ldsm_x4(a, smb + PS_AS + kc * 8192 + a_row * 128 + ((ak * 2) ^ ((a_row & 7) << 4)));
                int bn = wc * 16 + b4_n;
                int bk = ks * 16 + b4_k8;
                uint32_t b[4];
                ldsm_x4_trans(b, wbase + kq * 4096 + bn * 128 + ((bk * 2) ^ ((bn & 7) << 4)));
                mma_f16(acc[0], a, b);
                mma_f16(acc[1], a, b + 2);
            }
        }

        float* Dsw = wg ? Ds1 : Ds0;
#pragma unroll
        for (int j = 0; j < 2; ++j) {
            int row = wr * 16 + (l >> 2);
            int col = wc * 16 + j * 8 + (l & 3) * 2;
            Dsw[row * 36 + col]           = acc[j][0];
            Dsw[row * 36 + col + 1]       = acc[j][1];
            Dsw[(row + 8) * 36 + col]     = acc[j][2];
            Dsw[(row + 8) * 36 + col + 1] = acc[j][3];
        }
        __syncthreads();

        {
            const float* gxb = gxs + (t & 1) * 2048;
            float gate[4];
#pragma unroll
            for (int g = 0; g < 4; ++g)
                gate[g] = Ds0[cb * 36 + g * 8 + cjj] + Ds1[cb * 36 + g * 8 + cjj]
                        + gxb[cb * 32 + g * 8 + cjj];
            float cc = cs[tid];
            float cn = sigmoidf_(gate[1]) * cc + sigmoidf_(gate[0]) * tanhf(gate[2]);
            float hn = sigmoidf_(gate[3]) * tanhf(cn);
            cs[tid] = cn;
            g_hs[p ^ 1][(size_t)cb * HID + j0 + cjj] = __float2half(hn);
            if (t >= SRC) {
                size_t dr = (size_t)((t - SRC) * BATCH + cb) * HID + j0 + cjj;
                g_hall_b[dr] = __float2bfloat16(hn);
            }
        }

        if (t + 1 < NSTEP) {
            cp16(smb + PS_GX + (uint32_t)(((t + 1) & 1) * 8192 + gx_b * 128 + gx_g * 32 + gx_h * 16),
                 &g_gx[(size_t)((t + 1) * BATCH + gx_b) * G4 + gx_g * 512 + j0 + gx_h * 4]);
            CP_COMMIT();
        }

        // ---- distributed grid barrier (slot array, no atomics) ----
        __syncthreads();
        if (tid == 0) { __threadfence(); g_arrivev[bid] = t + 1; }
        if (tid < PCTAS) { while (g_arrivev[tid] < t + 1) {} }
        if (bid == 0 && tid == 0) { __threadfence(); g_genv = t + 1; }
        __syncthreads();
    }
}

// ---- one logits tile: 128m x 256n GEMM + fused LSE partials ----
__device__ void logits_tile(char* sm2, int m0, int ntile, const float* __restrict__ bout) {
    const uint32_t sbase = smem_u32(sm2);
    const int tid = threadIdx.x;
    const int l = tid & 31;
    const int w = tid >> 5;
    const int wr = w & 3;
    const int wc = w >> 2;
    const int n0 = ntile * 256;

    float* bias_s = (float*)(sm2 + LGB_BIAS);
    float* pm = (float*)(sm2 + LGB_PM);
    float* ps = (float*)(sm2 + LGB_PSUM);
    if (tid < 256) bias_s[tid] = bout[n0 + tid];

    float acc[2][8][4];
#pragma unroll
    for (int i = 0; i < 2; ++i)
#pragma unroll
        for (int j = 0; j < 8; ++j)
#pragma unroll
            for (int q = 0; q < 4; ++q) acc[i][j][q] = 0.0f;

    const int a_row = wr * 32 + (l & 7) + ((l & 8) ? 8 : 0);
    const int a_k8  = (l & 16) ? 8 : 0;
    const int b4_n  = (l & 7) + ((l & 16) ? 8 : 0);
    const int b4_k8 = (l & 8) ? 8 : 0;

#define LGB_STAGE_LD(kb, s) do {                                                      \
        uint32_t base = sbase + (s) * LGB_STG;                                        \
        _Pragma("unroll")                                                             \
        for (int i_ = 0; i_ < 2; ++i_) {                                              \
            int c_ = tid + i_ * 512;                                                  \
            int row_ = c_ >> 3;                                                       \
            int k8_ = (c_ & 7) * 8;                                                   \
            uint32_t so_ = (uint32_t)(row_ * 128 + ((k8_ * 2) ^ ((row_ & 7) << 4)));  \
            cp16(base + so_, &g_hall_b[(size_t)(m0 + row_) * HID + (kb) + k8_]);      \
        }                                                                             \
        _Pragma("unroll")                                                             \
        for (int i_ = 0; i_ < 4; ++i_) {                                              \
            int c_ = tid + i_ * 512;                                                  \
            int row_ = c_ >> 3;                                                       \
            int k8_ = (c_ & 7) * 8;                                                   \
            uint32_t so_ = (uint32_t)(row_ * 128 + ((k8_ * 2) ^ ((row_ & 7) << 4)));  \
            cp16(base + 16384 + so_, &g_wout_b[(size_t)(n0 + row_) * HID + (kb) + k8_]); \
        }                                                                             \
        CP_COMMIT();                                                                  \
    } while (0)

    LGB_STAGE_LD(0, 0);
    LGB_STAGE_LD(64, 1);
    for (int c = 0; c < 8; ++c) {
        if (c < 7) { CP_WAIT1(); } else { CP_WAIT0(); }
        __syncthreads();
        if (c < 6) LGB_STAGE_LD((c + 2) * 64, (c + 2) % 3);
        const uint32_t aB = sbase + (c % 3) * LGB_STG;
        const uint32_t bB = aB + 16384;
#pragma unroll
        for (int ks = 0; ks < 4; ++ks) {
            uint32_t a[2][4];
#pragma unroll
            for (int i = 0; i < 2; ++i) {
                int ar = a_row + i * 16;
                int ak = ks * 16 + a_k8;
                ldsm_x4(a[i], aB + ar * 128 + ((ak * 2) ^ ((ar & 7) << 4)));
            }
#pragma unroll
            for (int j16 = 0; j16 < 4; ++j16) {
                int bn = wc * 64 + j16 * 16 + b4_n;
                int bk = ks * 16 + b4_k8;
                uint32_t b[4];
                ldsm_x4_trans(b, bB + bn * 128 + ((bk * 2) ^ ((bn & 7) << 4)));
                mma_bf16(acc[0][j16 * 2],     a[0], b);
                mma_bf16(acc[1][j16 * 2],     a[1], b);
                mma_bf16(acc[0][j16 * 2 + 1], a[0], b + 2);
                mma_bf16(acc[1][j16 * 2 + 1], a[1], b + 2);
            }
        }
    }

#pragma unroll
    for (int i = 0; i < 2; ++i) {
#pragma unroll
        for (int half = 0; half < 2; ++half) {
            int row = wr * 32 + i * 16 + (l >> 2) + half * 8;
            float m = -INFINITY;
#pragma unroll
            for (int j = 0; j < 8; ++j) {
                int colL = wc * 64 + j * 8 + (l & 3) * 2;
                float v0 = acc[i][j][half * 2]     + bias_s[colL];
                float v1 = acc[i][j][half * 2 + 1] + bias_s[colL + 1];
                m = fmaxf(m, fmaxf(v0, v1));
            }
            float sx = 0.0f;
#pragma unroll
            for (int j = 0; j < 8; ++j) {
                int colL = wc * 64 + j * 8 + (l & 3) * 2;
                sx += fexp(acc[i][j][half * 2]     + bias_s[colL]     - m);
                sx += fexp(acc[i][j][half * 2 + 1] + bias_s[colL + 1] - m);
            }
#pragma unroll
            for (int d = 1; d < 4; d <<= 1) {
                float mo = __shfl_xor_sync(0xffffffffu, m, d);
                float so = __shfl_xor_sync(0xffffffffu, sx, d);
                float mm = fmaxf(m, mo);
                sx = sx * fexp(m - mm) + so * fexp(mo - mm);
                m = mm;
            }
            if ((l & 3) == 0) {
                pm[row * 4 + wc] = m;
                ps[row * 4 + wc] = sx;
            }
        }
    }
    __syncthreads();

    if (tid < 128) {
        float m = pm[tid * 4];
#pragma unroll
        for (int q = 1; q < 4; ++q) m = fmaxf(m, pm[tid * 4 + q]);
        float sx = 0.0f;
#pragma unroll
        for (int q = 0; q < 4; ++q) sx += ps[tid * 4 + q] * fexp(pm[tid * 4 + q] - m);
        int gr = m0 + tid;
        if (gr < DROWS) {
            g_pmax[(size_t)gr * VT2 + ntile] = m;
            g_psum[(size_t)gr * VT2 + ntile] = sx;
        }
    }
}

// ---- fused kernel ----
__global__ __launch_bounds__(512, 1) void fused_kernel(const float* __restrict__ bout) {
    extern __shared__ __align__(16) char sm[];
    const int tid = threadIdx.x;

    if (blockIdx.x < PCTAS) {
        lstm_recur(sm);
        __syncthreads();
    }

    // logits work loop (all CTAs; recurrence CTAs join after finishing)
    int* slot = (int*)(sm + FS_SLOT);
    for (;;) {
        if (tid == 0) {
            int tile = (int)atomicAdd(&g_tile, 1u);
            *slot = tile;
            if (tile < NTILES) {
                int m = tile / VT2;
                int ready = SRC + 2 * m + 2;
                if (ready > NSTEP) ready = NSTEP;
                while (g_genv < ready) __nanosleep(64);
            }
        }
        __syncthreads();
        int tile = *slot;
        if (tile >= NTILES) break;
        logits_tile(sm, (tile / VT2) * 128, tile % VT2, bout);
        __syncthreads();
    }
}

// ================= combine partials -> per-(d,b) loss =================
__global__ void combine_loss(const int* __restrict__ target_lines,
                             const float* __restrict__ bout) {
    __shared__ float sred[128];
    const int b = blockIdx.x;
    const int d = blockIdx.y;
    const int bs = d * BATCH + b;
    const int tid = threadIdx.x;

    float m = -INFINITY;
    for (int p = tid; p < VT2; p += 128) m = fmaxf(m, g_pmax[(size_t)bs * VT2 + p]);
    sred[tid] = m;
    __syncthreads();
    for (int s = 64; s > 0; s >>= 1) {
        if (tid < s) sred[tid] = fmaxf(sred[tid], sred[tid + s]);
        __syncthreads();
    }
    const float gmax = sred[0];
    __syncthreads();

    float sum = 0.0f;
    for (int p = tid; p < VT2; p += 128)
        sum += g_psum[(size_t)bs * VT2 + p] * __expf(g_pmax[(size_t)bs * VT2 + p] - gmax);
    sred[tid] = sum;
    __syncthreads();
    for (int s = 64; s > 0; s >>= 1) {
        if (tid < s) sred[tid] += sred[tid + s];
        __syncthreads();
    }
    const float gsum = sred[0];
    __syncthreads();

    const int nxt = target_lines[(d + 1) * BATCH + b];
    const __nv_bfloat16* hrow = &g_hall_b[(size_t)bs * HID];
    const __nv_bfloat16* wrow = &g_wout_b[(size_t)nxt * HID];
    float ds = 0.0f;
#pragma unroll
    for (int q = 0; q < 4; ++q)
        ds += __bfloat162float(hrow[tid * 4 + q]) * __bfloat162float(wrow[tid * 4 + q]);
    sred[tid] = ds;
    __syncthreads();
    for (int s = 64; s > 0; s >>= 1) {
        if (tid < s) sred[tid] += sred[tid + s];
        __syncthreads();
    }
    if (tid == 0)
        g_losses[bs] = -(sred[0] + bout[nxt] - gmax - logf(gsum));
}

// ---------------- final deterministic sum ----------------
__global__ void final_kernel(float* __restrict__ out) {
    __shared__ float sred[256];
    const int tid = threadIdx.x;
    float s = 0.0f;
    for (int i = tid; i < DROWS; i += 256) s += g_losses[i];
    sred[tid] = s;
    __syncthreads();
    for (int st = 128; st > 0; st >>= 1) {
        if (tid < st) sred[tid] += sred[tid + st];
        __syncthreads();
    }
    if (tid == 0) out[0] = sred[0] * (1.0f / (float)BATCH);
}

// ---------------- host ----------------
extern "C" void kernel_launch(void* const* d_in, const int* in_sizes, int n_in,
                              void* d_out, int out_size) {
    (void)in_sizes; (void)n_in; (void)out_size;
    const int*   input_lines  = (const int*)  d_in[0];
    const int*   target_lines = (const int*)  d_in[1];
    const float* emb_in       = (const float*)d_in[2];
    const float* emb_tgt      = (const float*)d_in[3];
    const float* W_ih_enc     = (const float*)d_in[4];
    const float* W_hh_enc     = (const float*)d_in[5];
    const float* b_ih_enc     = (const float*)d_in[6];
    const float* b_hh_enc     = (const float*)d_in[7];
    const float* W_ih_dec     = (const float*)d_in[8];
    const float* W_hh_dec     = (const float*)d_in[9];
    const float* b_ih_dec     = (const float*)d_in[10];
    const float* b_hh_dec     = (const float*)d_in[11];
    const float* W_out        = (const float*)d_in[12];
    const float* b_out        = (const float*)d_in[13];
    float* out = (float*)d_out;

    cudaFuncSetAttribute(gx_mma,       cudaFuncAttributeMaxDynamicSharedMemorySize, GX_SMEM);
    cudaFuncSetAttribute(fused_kernel, cudaFuncAttributeMaxDynamicSharedMemorySize, FS_SMEM);

    init_kernel<<<256, 256>>>();

    conv_weights<<<4096, 256>>>(W_ih_enc, W_ih_dec, W_hh_enc, W_hh_dec);
    conv_wout<<<VOCAB * HID / 4 / 256, 256>>>(W_out);
    prep_x<<<XROWS_PAD, 64>>>(input_lines, target_lines, emb_in, emb_tgt);

    gx_mma<<<dim3(16, XROWS_PAD / 128), 256, GX_SMEM>>>(b_ih_enc, b_hh_enc, b_ih_dec, b_hh_dec);

    fused_kernel<<<FCTAS, 512, FS_SMEM>>>(b_out);

    combine_loss<<<dim3(BATCH, TGT), 128>>>(target_lines, b_out);
    final_kernel<<<1, 256>>>(out);
}